// round 4
// baseline (speedup 1.0000x reference)
#include <cuda_runtime.h>
#include <math.h>
#include <stdint.h>

#define NNODES 50000
#define NEDGES 800000
#define NTOT   (2 * NNODES)

// ---------------- scratch (device globals; no allocations allowed) ----------
__device__ int   g_degcur[NTOT];
__device__ int   g_rowptr[2 * (NNODES + 1)];
__device__ int   g_csr_src[2 * NEDGES];        // unified src ids (graph B +NNODES)
__device__ float g_csr_w[2 * NEDGES];
__device__ float g_norm[NTOT];
__device__ float g_hid[NTOT * 128];

// ---------------- graph preprocessing ---------------------------------------

__global__ void degree_kernel(const int* __restrict__ eA, const int* __restrict__ eB) {
    int i = blockIdx.x * blockDim.x + threadIdx.x;
    if (i >= 2 * NEDGES) return;
    int g = i / NEDGES, e = i - g * NEDGES;
    const int* ei = g ? eB : eA;
    int dst = ei[NEDGES + e];
    atomicAdd(&g_degcur[g * NNODES + dst], 1);
}

__global__ void norm_kernel() {
    int i = blockIdx.x * blockDim.x + threadIdx.x;
    if (i >= NTOT) return;
    g_norm[i] = rsqrtf((float)g_degcur[i] + 1.0f);
}

__global__ void scan_kernel() {
    __shared__ int sm[1024];
    int g = blockIdx.x;
    int t = threadIdx.x;
    const int CH = (NNODES + 1023) / 1024;
    int base = g * NNODES;
    int start = t * CH;
    int s = 0;
    for (int i = 0; i < CH; i++) {
        int idx = start + i;
        if (idx < NNODES) s += g_degcur[base + idx];
    }
    sm[t] = s;
    __syncthreads();
    for (int d = 1; d < 1024; d <<= 1) {
        int v = sm[t];
        int add = (t >= d) ? sm[t - d] : 0;
        __syncthreads();
        sm[t] = v + add;
        __syncthreads();
    }
    int off = (t == 0) ? 0 : sm[t - 1];
    for (int i = 0; i < CH; i++) {
        int idx = start + i;
        if (idx < NNODES) {
            int d = g_degcur[base + idx];
            g_rowptr[g * (NNODES + 1) + idx] = off;
            g_degcur[base + idx] = off;
            off += d;
        }
    }
    if (t == 1023) g_rowptr[g * (NNODES + 1) + NNODES] = off;
}

__global__ void fill_kernel(const int* __restrict__ eA, const int* __restrict__ eB) {
    int i = blockIdx.x * blockDim.x + threadIdx.x;
    if (i >= 2 * NEDGES) return;
    int g = i / NEDGES, e = i - g * NEDGES;
    const int* ei = g ? eB : eA;
    int src = ei[e];
    int dst = ei[NEDGES + e];
    int pos = atomicAdd(&g_degcur[g * NNODES + dst], 1);
    int su = src + g * NNODES;
    int du = dst + g * NNODES;
    g_csr_src[g * NEDGES + pos] = su;
    g_csr_w[g * NEDGES + pos]   = g_norm[su] * g_norm[du];
}

// ---------------- MMA helpers -------------------------------------------------

__device__ __forceinline__ uint32_t f2tf32(float f) {
    uint32_t u;
    asm volatile("cvt.rna.tf32.f32 %0, %1;" : "=r"(u) : "f"(f));
    return u;
}
__device__ __forceinline__ void cpasync16(uint32_t dst, const void* src, bool pred) {
    int sz = pred ? 16 : 0;
    asm volatile("cp.async.cg.shared.global [%0], [%1], 16, %2;"
                 :: "r"(dst), "l"(src), "r"(sz));
}
__device__ __forceinline__ void mma_tf32(float* c, const uint32_t* a, const uint32_t* b) {
    asm volatile(
        "mma.sync.aligned.m16n8k8.row.col.f32.tf32.tf32.f32 "
        "{%0,%1,%2,%3}, {%4,%5,%6,%7}, {%8,%9}, {%0,%1,%2,%3};"
        : "+f"(c[0]), "+f"(c[1]), "+f"(c[2]), "+f"(c[3])
        : "r"(a[0]), "r"(a[1]), "r"(a[2]), "r"(a[3]), "r"(b[0]), "r"(b[1]));
}

// ============================================================================
// Fused GCN layer: block aggregates 128 node rows into smem, then TF32 GEMM
// Y[node] = epi( agg(x)[node] @ W + bias ),  EPI: 0 none, 1 relu
// smem: As 128*132 floats, Wb 2*32*136 floats  (102,400 B)
// ============================================================================
#define AS_STRIDE 132
#define WB_STRIDE 136

template <int EPI>
__global__ void fused_layer(const float* __restrict__ x1, const float* __restrict__ x2,
                            const float* __restrict__ W, const float* __restrict__ bias,
                            float* __restrict__ Y) {
    extern __shared__ float sm[];
    float* As = sm;                        // 128 * 132
    float* Wb = sm + 128 * AS_STRIDE;      // 2 * 32 * 136

    const int t = threadIdx.x;
    const int wid = t >> 5;
    const int lane = t & 31;
    const int lr = lane >> 2;
    const int lc = lane & 3;
    const int row0 = blockIdx.x * 128;

    uint32_t bBase = (uint32_t)__cvta_generic_to_shared(Wb);

    auto loadW = [&](int buf, int k0) {
#pragma unroll
        for (int i = 0; i < 4; i++) {
            int idx4 = t + i * 256;               // 0..1023 = 32 rows x 32 quads
            int k = idx4 >> 5;
            int cq = idx4 & 31;
            uint32_t dst = bBase + (uint32_t)((buf * 32 * WB_STRIDE + k * WB_STRIDE + 4 * cq) * 4);
            cpasync16(dst, W + (size_t)(k0 + k) * 128 + 4 * cq, true);
        }
    };

    loadW(0, 0);
    asm volatile("cp.async.commit_group;");

    // ---------------- phase 1: aggregation into As ----------------
    const float4* x1v = (const float4*)x1;
    const float4* x2v = (const float4*)x2;
    for (int i = 0; i < 16; i++) {
        int nl = wid * 16 + i;
        int node = row0 + nl;
        float4 acc = {0.f, 0.f, 0.f, 0.f};
        if (node < NTOT) {
            int g = (node >= NNODES);
            int local = node - (g ? NNODES : 0);
            const float4* xs = g ? x2v : x1v;
            float nn = g_norm[node];
            float c = nn * nn;
            float4 a = __ldg(&xs[local * 32 + lane]);
            acc.x = a.x * c; acc.y = a.y * c; acc.z = a.z * c; acc.w = a.w * c;
            int b  = g_rowptr[g * (NNODES + 1) + local]     + g * NEDGES;
            int en = g_rowptr[g * (NNODES + 1) + local + 1] + g * NEDGES;
            int e = b;
            for (; e + 4 <= en; e += 4) {
                int s0 = __ldg(&g_csr_src[e + 0]);
                int s1 = __ldg(&g_csr_src[e + 1]);
                int s2 = __ldg(&g_csr_src[e + 2]);
                int s3 = __ldg(&g_csr_src[e + 3]);
                float w0 = __ldg(&g_csr_w[e + 0]);
                float w1 = __ldg(&g_csr_w[e + 1]);
                float w2 = __ldg(&g_csr_w[e + 2]);
                float w3 = __ldg(&g_csr_w[e + 3]);
                const float4* p0 = (s0 >= NNODES) ? (x2v + (size_t)(s0 - NNODES) * 32) : (x1v + (size_t)s0 * 32);
                const float4* p1 = (s1 >= NNODES) ? (x2v + (size_t)(s1 - NNODES) * 32) : (x1v + (size_t)s1 * 32);
                const float4* p2 = (s2 >= NNODES) ? (x2v + (size_t)(s2 - NNODES) * 32) : (x1v + (size_t)s2 * 32);
                const float4* p3 = (s3 >= NNODES) ? (x2v + (size_t)(s3 - NNODES) * 32) : (x1v + (size_t)s3 * 32);
                float4 v0 = __ldg(&p0[lane]);
                float4 v1 = __ldg(&p1[lane]);
                float4 v2 = __ldg(&p2[lane]);
                float4 v3 = __ldg(&p3[lane]);
                acc.x += v0.x * w0 + v1.x * w1 + v2.x * w2 + v3.x * w3;
                acc.y += v0.y * w0 + v1.y * w1 + v2.y * w2 + v3.y * w3;
                acc.z += v0.z * w0 + v1.z * w1 + v2.z * w2 + v3.z * w3;
                acc.w += v0.w * w0 + v1.w * w1 + v2.w * w2 + v3.w * w3;
            }
            for (; e < en; e++) {
                int s = __ldg(&g_csr_src[e]);
                float w = __ldg(&g_csr_w[e]);
                const float4* p = (s >= NNODES) ? (x2v + (size_t)(s - NNODES) * 32) : (x1v + (size_t)s * 32);
                float4 v = __ldg(&p[lane]);
                acc.x += v.x * w; acc.y += v.y * w; acc.z += v.z * w; acc.w += v.w * w;
            }
        }
        *(float4*)&As[nl * AS_STRIDE + lane * 4] = acc;
    }
    __syncthreads();

    // ---------------- phase 2: TF32 GEMM from smem ----------------
    const int warpRow = (wid & 3) * 32;
    const int warpCol = (wid >> 2) * 64;
    float acc[2][8][4];
#pragma unroll
    for (int m = 0; m < 2; m++)
#pragma unroll
        for (int nt = 0; nt < 8; nt++)
#pragma unroll
            for (int j = 0; j < 4; j++) acc[m][nt][j] = 0.0f;

    for (int tt = 0; tt < 4; tt++) {
        int buf = tt & 1;
        if (tt < 3) {
            loadW(buf ^ 1, (tt + 1) * 32);
            asm volatile("cp.async.commit_group;");
            asm volatile("cp.async.wait_group 1;");
        } else {
            asm volatile("cp.async.wait_group 0;");
        }
        __syncthreads();
        const float* Bs = Wb + buf * 32 * WB_STRIDE;
#pragma unroll
        for (int kk8 = 0; kk8 < 4; kk8++) {
            int kb = kk8 * 8;
            int col = tt * 32 + kb + lc;
            uint32_t af[2][4];
#pragma unroll
            for (int m = 0; m < 2; m++) {
                int r1 = warpRow + m * 16 + lr;
                af[m][0] = f2tf32(As[r1 * AS_STRIDE + col]);
                af[m][1] = f2tf32(As[(r1 + 8) * AS_STRIDE + col]);
                af[m][2] = f2tf32(As[r1 * AS_STRIDE + col + 4]);
                af[m][3] = f2tf32(As[(r1 + 8) * AS_STRIDE + col + 4]);
            }
            uint32_t bf[8][2];
#pragma unroll
            for (int nt = 0; nt < 8; nt++) {
                int cc = warpCol + nt * 8 + lr;
                bf[nt][0] = f2tf32(Bs[(kb + lc) * WB_STRIDE + cc]);
                bf[nt][1] = f2tf32(Bs[(kb + lc + 4) * WB_STRIDE + cc]);
            }
#pragma unroll
            for (int m = 0; m < 2; m++)
#pragma unroll
                for (int nt = 0; nt < 8; nt++)
                    mma_tf32(acc[m][nt], af[m], bf[nt]);
        }
        __syncthreads();
    }

    // ---------------- epilogue ----------------
#pragma unroll
    for (int m = 0; m < 2; m++) {
        int r1 = row0 + warpRow + m * 16 + lr;
        int r2 = r1 + 8;
#pragma unroll
        for (int nt = 0; nt < 8; nt++) {
            int col = warpCol + nt * 8 + 2 * lc;
            float b0 = __ldg(&bias[col]);
            float b1 = __ldg(&bias[col + 1]);
            float v0 = acc[m][nt][0] + b0;
            float v1 = acc[m][nt][1] + b1;
            float v2 = acc[m][nt][2] + b0;
            float v3 = acc[m][nt][3] + b1;
            if (EPI == 1) {
                v0 = fmaxf(v0, 0.f); v1 = fmaxf(v1, 0.f);
                v2 = fmaxf(v2, 0.f); v3 = fmaxf(v3, 0.f);
            }
            if (r1 < NTOT) { float2 s = {v0, v1}; *(float2*)&Y[(size_t)r1 * 128 + col] = s; }
            if (r2 < NTOT) { float2 s = {v2, v3}; *(float2*)&Y[(size_t)r2 * 128 + col] = s; }
        }
    }
}

// ============================================================================
// Fused projection: z = l2norm( relu(h@Wp1+bp1) @ Wp2 + bp2 )
// smem: Ab 2*128*36, Wb 2*32*72, Ts 128*68  (90,112 B)
// ============================================================================
#define PA_STRIDE 36
#define PW_STRIDE 72
#define TS_STRIDE 68

__global__ void proj_fused(const float* __restrict__ h,
                           const float* __restrict__ Wp1, const float* __restrict__ bp1,
                           const float* __restrict__ Wp2, const float* __restrict__ bp2,
                           float* __restrict__ z) {
    extern __shared__ float sm[];
    float* Ab = sm;                                   // 2*128*36
    float* Wb = sm + 2 * 128 * PA_STRIDE;             // 2*32*72
    float* Ts = Wb + 2 * 32 * PW_STRIDE;              // 128*68

    const int t = threadIdx.x;
    const int wid = t >> 5;
    const int lane = t & 31;
    const int lr = lane >> 2;
    const int lc = lane & 3;
    const int row0 = blockIdx.x * 128;
    const int warpRow = wid * 16;

    uint32_t aBase = (uint32_t)__cvta_generic_to_shared(Ab);
    uint32_t bBase = (uint32_t)__cvta_generic_to_shared(Wb);

    auto loadA = [&](int buf, int k0) {
#pragma unroll
        for (int i = 0; i < 4; i++) {
            int idx4 = t + i * 256;
            int row = idx4 >> 3;
            int kq = idx4 & 7;
            int rg = row0 + row;
            uint32_t dst = aBase + (uint32_t)((buf * 128 * PA_STRIDE + row * PA_STRIDE + 4 * kq) * 4);
            cpasync16(dst, h + (size_t)rg * 128 + k0 + 4 * kq, rg < NTOT);
        }
    };
    auto loadW = [&](const float* W, int buf, int k0) {
#pragma unroll
        for (int i = 0; i < 2; i++) {
            int idx4 = t + i * 256;
            int k = idx4 >> 4;
            int cq = idx4 & 15;
            uint32_t dst = bBase + (uint32_t)((buf * 32 * PW_STRIDE + k * PW_STRIDE + 4 * cq) * 4);
            cpasync16(dst, W + (size_t)(k0 + k) * 64 + 4 * cq, true);
        }
    };

    // ---------------- stage 1: t = relu(h @ Wp1 + bp1) -> Ts ----------------
    float acc[8][4];
#pragma unroll
    for (int nt = 0; nt < 8; nt++)
#pragma unroll
        for (int j = 0; j < 4; j++) acc[nt][j] = 0.0f;

    loadA(0, 0);
    loadW(Wp1, 0, 0);
    asm volatile("cp.async.commit_group;");

    for (int tt = 0; tt < 4; tt++) {
        int buf = tt & 1;
        if (tt < 3) {
            loadA(buf ^ 1, (tt + 1) * 32);
            loadW(Wp1, buf ^ 1, (tt + 1) * 32);
            asm volatile("cp.async.commit_group;");
            asm volatile("cp.async.wait_group 1;");
        } else {
            asm volatile("cp.async.wait_group 0;");
        }
        __syncthreads();
        const float* As = Ab + buf * 128 * PA_STRIDE;
        const float* Bs = Wb + buf * 32 * PW_STRIDE;
#pragma unroll
        for (int kk8 = 0; kk8 < 4; kk8++) {
            int kb = kk8 * 8;
            uint32_t af[4];
            int r1 = warpRow + lr;
            af[0] = f2tf32(As[r1 * PA_STRIDE + kb + lc]);
            af[1] = f2tf32(As[(r1 + 8) * PA_STRIDE + kb + lc]);
            af[2] = f2tf32(As[r1 * PA_STRIDE + kb + lc + 4]);
            af[3] = f2tf32(As[(r1 + 8) * PA_STRIDE + kb + lc + 4]);
            uint32_t bf[8][2];
#pragma unroll
            for (int nt = 0; nt < 8; nt++) {
                int cc = nt * 8 + lr;
                bf[nt][0] = f2tf32(Bs[(kb + lc) * PW_STRIDE + cc]);
                bf[nt][1] = f2tf32(Bs[(kb + lc + 4) * PW_STRIDE + cc]);
            }
#pragma unroll
            for (int nt = 0; nt < 8; nt++)
                mma_tf32(acc[nt], af, bf[nt]);
        }
        __syncthreads();
    }

    {
        int r1l = warpRow + lr;
        int r2l = r1l + 8;
#pragma unroll
        for (int nt = 0; nt < 8; nt++) {
            int col = nt * 8 + 2 * lc;
            float b0 = __ldg(&bp1[col]);
            float b1 = __ldg(&bp1[col + 1]);
            Ts[r1l * TS_STRIDE + col]     = fmaxf(acc[nt][0] + b0, 0.f);
            Ts[r1l * TS_STRIDE + col + 1] = fmaxf(acc[nt][1] + b1, 0.f);
            Ts[r2l * TS_STRIDE + col]     = fmaxf(acc[nt][2] + b0, 0.f);
            Ts[r2l * TS_STRIDE + col + 1] = fmaxf(acc[nt][3] + b1, 0.f);
        }
    }
    __syncthreads();

    // ---------------- stage 2: z = l2norm(t @ Wp2 + bp2) ----------------
#pragma unroll
    for (int nt = 0; nt < 8; nt++)
#pragma unroll
        for (int j = 0; j < 4; j++) acc[nt][j] = 0.0f;

    loadW(Wp2, 0, 0);
    asm volatile("cp.async.commit_group;");

    for (int tt = 0; tt < 2; tt++) {
        int buf = tt & 1;
        if (tt < 1) {
            loadW(Wp2, buf ^ 1, 32);
            asm volatile("cp.async.commit_group;");
            asm volatile("cp.async.wait_group 1;");
        } else {
            asm volatile("cp.async.wait_group 0;");
        }
        __syncthreads();
        const float* Bs = Wb + buf * 32 * PW_STRIDE;
#pragma unroll
        for (int kk8 = 0; kk8 < 4; kk8++) {
            int kb = kk8 * 8;
            int col = tt * 32 + kb + lc;
            uint32_t af[4];
            int r1 = warpRow + lr;
            af[0] = f2tf32(Ts[r1 * TS_STRIDE + col]);
            af[1] = f2tf32(Ts[(r1 + 8) * TS_STRIDE + col]);
            af[2] = f2tf32(Ts[r1 * TS_STRIDE + col + 4]);
            af[3] = f2tf32(Ts[(r1 + 8) * TS_STRIDE + col + 4]);
            uint32_t bf[8][2];
#pragma unroll
            for (int nt = 0; nt < 8; nt++) {
                int cc = nt * 8 + lr;
                bf[nt][0] = f2tf32(Bs[(kb + lc) * PW_STRIDE + cc]);
                bf[nt][1] = f2tf32(Bs[(kb + lc + 4) * PW_STRIDE + cc]);
            }
#pragma unroll
            for (int nt = 0; nt < 8; nt++)
                mma_tf32(acc[nt], af, bf[nt]);
        }
        __syncthreads();
    }

    {
        int r1 = row0 + warpRow + lr;
        int r2 = r1 + 8;
        float v[8][4];
#pragma unroll
        for (int nt = 0; nt < 8; nt++) {
            int col = nt * 8 + 2 * lc;
            float b0 = __ldg(&bp2[col]);
            float b1 = __ldg(&bp2[col + 1]);
            v[nt][0] = acc[nt][0] + b0;
            v[nt][1] = acc[nt][1] + b1;
            v[nt][2] = acc[nt][2] + b0;
            v[nt][3] = acc[nt][3] + b1;
        }
        float s1 = 0.f, s2 = 0.f;
#pragma unroll
        for (int nt = 0; nt < 8; nt++) {
            s1 += v[nt][0] * v[nt][0] + v[nt][1] * v[nt][1];
            s2 += v[nt][2] * v[nt][2] + v[nt][3] * v[nt][3];
        }
        s1 += __shfl_xor_sync(0xffffffffu, s1, 1);
        s1 += __shfl_xor_sync(0xffffffffu, s1, 2);
        s2 += __shfl_xor_sync(0xffffffffu, s2, 1);
        s2 += __shfl_xor_sync(0xffffffffu, s2, 2);
        float i1 = 1.0f / fmaxf(sqrtf(s1), 1e-12f);
        float i2 = 1.0f / fmaxf(sqrtf(s2), 1e-12f);
#pragma unroll
        for (int nt = 0; nt < 8; nt++) {
            int col = nt * 8 + 2 * lc;
            if (r1 < NTOT) { float2 s = {v[nt][0] * i1, v[nt][1] * i1}; *(float2*)&z[(size_t)r1 * 64 + col] = s; }
            if (r2 < NTOT) { float2 s = {v[nt][2] * i2, v[nt][3] * i2}; *(float2*)&z[(size_t)r2 * 64 + col] = s; }
        }
    }
}

// ============================================================================
// Null head: out[r] = relu([h|z] @ Wn1 + bn1) . Wn2 + bn2   (streamed GEMM)
// smem: Ab 2*128*36, Wb 2*32*72  (55,296 B)
// ============================================================================
__global__ void null_gemm(const float* __restrict__ h, const float* __restrict__ z,
                          const float* __restrict__ Wn1, const float* __restrict__ bn1,
                          const float* __restrict__ Wn2, const float* __restrict__ bn2,
                          float* __restrict__ out) {
    extern __shared__ float sm[];
    float* Ab = sm;
    float* Wb = sm + 2 * 128 * PA_STRIDE;

    const int t = threadIdx.x;
    const int wid = t >> 5;
    const int lane = t & 31;
    const int lr = lane >> 2;
    const int lc = lane & 3;
    const int row0 = blockIdx.x * 128;
    const int warpRow = wid * 16;
    const int K = 192;

    uint32_t aBase = (uint32_t)__cvta_generic_to_shared(Ab);
    uint32_t bBase = (uint32_t)__cvta_generic_to_shared(Wb);

    auto loadA = [&](int buf, int k0) {
#pragma unroll
        for (int i = 0; i < 4; i++) {
            int idx4 = t + i * 256;
            int row = idx4 >> 3;
            int kq = idx4 & 7;
            int kg = k0 + 4 * kq;
            int rg = row0 + row;
            const float* src = (kg < 128) ? (h + (size_t)rg * 128 + kg)
                                          : (z + (size_t)rg * 64 + (kg - 128));
            uint32_t dst = aBase + (uint32_t)((buf * 128 * PA_STRIDE + row * PA_STRIDE + 4 * kq) * 4);
            cpasync16(dst, src, rg < NTOT);
        }
    };
    auto loadW = [&](int buf, int k0) {
#pragma unroll
        for (int i = 0; i < 2; i++) {
            int idx4 = t + i * 256;
            int k = idx4 >> 4;
            int cq = idx4 & 15;
            uint32_t dst = bBase + (uint32_t)((buf * 32 * PW_STRIDE + k * PW_STRIDE + 4 * cq) * 4);
            cpasync16(dst, Wn1 + (size_t)(k0 + k) * 64 + 4 * cq, true);
        }
    };

    float acc[8][4];
#pragma unroll
    for (int nt = 0; nt < 8; nt++)
#pragma unroll
        for (int j = 0; j < 4; j++) acc[nt][j] = 0.0f;

    loadA(0, 0);
    loadW(0, 0);
    asm volatile("cp.async.commit_group;");

    const int T = K / 32;  // 6
    for (int tt = 0; tt < T; tt++) {
        int buf = tt & 1;
        if (tt + 1 < T) {
            loadA(buf ^ 1, (tt + 1) * 32);
            loadW(buf ^ 1, (tt + 1) * 32);
            asm volatile("cp.async.commit_group;");
            asm volatile("cp.async.wait_group 1;");
        } else {
            asm volatile("cp.async.wait_group 0;");
        }
        __syncthreads();
        const float* As = Ab + buf * 128 * PA_STRIDE;
        const float* Bs = Wb + buf * 32 * PW_STRIDE;
#pragma unroll
        for (int kk8 = 0; kk8 < 4; kk8++) {
            int kb = kk8 * 8;
            uint32_t af[4];
            int r1 = warpRow + lr;
            af[0] = f2tf32(As[r1 * PA_STRIDE + kb + lc]);
            af[1] = f2tf32(As[(r1 + 8) * PA_STRIDE + kb + lc]);
            af[2] = f2tf32(As[r1 * PA_STRIDE + kb + lc + 4]);
            af[3] = f2tf32(As[(r1 + 8) * PA_STRIDE + kb + lc + 4]);
            uint32_t bf[8][2];
#pragma unroll
            for (int nt = 0; nt < 8; nt++) {
                int cc = nt * 8 + lr;
                bf[nt][0] = f2tf32(Bs[(kb + lc) * PW_STRIDE + cc]);
                bf[nt][1] = f2tf32(Bs[(kb + lc + 4) * PW_STRIDE + cc]);
            }
#pragma unroll
            for (int nt = 0; nt < 8; nt++)
                mma_tf32(acc[nt], af, bf[nt]);
        }
        __syncthreads();
    }

    {
        int r1 = row0 + warpRow + lr;
        int r2 = r1 + 8;
        float d1 = 0.f, d2 = 0.f;
#pragma unroll
        for (int nt = 0; nt < 8; nt++) {
            int col = nt * 8 + 2 * lc;
            float b0 = __ldg(&bn1[col]);
            float b1 = __ldg(&bn1[col + 1]);
            float w0 = __ldg(&Wn2[col]);
            float w1 = __ldg(&Wn2[col + 1]);
            d1 += fmaxf(acc[nt][0] + b0, 0.f) * w0 + fmaxf(acc[nt][1] + b1, 0.f) * w1;
            d2 += fmaxf(acc[nt][2] + b0, 0.f) * w0 + fmaxf(acc[nt][3] + b1, 0.f) * w1;
        }
        d1 += __shfl_xor_sync(0xffffffffu, d1, 1);
        d1 += __shfl_xor_sync(0xffffffffu, d1, 2);
        d2 += __shfl_xor_sync(0xffffffffu, d2, 1);
        d2 += __shfl_xor_sync(0xffffffffu, d2, 2);
        if (lc == 0) {
            float bb = __ldg(&bn2[0]);
            if (r1 < NTOT) out[r1] = d1 + bb;
            if (r2 < NTOT) out[r2] = d2 + bb;
        }
    }
}

// ---------------- launch ------------------------------------------------------

extern "C" void kernel_launch(void* const* d_in, const int* in_sizes, int n_in,
                              void* d_out, int out_size) {
    const float* xA  = (const float*)d_in[0];
    const float* xB  = (const float*)d_in[1];
    const int*   eA  = (const int*)d_in[2];
    const int*   eB  = (const int*)d_in[3];
    const float* W1  = (const float*)d_in[4];
    const float* b1  = (const float*)d_in[5];
    const float* W2  = (const float*)d_in[6];
    const float* b2  = (const float*)d_in[7];
    const float* Wp1 = (const float*)d_in[8];
    const float* bp1 = (const float*)d_in[9];
    const float* Wp2 = (const float*)d_in[10];
    const float* bp2 = (const float*)d_in[11];
    const float* Wn1 = (const float*)d_in[12];
    const float* bn1 = (const float*)d_in[13];
    const float* Wn2 = (const float*)d_in[14];
    const float* bn2 = (const float*)d_in[15];

    float* out  = (float*)d_out;
    float* h    = out;                               // [2N,128] (hA | hB)
    float* z    = out + (size_t)NTOT * 128;          // [2N,64]  (zA | zB)
    float* nul  = z + (size_t)NTOT * 64;             // [2N]

    void* p;
    int* degcur;  cudaGetSymbolAddress(&p, g_degcur); degcur = (int*)p;
    float* hid;   cudaGetSymbolAddress(&p, g_hid);    hid    = (float*)p;

    cudaMemsetAsync(degcur, 0, NTOT * sizeof(int));
    degree_kernel<<<(2 * NEDGES + 255) / 256, 256>>>(eA, eB);
    norm_kernel<<<(NTOT + 255) / 256, 256>>>();
    scan_kernel<<<2, 1024>>>();
    fill_kernel<<<(2 * NEDGES + 255) / 256, 256>>>(eA, eB);

    const int grid = (NTOT + 127) / 128;

    size_t shLayer = (128 * AS_STRIDE + 2 * 32 * WB_STRIDE) * sizeof(float);      // 102,400
    size_t shProj  = (2 * 128 * PA_STRIDE + 2 * 32 * PW_STRIDE + 128 * TS_STRIDE) * sizeof(float); // 90,112
    size_t shNull  = (2 * 128 * PA_STRIDE + 2 * 32 * PW_STRIDE) * sizeof(float);  // 55,296

    cudaFuncSetAttribute(fused_layer<1>, cudaFuncAttributeMaxDynamicSharedMemorySize, (int)shLayer);
    cudaFuncSetAttribute(fused_layer<0>, cudaFuncAttributeMaxDynamicSharedMemorySize, (int)shLayer);
    cudaFuncSetAttribute(proj_fused,     cudaFuncAttributeMaxDynamicSharedMemorySize, (int)shProj);
    cudaFuncSetAttribute(null_gemm,      cudaFuncAttributeMaxDynamicSharedMemorySize, (int)shNull);

    // layer 1: hid = relu(agg(x) @ W1 + b1)
    fused_layer<1><<<grid, 256, shLayer>>>(xA, xB, W1, b1, hid);
    // layer 2: h = agg(hid) @ W2 + b2
    fused_layer<0><<<grid, 256, shLayer>>>(hid, hid + (size_t)NNODES * 128, W2, b2, h);
    // proj: z = l2norm(relu(h@Wp1+bp1) @ Wp2 + bp2)
    proj_fused<<<grid, 256, shProj>>>(h, Wp1, bp1, Wp2, bp2, z);
    // null head
    null_gemm<<<grid, 256, shNull>>>(h, z, Wn1, bn1, Wn2, bn2, nul);
}

// round 5
// speedup vs baseline: 1.2691x; 1.2691x over previous
#include <cuda_runtime.h>
#include <math.h>
#include <stdint.h>

#define NNODES 50000
#define NEDGES 800000
#define NTOT   (2 * NNODES)

// ---------------- scratch (device globals; no allocations allowed) ----------
__device__ int   g_degcur[NTOT];
__device__ int   g_rowptr[2 * (NNODES + 1)];
__device__ int   g_csr_src[2 * NEDGES];        // unified src ids (graph B +NNODES)
__device__ float g_norm[NTOT];
__device__ float g_agg[NTOT * 128];
__device__ float g_hid[NTOT * 128];
__device__ float g_tmp[NTOT * 64];

// ---------------- graph preprocessing ---------------------------------------

__global__ void degree_kernel(const int* __restrict__ eA, const int* __restrict__ eB) {
    int i = blockIdx.x * blockDim.x + threadIdx.x;
    if (i >= 2 * NEDGES) return;
    int g = i / NEDGES, e = i - g * NEDGES;
    const int* ei = g ? eB : eA;
    int dst = ei[NEDGES + e];
    atomicAdd(&g_degcur[g * NNODES + dst], 1);
}

// one block per graph: norm = rsqrt(deg+1), exclusive scan -> rowptr + cursor
__global__ void scan_kernel() {
    __shared__ int sm[1024];
    int g = blockIdx.x;
    int t = threadIdx.x;
    const int CH = (NNODES + 1023) / 1024;
    int base = g * NNODES;
    int start = t * CH;
    int s = 0;
    for (int i = 0; i < CH; i++) {
        int idx = start + i;
        if (idx < NNODES) {
            int d = g_degcur[base + idx];
            g_norm[base + idx] = rsqrtf((float)d + 1.0f);
            s += d;
        }
    }
    sm[t] = s;
    __syncthreads();
    for (int d = 1; d < 1024; d <<= 1) {
        int v = sm[t];
        int add = (t >= d) ? sm[t - d] : 0;
        __syncthreads();
        sm[t] = v + add;
        __syncthreads();
    }
    int off = (t == 0) ? 0 : sm[t - 1];
    for (int i = 0; i < CH; i++) {
        int idx = start + i;
        if (idx < NNODES) {
            int d = g_degcur[base + idx];
            g_rowptr[g * (NNODES + 1) + idx] = off;
            g_degcur[base + idx] = off;
            off += d;
        }
    }
    if (t == 1023) g_rowptr[g * (NNODES + 1) + NNODES] = off;
}

__global__ void fill_kernel(const int* __restrict__ eA, const int* __restrict__ eB) {
    int i = blockIdx.x * blockDim.x + threadIdx.x;
    if (i >= 2 * NEDGES) return;
    int g = i / NEDGES, e = i - g * NEDGES;
    const int* ei = g ? eB : eA;
    int src = ei[e];
    int dst = ei[NEDGES + e];
    int pos = atomicAdd(&g_degcur[g * NNODES + dst], 1);
    g_csr_src[g * NEDGES + pos] = src + g * NNODES;
}

// ---------------- GCN aggregation: warp per node (unified 2N) ----------------
// out[d] = norm[d] * ( sum_e norm[s]*x[s]  +  norm[d]*x[d] )
__global__ void agg_kernel(const float* __restrict__ x1,
                           const float* __restrict__ x2,
                           float* __restrict__ out) {
    int node = (blockIdx.x * blockDim.x + threadIdx.x) >> 5;
    int lane = threadIdx.x & 31;
    if (node >= NTOT) return;
    int g = (node >= NNODES);
    int local = node - (g ? NNODES : 0);
    const float4* x1v = (const float4*)x1;
    const float4* x2v = (const float4*)x2;
    const float4* xs = g ? x2v : x1v;

    float nd = g_norm[node];
    float4 a = __ldg(&xs[local * 32 + lane]);
    float4 acc;
    acc.x = a.x * nd; acc.y = a.y * nd; acc.z = a.z * nd; acc.w = a.w * nd;

    int b  = g_rowptr[g * (NNODES + 1) + local]     + g * NEDGES;
    int en = g_rowptr[g * (NNODES + 1) + local + 1] + g * NEDGES;
    int e = b;
    for (; e + 4 <= en; e += 4) {
        int s0 = __ldg(&g_csr_src[e + 0]);
        int s1 = __ldg(&g_csr_src[e + 1]);
        int s2 = __ldg(&g_csr_src[e + 2]);
        int s3 = __ldg(&g_csr_src[e + 3]);
        float w0 = __ldg(&g_norm[s0]);
        float w1 = __ldg(&g_norm[s1]);
        float w2 = __ldg(&g_norm[s2]);
        float w3 = __ldg(&g_norm[s3]);
        const float4* p0 = (s0 >= NNODES) ? (x2v + (size_t)(s0 - NNODES) * 32) : (x1v + (size_t)s0 * 32);
        const float4* p1 = (s1 >= NNODES) ? (x2v + (size_t)(s1 - NNODES) * 32) : (x1v + (size_t)s1 * 32);
        const float4* p2 = (s2 >= NNODES) ? (x2v + (size_t)(s2 - NNODES) * 32) : (x1v + (size_t)s2 * 32);
        const float4* p3 = (s3 >= NNODES) ? (x2v + (size_t)(s3 - NNODES) * 32) : (x1v + (size_t)s3 * 32);
        float4 v0 = __ldg(&p0[lane]);
        float4 v1 = __ldg(&p1[lane]);
        float4 v2 = __ldg(&p2[lane]);
        float4 v3 = __ldg(&p3[lane]);
        acc.x += v0.x * w0 + v1.x * w1 + v2.x * w2 + v3.x * w3;
        acc.y += v0.y * w0 + v1.y * w1 + v2.y * w2 + v3.y * w3;
        acc.z += v0.z * w0 + v1.z * w1 + v2.z * w2 + v3.z * w3;
        acc.w += v0.w * w0 + v1.w * w1 + v2.w * w2 + v3.w * w3;
    }
    for (; e < en; e++) {
        int s = __ldg(&g_csr_src[e]);
        float w = __ldg(&g_norm[s]);
        const float4* p = (s >= NNODES) ? (x2v + (size_t)(s - NNODES) * 32) : (x1v + (size_t)s * 32);
        float4 v = __ldg(&p[lane]);
        acc.x += v.x * w; acc.y += v.y * w; acc.z += v.z * w; acc.w += v.w * w;
    }
    acc.x *= nd; acc.y *= nd; acc.z *= nd; acc.w *= nd;
    ((float4*)out)[node * 32 + lane] = acc;
}

// ---------------- TF32 tensor-core GEMM --------------------------------------
// Y[n x BN] = epi( X[n x K] @ W[K x BN] + bias ),  X = concat(X1[K1], X2[K2])
// BM=128, BK=32, 256 threads. EPI: 0 none, 1 relu, 2 l2norm-row, 3 relu+dot(Wn2)+bn2
#define ASTRIDE 36

__device__ __forceinline__ uint32_t f2tf32(float f) {
    uint32_t u;
    asm volatile("cvt.rna.tf32.f32 %0, %1;" : "=r"(u) : "f"(f));
    return u;
}
__device__ __forceinline__ void cpasync16(uint32_t dst, const void* src, bool pred) {
    int sz = pred ? 16 : 0;
    asm volatile("cp.async.cg.shared.global [%0], [%1], 16, %2;"
                 :: "r"(dst), "l"(src), "r"(sz));
}
__device__ __forceinline__ void mma_tf32(float* c, const uint32_t* a, const uint32_t* b) {
    asm volatile(
        "mma.sync.aligned.m16n8k8.row.col.f32.tf32.tf32.f32 "
        "{%0,%1,%2,%3}, {%4,%5,%6,%7}, {%8,%9}, {%0,%1,%2,%3};"
        : "+f"(c[0]), "+f"(c[1]), "+f"(c[2]), "+f"(c[3])
        : "r"(a[0]), "r"(a[1]), "r"(a[2]), "r"(a[3]), "r"(b[0]), "r"(b[1]));
}

template <int BN, int MT, int EPI>
__global__ void gemm_tc(const float* __restrict__ X1, int K1,
                        const float* __restrict__ X2, int K2,
                        const float* __restrict__ W,
                        const float* __restrict__ bias,
                        float* __restrict__ Y, int n,
                        const float* __restrict__ Wn2,
                        const float* __restrict__ bn2) {
    constexpr int SB = BN + 8;
    extern __shared__ float sm[];
    float* Ab = sm;                       // 2 * 128 * ASTRIDE
    float* Bb = sm + 2 * 128 * ASTRIDE;   // 2 * 32 * SB

    const int t = threadIdx.x;
    const int wid = t >> 5;
    const int lane = t & 31;
    const int lr = lane >> 2;     // 0..7
    const int lc = lane & 3;      // 0..3
    const int K = K1 + K2;
    const int T = K / 32;
    const int row0 = blockIdx.x * 128;

    constexpr int WROWS = (BN == 128) ? 4 : 8;
    const int warpRow = (wid % WROWS) * (MT * 16);
    const int warpCol = (wid / WROWS) * 64;

    float acc[MT][8][4];
#pragma unroll
    for (int m = 0; m < MT; m++)
#pragma unroll
        for (int nt = 0; nt < 8; nt++)
#pragma unroll
            for (int j = 0; j < 4; j++) acc[m][nt][j] = 0.0f;

    uint32_t aBase = (uint32_t)__cvta_generic_to_shared(Ab);
    uint32_t bBase = (uint32_t)__cvta_generic_to_shared(Bb);

    auto loadA = [&](int buf, int k0) {
#pragma unroll
        for (int i = 0; i < 4; i++) {
            int idx4 = t + i * 256;           // 0..1023
            int row = idx4 >> 3;              // 0..127
            int kq = idx4 & 7;
            int kg = k0 + 4 * kq;
            int rg = row0 + row;
            const float* src = (kg < K1) ? (X1 + (size_t)rg * K1 + kg)
                                         : (X2 + (size_t)rg * K2 + (kg - K1));
            uint32_t dst = aBase + (uint32_t)((buf * 128 * ASTRIDE + row * ASTRIDE + 4 * kq) * 4);
            cpasync16(dst, src, rg < n);
        }
    };
    auto loadB = [&](int buf, int k0) {
        constexpr int ITER = (32 * BN) / (256 * 4);
#pragma unroll
        for (int i = 0; i < ITER; i++) {
            int idx4 = t + i * 256;
            int k = idx4 / (BN / 4);
            int cq = idx4 % (BN / 4);
            const float* src = W + (size_t)(k0 + k) * BN + 4 * cq;
            uint32_t dst = bBase + (uint32_t)((buf * 32 * SB + k * SB + 4 * cq) * 4);
            cpasync16(dst, src, true);
        }
    };

    loadA(0, 0);
    loadB(0, 0);
    asm volatile("cp.async.commit_group;");

    for (int tt = 0; tt < T; tt++) {
        int buf = tt & 1;
        if (tt + 1 < T) {
            loadA(buf ^ 1, (tt + 1) * 32);
            loadB(buf ^ 1, (tt + 1) * 32);
            asm volatile("cp.async.commit_group;");
            asm volatile("cp.async.wait_group 1;");
        } else {
            asm volatile("cp.async.wait_group 0;");
        }
        __syncthreads();

        const float* As = Ab + buf * 128 * ASTRIDE;
        const float* Bs = Bb + buf * 32 * SB;
#pragma unroll
        for (int kk8 = 0; kk8 < 4; kk8++) {
            int kb = kk8 * 8;
            uint32_t af[MT][4];
#pragma unroll
            for (int m = 0; m < MT; m++) {
                int r1 = warpRow + m * 16 + lr;
                af[m][0] = f2tf32(As[r1 * ASTRIDE + kb + lc]);
                af[m][1] = f2tf32(As[(r1 + 8) * ASTRIDE + kb + lc]);
                af[m][2] = f2tf32(As[r1 * ASTRIDE + kb + lc + 4]);
                af[m][3] = f2tf32(As[(r1 + 8) * ASTRIDE + kb + lc + 4]);
            }
            uint32_t bf[8][2];
#pragma unroll
            for (int nt = 0; nt < 8; nt++) {
                int cc = warpCol + nt * 8 + lr;
                bf[nt][0] = f2tf32(Bs[(kb + lc) * SB + cc]);
                bf[nt][1] = f2tf32(Bs[(kb + lc + 4) * SB + cc]);
            }
#pragma unroll
            for (int m = 0; m < MT; m++)
#pragma unroll
                for (int nt = 0; nt < 8; nt++)
                    mma_tf32(acc[m][nt], af[m], bf[nt]);
        }
        __syncthreads();
    }

    // ----------------- epilogue -----------------
#pragma unroll
    for (int m = 0; m < MT; m++) {
        int r1 = row0 + warpRow + m * 16 + lr;
        int r2 = r1 + 8;

        float v[8][4];
#pragma unroll
        for (int nt = 0; nt < 8; nt++) {
            int col = warpCol + nt * 8 + 2 * lc;
            float b0 = __ldg(&bias[col]);
            float b1 = __ldg(&bias[col + 1]);
            v[nt][0] = acc[m][nt][0] + b0;
            v[nt][1] = acc[m][nt][1] + b1;
            v[nt][2] = acc[m][nt][2] + b0;
            v[nt][3] = acc[m][nt][3] + b1;
            if (EPI == 1 || EPI == 3) {
#pragma unroll
                for (int j = 0; j < 4; j++) v[nt][j] = fmaxf(v[nt][j], 0.0f);
            }
        }

        if (EPI == 0 || EPI == 1) {
#pragma unroll
            for (int nt = 0; nt < 8; nt++) {
                int col = warpCol + nt * 8 + 2 * lc;
                if (r1 < n) { float2 s = {v[nt][0], v[nt][1]}; *(float2*)&Y[(size_t)r1 * BN + col] = s; }
                if (r2 < n) { float2 s = {v[nt][2], v[nt][3]}; *(float2*)&Y[(size_t)r2 * BN + col] = s; }
            }
        } else if (EPI == 2) {
            float s1 = 0.0f, s2 = 0.0f;
#pragma unroll
            for (int nt = 0; nt < 8; nt++) {
                s1 += v[nt][0] * v[nt][0] + v[nt][1] * v[nt][1];
                s2 += v[nt][2] * v[nt][2] + v[nt][3] * v[nt][3];
            }
            s1 += __shfl_xor_sync(0xffffffffu, s1, 1);
            s1 += __shfl_xor_sync(0xffffffffu, s1, 2);
            s2 += __shfl_xor_sync(0xffffffffu, s2, 1);
            s2 += __shfl_xor_sync(0xffffffffu, s2, 2);
            float i1 = 1.0f / fmaxf(sqrtf(s1), 1e-12f);
            float i2 = 1.0f / fmaxf(sqrtf(s2), 1e-12f);
#pragma unroll
            for (int nt = 0; nt < 8; nt++) {
                int col = warpCol + nt * 8 + 2 * lc;
                if (r1 < n) { float2 s = {v[nt][0] * i1, v[nt][1] * i1}; *(float2*)&Y[(size_t)r1 * BN + col] = s; }
                if (r2 < n) { float2 s = {v[nt][2] * i2, v[nt][3] * i2}; *(float2*)&Y[(size_t)r2 * BN + col] = s; }
            }
        } else { // EPI == 3
            float d1 = 0.0f, d2 = 0.0f;
#pragma unroll
            for (int nt = 0; nt < 8; nt++) {
                int col = warpCol + nt * 8 + 2 * lc;
                float w0 = __ldg(&Wn2[col]);
                float w1 = __ldg(&Wn2[col + 1]);
                d1 += v[nt][0] * w0 + v[nt][1] * w1;
                d2 += v[nt][2] * w0 + v[nt][3] * w1;
            }
            d1 += __shfl_xor_sync(0xffffffffu, d1, 1);
            d1 += __shfl_xor_sync(0xffffffffu, d1, 2);
            d2 += __shfl_xor_sync(0xffffffffu, d2, 1);
            d2 += __shfl_xor_sync(0xffffffffu, d2, 2);
            if (lc == 0) {
                float bb = __ldg(&bn2[0]);
                if (r1 < n) Y[r1] = d1 + bb;
                if (r2 < n) Y[r2] = d2 + bb;
            }
        }
    }
}

// ---------------- launch ------------------------------------------------------

extern "C" void kernel_launch(void* const* d_in, const int* in_sizes, int n_in,
                              void* d_out, int out_size) {
    const float* xA  = (const float*)d_in[0];
    const float* xB  = (const float*)d_in[1];
    const int*   eA  = (const int*)d_in[2];
    const int*   eB  = (const int*)d_in[3];
    const float* W1  = (const float*)d_in[4];
    const float* b1  = (const float*)d_in[5];
    const float* W2  = (const float*)d_in[6];
    const float* b2  = (const float*)d_in[7];
    const float* Wp1 = (const float*)d_in[8];
    const float* bp1 = (const float*)d_in[9];
    const float* Wp2 = (const float*)d_in[10];
    const float* bp2 = (const float*)d_in[11];
    const float* Wn1 = (const float*)d_in[12];
    const float* bn1 = (const float*)d_in[13];
    const float* Wn2 = (const float*)d_in[14];
    const float* bn2 = (const float*)d_in[15];

    float* out  = (float*)d_out;
    float* h    = out;                               // [2N,128] (hA | hB)
    float* z    = out + (size_t)NTOT * 128;          // [2N,64]
    float* nul  = z + (size_t)NTOT * 64;             // [2N]

    void* p;
    int* degcur;  cudaGetSymbolAddress(&p, g_degcur); degcur = (int*)p;
    float* agg;   cudaGetSymbolAddress(&p, g_agg);    agg    = (float*)p;
    float* hid;   cudaGetSymbolAddress(&p, g_hid);    hid    = (float*)p;
    float* tmp;   cudaGetSymbolAddress(&p, g_tmp);    tmp    = (float*)p;

    cudaMemsetAsync(degcur, 0, NTOT * sizeof(int));
    degree_kernel<<<(2 * NEDGES + 255) / 256, 256>>>(eA, eB);
    scan_kernel<<<2, 1024>>>();
    fill_kernel<<<(2 * NEDGES + 255) / 256, 256>>>(eA, eB);

    const int gemmGrid = (NTOT + 127) / 128;
    const int aggGrid  = (NTOT * 32 + 255) / 256;

    size_t sh128 = (2 * 128 * ASTRIDE + 2 * 32 * (128 + 8)) * sizeof(float);
    size_t sh64  = (2 * 128 * ASTRIDE + 2 * 32 * (64 + 8)) * sizeof(float);
    cudaFuncSetAttribute(gemm_tc<128, 2, 1>, cudaFuncAttributeMaxDynamicSharedMemorySize, (int)sh128);
    cudaFuncSetAttribute(gemm_tc<128, 2, 0>, cudaFuncAttributeMaxDynamicSharedMemorySize, (int)sh128);
    cudaFuncSetAttribute(gemm_tc<64, 1, 1>,  cudaFuncAttributeMaxDynamicSharedMemorySize, (int)sh64);
    cudaFuncSetAttribute(gemm_tc<64, 1, 2>,  cudaFuncAttributeMaxDynamicSharedMemorySize, (int)sh64);
    cudaFuncSetAttribute(gemm_tc<64, 1, 3>,  cudaFuncAttributeMaxDynamicSharedMemorySize, (int)sh64);

    // layer 1: agg(x) -> relu(. @ W1 + b1)
    agg_kernel<<<aggGrid, 256>>>(xA, xB, agg);
    gemm_tc<128, 2, 1><<<gemmGrid, 256, sh128>>>(agg, 128, nullptr, 0, W1, b1, hid, NTOT, nullptr, nullptr);
    // layer 2: agg(h1) -> . @ W2 + b2   (encoder output h)
    agg_kernel<<<aggGrid, 256>>>(hid, hid + (size_t)NNODES * 128, agg);
    gemm_tc<128, 2, 0><<<gemmGrid, 256, sh128>>>(agg, 128, nullptr, 0, W2, b2, h, NTOT, nullptr, nullptr);
    // proj: relu(h@Wp1+bp1) -> @Wp2+bp2 -> row-l2norm (fused)
    gemm_tc<64, 1, 1><<<gemmGrid, 256, sh64>>>(h, 128, nullptr, 0, Wp1, bp1, tmp, NTOT, nullptr, nullptr);
    gemm_tc<64, 1, 2><<<gemmGrid, 256, sh64>>>(tmp, 64, nullptr, 0, Wp2, bp2, z, NTOT, nullptr, nullptr);
    // null head: relu([h|z]@Wn1+bn1) . Wn2 + bn2 (fused dot)
    gemm_tc<64, 1, 3><<<gemmGrid, 256, sh64>>>(h, 128, z, 64, Wn1, bn1, nul, NTOT, Wn2, bn2);
}

// round 6
// speedup vs baseline: 1.2805x; 1.0090x over previous
#include <cuda_runtime.h>
#include <math.h>
#include <stdint.h>

#define NNODES 50000
#define NEDGES 800000
#define NTOT   (2 * NNODES)

// ---------------- scratch (device globals; no allocations allowed) ----------
__device__ int   g_degcur[NTOT];
__device__ int   g_rowptr[2 * (NNODES + 1)];
__device__ int   g_csr_src[2 * NEDGES];        // unified src ids (graph B +NNODES)
__device__ float g_norm[NTOT];
__device__ float g_agg[NTOT * 128];
__device__ float g_hid[NTOT * 128];
__device__ float g_tmp[NTOT * 64];
__device__ float g_w[57344];                   // tf32-rounded weights

// rounded-weight layout offsets (floats)
#define OW1  0
#define OW2  16384
#define OWP1 32768
#define OWP2 40960
#define OWN1 45056

__device__ __forceinline__ uint32_t f2tf32(float f) {
    uint32_t u;
    asm volatile("cvt.rna.tf32.f32 %0, %1;" : "=r"(u) : "f"(f));
    return u;
}
__device__ __forceinline__ float rnd32(float f) {
    return __uint_as_float(f2tf32(f));
}

// ---------------- graph preprocessing ---------------------------------------

__global__ void degree_kernel(const int* __restrict__ eA, const int* __restrict__ eB) {
    int i = blockIdx.x * blockDim.x + threadIdx.x;
    if (i >= 2 * NEDGES) return;
    int g = i / NEDGES, e = i - g * NEDGES;
    const int* ei = g ? eB : eA;
    int dst = ei[NEDGES + e];
    atomicAdd(&g_degcur[g * NNODES + dst], 1);
}

// pre-round all GEMM weights to tf32 (RNA) once
__global__ void roundw_kernel(const float* __restrict__ W1, const float* __restrict__ W2,
                              const float* __restrict__ Wp1, const float* __restrict__ Wp2,
                              const float* __restrict__ Wn1) {
    int i = blockIdx.x * blockDim.x + threadIdx.x;
    if (i >= 57344) return;
    float v;
    if (i < 16384)      v = W1[i];
    else if (i < 32768) v = W2[i - 16384];
    else if (i < 40960) v = Wp1[i - 32768];
    else if (i < 45056) v = Wp2[i - 40960];
    else                v = Wn1[i - 45056];
    g_w[i] = rnd32(v);
}

// one block per graph: norm = rsqrt(deg+1), exclusive scan -> rowptr + cursor
__global__ void scan_kernel() {
    __shared__ int sm[1024];
    int g = blockIdx.x;
    int t = threadIdx.x;
    const int CH = (NNODES + 1023) / 1024;
    int base = g * NNODES;
    int start = t * CH;
    int s = 0;
    for (int i = 0; i < CH; i++) {
        int idx = start + i;
        if (idx < NNODES) {
            int d = g_degcur[base + idx];
            g_norm[base + idx] = rsqrtf((float)d + 1.0f);
            s += d;
        }
    }
    sm[t] = s;
    __syncthreads();
    for (int d = 1; d < 1024; d <<= 1) {
        int v = sm[t];
        int add = (t >= d) ? sm[t - d] : 0;
        __syncthreads();
        sm[t] = v + add;
        __syncthreads();
    }
    int off = (t == 0) ? 0 : sm[t - 1];
    for (int i = 0; i < CH; i++) {
        int idx = start + i;
        if (idx < NNODES) {
            int d = g_degcur[base + idx];
            g_rowptr[g * (NNODES + 1) + idx] = off;
            g_degcur[base + idx] = off;
            off += d;
        }
    }
    if (t == 1023) g_rowptr[g * (NNODES + 1) + NNODES] = off;
}

__global__ void fill_kernel(const int* __restrict__ eA, const int* __restrict__ eB) {
    int i = blockIdx.x * blockDim.x + threadIdx.x;
    if (i >= 2 * NEDGES) return;
    int g = i / NEDGES, e = i - g * NEDGES;
    const int* ei = g ? eB : eA;
    int src = ei[e];
    int dst = ei[NEDGES + e];
    int pos = atomicAdd(&g_degcur[g * NNODES + dst], 1);
    g_csr_src[g * NEDGES + pos] = src + g * NNODES;
}

// ---------------- GCN aggregation: warp per node (unified 2N) ----------------
// out[d] = tf32rnd( norm[d] * ( sum_e norm[s]*x[s] + norm[d]*x[d] ) )
__global__ void agg_kernel(const float* __restrict__ x1,
                           const float* __restrict__ x2,
                           float* __restrict__ out) {
    int node = (blockIdx.x * blockDim.x + threadIdx.x) >> 5;
    int lane = threadIdx.x & 31;
    if (node >= NTOT) return;
    int g = (node >= NNODES);
    int local = node - (g ? NNODES : 0);
    const float4* x1v = (const float4*)x1;
    const float4* x2v = (const float4*)x2;
    const float4* xs = g ? x2v : x1v;

    float nd = g_norm[node];
    float4 a = __ldg(&xs[local * 32 + lane]);
    float4 acc;
    acc.x = a.x * nd; acc.y = a.y * nd; acc.z = a.z * nd; acc.w = a.w * nd;

    int b  = g_rowptr[g * (NNODES + 1) + local]     + g * NEDGES;
    int en = g_rowptr[g * (NNODES + 1) + local + 1] + g * NEDGES;
    int e = b;
    for (; e + 4 <= en; e += 4) {
        int s0 = __ldg(&g_csr_src[e + 0]);
        int s1 = __ldg(&g_csr_src[e + 1]);
        int s2 = __ldg(&g_csr_src[e + 2]);
        int s3 = __ldg(&g_csr_src[e + 3]);
        float w0 = __ldg(&g_norm[s0]);
        float w1 = __ldg(&g_norm[s1]);
        float w2 = __ldg(&g_norm[s2]);
        float w3 = __ldg(&g_norm[s3]);
        const float4* p0 = (s0 >= NNODES) ? (x2v + (size_t)(s0 - NNODES) * 32) : (x1v + (size_t)s0 * 32);
        const float4* p1 = (s1 >= NNODES) ? (x2v + (size_t)(s1 - NNODES) * 32) : (x1v + (size_t)s1 * 32);
        const float4* p2 = (s2 >= NNODES) ? (x2v + (size_t)(s2 - NNODES) * 32) : (x1v + (size_t)s2 * 32);
        const float4* p3 = (s3 >= NNODES) ? (x2v + (size_t)(s3 - NNODES) * 32) : (x1v + (size_t)s3 * 32);
        float4 v0 = __ldg(&p0[lane]);
        float4 v1 = __ldg(&p1[lane]);
        float4 v2 = __ldg(&p2[lane]);
        float4 v3 = __ldg(&p3[lane]);
        acc.x += v0.x * w0 + v1.x * w1 + v2.x * w2 + v3.x * w3;
        acc.y += v0.y * w0 + v1.y * w1 + v2.y * w2 + v3.y * w3;
        acc.z += v0.z * w0 + v1.z * w1 + v2.z * w2 + v3.z * w3;
        acc.w += v0.w * w0 + v1.w * w1 + v2.w * w2 + v3.w * w3;
    }
    for (; e < en; e++) {
        int s = __ldg(&g_csr_src[e]);
        float w = __ldg(&g_norm[s]);
        const float4* p = (s >= NNODES) ? (x2v + (size_t)(s - NNODES) * 32) : (x1v + (size_t)s * 32);
        float4 v = __ldg(&p[lane]);
        acc.x += v.x * w; acc.y += v.y * w; acc.z += v.z * w; acc.w += v.w * w;
    }
    acc.x = rnd32(acc.x * nd); acc.y = rnd32(acc.y * nd);
    acc.z = rnd32(acc.z * nd); acc.w = rnd32(acc.w * nd);
    ((float4*)out)[node * 32 + lane] = acc;
}

// ---------------- TF32 tensor-core GEMM --------------------------------------
// All X/W inputs are pre-rounded to tf32 -> mainloop passes raw bits (no cvt).
// Y[n x BN] = epi( X[n x K] @ W[K x BN] + bias ),  X = concat(X1[K1], X2[K2])
// EPI: 0 none, 1 relu, 2 l2norm-row, 3 relu+dot(Wn2)+bn2. EPI 0/1/2 stores tf32-rounded.
#define ASTRIDE 36

__device__ __forceinline__ void cpasync16(uint32_t dst, const void* src, bool pred) {
    int sz = pred ? 16 : 0;
    asm volatile("cp.async.cg.shared.global [%0], [%1], 16, %2;"
                 :: "r"(dst), "l"(src), "r"(sz));
}
__device__ __forceinline__ void mma_tf32(float* c, const uint32_t* a, const uint32_t* b) {
    asm volatile(
        "mma.sync.aligned.m16n8k8.row.col.f32.tf32.tf32.f32 "
        "{%0,%1,%2,%3}, {%4,%5,%6,%7}, {%8,%9}, {%0,%1,%2,%3};"
        : "+f"(c[0]), "+f"(c[1]), "+f"(c[2]), "+f"(c[3])
        : "r"(a[0]), "r"(a[1]), "r"(a[2]), "r"(a[3]), "r"(b[0]), "r"(b[1]));
}

template <int BN, int MT, int EPI>
__global__ void gemm_tc(const float* __restrict__ X1, int K1,
                        const float* __restrict__ X2, int K2,
                        const float* __restrict__ W,
                        const float* __restrict__ bias,
                        float* __restrict__ Y, int n,
                        const float* __restrict__ Wn2,
                        const float* __restrict__ bn2) {
    constexpr int SB = BN + 8;
    extern __shared__ float sm[];
    float* Ab = sm;                       // 2 * 128 * ASTRIDE
    float* Bb = sm + 2 * 128 * ASTRIDE;   // 2 * 32 * SB

    const int t = threadIdx.x;
    const int wid = t >> 5;
    const int lane = t & 31;
    const int lr = lane >> 2;     // 0..7
    const int lc = lane & 3;      // 0..3
    const int K = K1 + K2;
    const int T = K / 32;
    const int row0 = blockIdx.x * 128;

    constexpr int WROWS = (BN == 128) ? 4 : 8;
    const int warpRow = (wid % WROWS) * (MT * 16);
    const int warpCol = (wid / WROWS) * 64;

    float acc[MT][8][4];
#pragma unroll
    for (int m = 0; m < MT; m++)
#pragma unroll
        for (int nt = 0; nt < 8; nt++)
#pragma unroll
            for (int j = 0; j < 4; j++) acc[m][nt][j] = 0.0f;

    uint32_t aBase = (uint32_t)__cvta_generic_to_shared(Ab);
    uint32_t bBase = (uint32_t)__cvta_generic_to_shared(Bb);

    auto loadA = [&](int buf, int k0) {
#pragma unroll
        for (int i = 0; i < 4; i++) {
            int idx4 = t + i * 256;           // 0..1023
            int row = idx4 >> 3;              // 0..127
            int kq = idx4 & 7;
            int kg = k0 + 4 * kq;
            int rg = row0 + row;
            const float* src = (kg < K1) ? (X1 + (size_t)rg * K1 + kg)
                                         : (X2 + (size_t)rg * K2 + (kg - K1));
            uint32_t dst = aBase + (uint32_t)((buf * 128 * ASTRIDE + row * ASTRIDE + 4 * kq) * 4);
            cpasync16(dst, src, rg < n);
        }
    };
    auto loadB = [&](int buf, int k0) {
        constexpr int ITER = (32 * BN) / (256 * 4);
#pragma unroll
        for (int i = 0; i < ITER; i++) {
            int idx4 = t + i * 256;
            int k = idx4 / (BN / 4);
            int cq = idx4 % (BN / 4);
            const float* src = W + (size_t)(k0 + k) * BN + 4 * cq;
            uint32_t dst = bBase + (uint32_t)((buf * 32 * SB + k * SB + 4 * cq) * 4);
            cpasync16(dst, src, true);
        }
    };

    loadA(0, 0);
    loadB(0, 0);
    asm volatile("cp.async.commit_group;");

    for (int tt = 0; tt < T; tt++) {
        int buf = tt & 1;
        if (tt + 1 < T) {
            loadA(buf ^ 1, (tt + 1) * 32);
            loadB(buf ^ 1, (tt + 1) * 32);
            asm volatile("cp.async.commit_group;");
            asm volatile("cp.async.wait_group 1;");
        } else {
            asm volatile("cp.async.wait_group 0;");
        }
        __syncthreads();

        const float* As = Ab + buf * 128 * ASTRIDE;
        const float* Bs = Bb + buf * 32 * SB;
#pragma unroll
        for (int kk8 = 0; kk8 < 4; kk8++) {
            int kb = kk8 * 8;
            uint32_t af[MT][4];
#pragma unroll
            for (int m = 0; m < MT; m++) {
                int r1 = warpRow + m * 16 + lr;
                af[m][0] = __float_as_uint(As[r1 * ASTRIDE + kb + lc]);
                af[m][1] = __float_as_uint(As[(r1 + 8) * ASTRIDE + kb + lc]);
                af[m][2] = __float_as_uint(As[r1 * ASTRIDE + kb + lc + 4]);
                af[m][3] = __float_as_uint(As[(r1 + 8) * ASTRIDE + kb + lc + 4]);
            }
            uint32_t bf[8][2];
#pragma unroll
            for (int nt = 0; nt < 8; nt++) {
                int cc = warpCol + nt * 8 + lr;
                bf[nt][0] = __float_as_uint(Bs[(kb + lc) * SB + cc]);
                bf[nt][1] = __float_as_uint(Bs[(kb + lc + 4) * SB + cc]);
            }
#pragma unroll
            for (int m = 0; m < MT; m++)
#pragma unroll
                for (int nt = 0; nt < 8; nt++)
                    mma_tf32(acc[m][nt], af[m], bf[nt]);
        }
        __syncthreads();
    }

    // ----------------- epilogue -----------------
#pragma unroll
    for (int m = 0; m < MT; m++) {
        int r1 = row0 + warpRow + m * 16 + lr;
        int r2 = r1 + 8;

        float v[8][4];
#pragma unroll
        for (int nt = 0; nt < 8; nt++) {
            int col = warpCol + nt * 8 + 2 * lc;
            float b0 = __ldg(&bias[col]);
            float b1 = __ldg(&bias[col + 1]);
            v[nt][0] = acc[m][nt][0] + b0;
            v[nt][1] = acc[m][nt][1] + b1;
            v[nt][2] = acc[m][nt][2] + b0;
            v[nt][3] = acc[m][nt][3] + b1;
            if (EPI == 1 || EPI == 3) {
#pragma unroll
                for (int j = 0; j < 4; j++) v[nt][j] = fmaxf(v[nt][j], 0.0f);
            }
        }

        if (EPI == 0 || EPI == 1) {
#pragma unroll
            for (int nt = 0; nt < 8; nt++) {
                int col = warpCol + nt * 8 + 2 * lc;
                if (r1 < n) { float2 s = {rnd32(v[nt][0]), rnd32(v[nt][1])}; *(float2*)&Y[(size_t)r1 * BN + col] = s; }
                if (r2 < n) { float2 s = {rnd32(v[nt][2]), rnd32(v[nt][3])}; *(float2*)&Y[(size_t)r2 * BN + col] = s; }
            }
        } else if (EPI == 2) {
            float s1 = 0.0f, s2 = 0.0f;
#pragma unroll
            for (int nt = 0; nt < 8; nt++) {
                s1 += v[nt][0] * v[nt][0] + v[nt][1] * v[nt][1];
                s2 += v[nt][2] * v[nt][2] + v[nt][3] * v[nt][3];
            }
            s1 += __shfl_xor_sync(0xffffffffu, s1, 1);
            s1 += __shfl_xor_sync(0xffffffffu, s1, 2);
            s2 += __shfl_xor_sync(0xffffffffu, s2, 1);
            s2 += __shfl_xor_sync(0xffffffffu, s2, 2);
            float i1 = 1.0f / fmaxf(sqrtf(s1), 1e-12f);
            float i2 = 1.0f / fmaxf(sqrtf(s2), 1e-12f);
#pragma unroll
            for (int nt = 0; nt < 8; nt++) {
                int col = warpCol + nt * 8 + 2 * lc;
                if (r1 < n) { float2 s = {rnd32(v[nt][0] * i1), rnd32(v[nt][1] * i1)}; *(float2*)&Y[(size_t)r1 * BN + col] = s; }
                if (r2 < n) { float2 s = {rnd32(v[nt][2] * i2), rnd32(v[nt][3] * i2)}; *(float2*)&Y[(size_t)r2 * BN + col] = s; }
            }
        } else { // EPI == 3
            float d1 = 0.0f, d2 = 0.0f;
#pragma unroll
            for (int nt = 0; nt < 8; nt++) {
                int col = warpCol + nt * 8 + 2 * lc;
                float w0 = __ldg(&Wn2[col]);
                float w1 = __ldg(&Wn2[col + 1]);
                d1 += v[nt][0] * w0 + v[nt][1] * w1;
                d2 += v[nt][2] * w0 + v[nt][3] * w1;
            }
            d1 += __shfl_xor_sync(0xffffffffu, d1, 1);
            d1 += __shfl_xor_sync(0xffffffffu, d1, 2);
            d2 += __shfl_xor_sync(0xffffffffu, d2, 1);
            d2 += __shfl_xor_sync(0xffffffffu, d2, 2);
            if (lc == 0) {
                float bb = __ldg(&bn2[0]);
                if (r1 < n) Y[r1] = d1 + bb;
                if (r2 < n) Y[r2] = d2 + bb;
            }
        }
    }
}

// ---------------- launch ------------------------------------------------------

extern "C" void kernel_launch(void* const* d_in, const int* in_sizes, int n_in,
                              void* d_out, int out_size) {
    const float* xA  = (const float*)d_in[0];
    const float* xB  = (const float*)d_in[1];
    const int*   eA  = (const int*)d_in[2];
    const int*   eB  = (const int*)d_in[3];
    const float* W1  = (const float*)d_in[4];
    const float* b1  = (const float*)d_in[5];
    const float* W2  = (const float*)d_in[6];
    const float* b2  = (const float*)d_in[7];
    const float* Wp1 = (const float*)d_in[8];
    const float* bp1 = (const float*)d_in[9];
    const float* Wp2 = (const float*)d_in[10];
    const float* bp2 = (const float*)d_in[11];
    const float* Wn1 = (const float*)d_in[12];
    const float* bn1 = (const float*)d_in[13];
    const float* Wn2 = (const float*)d_in[14];
    const float* bn2 = (const float*)d_in[15];

    float* out  = (float*)d_out;
    float* h    = out;                               // [2N,128] (hA | hB)
    float* z    = out + (size_t)NTOT * 128;          // [2N,64]
    float* nul  = z + (size_t)NTOT * 64;             // [2N]

    void* p;
    int* degcur;  cudaGetSymbolAddress(&p, g_degcur); degcur = (int*)p;
    float* agg;   cudaGetSymbolAddress(&p, g_agg);    agg    = (float*)p;
    float* hid;   cudaGetSymbolAddress(&p, g_hid);    hid    = (float*)p;
    float* tmp;   cudaGetSymbolAddress(&p, g_tmp);    tmp    = (float*)p;
    float* w;     cudaGetSymbolAddress(&p, g_w);      w      = (float*)p;

    cudaMemsetAsync(degcur, 0, NTOT * sizeof(int));
    roundw_kernel<<<(57344 + 255) / 256, 256>>>(W1, W2, Wp1, Wp2, Wn1);
    degree_kernel<<<(2 * NEDGES + 255) / 256, 256>>>(eA, eB);
    scan_kernel<<<2, 1024>>>();
    fill_kernel<<<(2 * NEDGES + 255) / 256, 256>>>(eA, eB);

    const int gemmGrid = (NTOT + 127) / 128;
    const int aggGrid  = (NTOT * 32 + 255) / 256;

    size_t sh128 = (2 * 128 * ASTRIDE + 2 * 32 * (128 + 8)) * sizeof(float);
    size_t sh64  = (2 * 128 * ASTRIDE + 2 * 32 * (64 + 8)) * sizeof(float);
    cudaFuncSetAttribute(gemm_tc<128, 2, 1>, cudaFuncAttributeMaxDynamicSharedMemorySize, (int)sh128);
    cudaFuncSetAttribute(gemm_tc<128, 2, 0>, cudaFuncAttributeMaxDynamicSharedMemorySize, (int)sh128);
    cudaFuncSetAttribute(gemm_tc<64, 1, 1>,  cudaFuncAttributeMaxDynamicSharedMemorySize, (int)sh64);
    cudaFuncSetAttribute(gemm_tc<64, 1, 2>,  cudaFuncAttributeMaxDynamicSharedMemorySize, (int)sh64);
    cudaFuncSetAttribute(gemm_tc<64, 1, 3>,  cudaFuncAttributeMaxDynamicSharedMemorySize, (int)sh64);

    // layer 1: agg(x) -> relu(. @ W1 + b1)
    agg_kernel<<<aggGrid, 256>>>(xA, xB, agg);
    gemm_tc<128, 2, 1><<<gemmGrid, 256, sh128>>>(agg, 128, nullptr, 0, w + OW1, b1, hid, NTOT, nullptr, nullptr);
    // layer 2: agg(h1) -> . @ W2 + b2   (encoder output h)
    agg_kernel<<<aggGrid, 256>>>(hid, hid + (size_t)NNODES * 128, agg);
    gemm_tc<128, 2, 0><<<gemmGrid, 256, sh128>>>(agg, 128, nullptr, 0, w + OW2, b2, h, NTOT, nullptr, nullptr);
    // proj: relu(h@Wp1+bp1) -> @Wp2+bp2 -> row-l2norm (fused)
    gemm_tc<64, 1, 1><<<gemmGrid, 256, sh64>>>(h, 128, nullptr, 0, w + OWP1, bp1, tmp, NTOT, nullptr, nullptr);
    gemm_tc<64, 1, 2><<<gemmGrid, 256, sh64>>>(tmp, 64, nullptr, 0, w + OWP2, bp2, z, NTOT, nullptr, nullptr);
    // null head: relu([h|z]@Wn1+bn1) . Wn2 + bn2 (fused dot)
    gemm_tc<64, 1, 3><<<gemmGrid, 256, sh64>>>(h, 128, z, 64, w + OWN1, bn1, nul, NTOT, Wn2, bn2);
}

// round 12
// speedup vs baseline: 1.3025x; 1.0172x over previous
#include <cuda_runtime.h>
#include <cuda_fp16.h>
#include <math.h>
#include <stdint.h>

#define NNODES 50000
#define NEDGES 800000
#define NTOT   (2 * NNODES)

// ---------------- scratch (device globals; no allocations allowed) ----------
__device__ int   g_degcur[NTOT];
__device__ int   g_rowptr[2 * (NNODES + 1)];
__device__ int   g_csr_src[2 * NEDGES];        // unified src ids (graph B +NNODES)
__device__ float g_norm[NTOT];
__device__ float g_agg[NTOT * 128];
__device__ uint2 g_xh[NTOT * 32];              // fp16 features, unified [2N,128]
__device__ uint2 g_hidh[NTOT * 32];            // fp16 hidden layer
__device__ float g_tmp[NTOT * 64];
__device__ float g_w[57344];                   // tf32-rounded weights

#define OW1  0
#define OW2  16384
#define OWP1 32768
#define OWP2 40960
#define OWN1 45056

__device__ __forceinline__ uint32_t f2tf32(float f) {
    uint32_t u;
    asm volatile("cvt.rna.tf32.f32 %0, %1;" : "=r"(u) : "f"(f));
    return u;
}
__device__ __forceinline__ float rnd32(float f) {
    return __uint_as_float(f2tf32(f));
}
__device__ __forceinline__ float4 h4tof4(uint2 u) {
    __half2 h0 = *reinterpret_cast<__half2*>(&u.x);
    __half2 h1 = *reinterpret_cast<__half2*>(&u.y);
    float2 f0 = __half22float2(h0);
    float2 f1 = __half22float2(h1);
    float4 r; r.x = f0.x; r.y = f0.y; r.z = f1.x; r.w = f1.y;
    return r;
}

// ---------------- graph preprocessing ---------------------------------------

__global__ void degree_kernel(const int* __restrict__ eA, const int* __restrict__ eB) {
    int i = blockIdx.x * blockDim.x + threadIdx.x;
    if (i >= 2 * NEDGES) return;
    int g = i / NEDGES, e = i - g * NEDGES;
    const int* ei = g ? eB : eA;
    int dst = ei[NEDGES + e];
    atomicAdd(&g_degcur[g * NNODES + dst], 1);
}

// convert x (both graphs) to unified fp16 [2N,128]
__global__ void conv_kernel(const float* __restrict__ xA, const float* __restrict__ xB) {
    int i = blockIdx.x * blockDim.x + threadIdx.x;   // per 4 floats
    if (i >= NTOT * 32) return;
    const float4* src = (i < NNODES * 32) ? ((const float4*)xA + i)
                                          : ((const float4*)xB + (i - NNODES * 32));
    float4 v = __ldg(src);
    __half2 a = __floats2half2_rn(v.x, v.y);
    __half2 b = __floats2half2_rn(v.z, v.w);
    uint2 u;
    u.x = *reinterpret_cast<uint32_t*>(&a);
    u.y = *reinterpret_cast<uint32_t*>(&b);
    g_xh[i] = u;
}

// pre-round all GEMM weights to tf32 (RNA) once
__global__ void roundw_kernel(const float* __restrict__ W1, const float* __restrict__ W2,
                              const float* __restrict__ Wp1, const float* __restrict__ Wp2,
                              const float* __restrict__ Wn1) {
    int i = blockIdx.x * blockDim.x + threadIdx.x;
    if (i >= 57344) return;
    float v;
    if (i < 16384)      v = W1[i];
    else if (i < 32768) v = W2[i - 16384];
    else if (i < 40960) v = Wp1[i - 32768];
    else if (i < 45056) v = Wp2[i - 40960];
    else                v = Wn1[i - 45056];
    g_w[i] = rnd32(v);
}

// one block per graph: norm = rsqrt(deg+1), exclusive scan -> rowptr + cursor
__global__ void scan_kernel() {
    __shared__ int sm[1024];
    int g = blockIdx.x;
    int t = threadIdx.x;
    const int CH = (NNODES + 1023) / 1024;
    int base = g * NNODES;
    int start = t * CH;
    int s = 0;
    for (int i = 0; i < CH; i++) {
        int idx = start + i;
        if (idx < NNODES) {
            int d = g_degcur[base + idx];
            g_norm[base + idx] = rsqrtf((float)d + 1.0f);
            s += d;
        }
    }
    sm[t] = s;
    __syncthreads();
    for (int d = 1; d < 1024; d <<= 1) {
        int v = sm[t];
        int add = (t >= d) ? sm[t - d] : 0;
        __syncthreads();
        sm[t] = v + add;
        __syncthreads();
    }
    int off = (t == 0) ? 0 : sm[t - 1];
    for (int i = 0; i < CH; i++) {
        int idx = start + i;
        if (idx < NNODES) {
            int d = g_degcur[base + idx];
            g_rowptr[g * (NNODES + 1) + idx] = off;
            g_degcur[base + idx] = off;
            off += d;
        }
    }
    if (t == 1023) g_rowptr[g * (NNODES + 1) + NNODES] = off;
}

__global__ void fill_kernel(const int* __restrict__ eA, const int* __restrict__ eB) {
    int i = blockIdx.x * blockDim.x + threadIdx.x;
    if (i >= 2 * NEDGES) return;
    int g = i / NEDGES, e = i - g * NEDGES;
    const int* ei = g ? eB : eA;
    int src = ei[e];
    int dst = ei[NEDGES + e];
    int pos = atomicAdd(&g_degcur[g * NNODES + dst], 1);
    g_csr_src[g * NEDGES + pos] = src + g * NNODES;
}

// ---------------- GCN aggregation: warp per node, fp16 gathers ---------------
// out[d] = tf32rnd( norm[d] * ( sum_e norm[s]*x[s] + norm[d]*x[d] ) )
__global__ void aggh_kernel(const uint2* __restrict__ xh, float* __restrict__ out) {
    int node = (blockIdx.x * blockDim.x + threadIdx.x) >> 5;
    int lane = threadIdx.x & 31;
    if (node >= NTOT) return;
    int g = (node >= NNODES);
    int local = node - (g ? NNODES : 0);

    float nd = g_norm[node];
    float4 a = h4tof4(__ldg(&xh[node * 32 + lane]));
    float4 acc;
    acc.x = a.x * nd; acc.y = a.y * nd; acc.z = a.z * nd; acc.w = a.w * nd;

    int b  = g_rowptr[g * (NNODES + 1) + local]     + g * NEDGES;
    int en = g_rowptr[g * (NNODES + 1) + local + 1] + g * NEDGES;
    int e = b;
    for (; e + 4 <= en; e += 4) {
        int s0 = __ldg(&g_csr_src[e + 0]);
        int s1 = __ldg(&g_csr_src[e + 1]);
        int s2 = __ldg(&g_csr_src[e + 2]);
        int s3 = __ldg(&g_csr_src[e + 3]);
        float w0 = __ldg(&g_norm[s0]);
        float w1 = __ldg(&g_norm[s1]);
        float w2 = __ldg(&g_norm[s2]);
        float w3 = __ldg(&g_norm[s3]);
        float4 v0 = h4tof4(__ldg(&xh[(size_t)s0 * 32 + lane]));
        float4 v1 = h4tof4(__ldg(&xh[(size_t)s1 * 32 + lane]));
        float4 v2 = h4tof4(__ldg(&xh[(size_t)s2 * 32 + lane]));
        float4 v3 = h4tof4(__ldg(&xh[(size_t)s3 * 32 + lane]));
        acc.x += v0.x * w0 + v1.x * w1 + v2.x * w2 + v3.x * w3;
        acc.y += v0.y * w0 + v1.y * w1 + v2.y * w2 + v3.y * w3;
        acc.z += v0.z * w0 + v1.z * w1 + v2.z * w2 + v3.z * w3;
        acc.w += v0.w * w0 + v1.w * w1 + v2.w * w2 + v3.w * w3;
    }
    for (; e < en; e++) {
        int s = __ldg(&g_csr_src[e]);
        float w = __ldg(&g_norm[s]);
        float4 v = h4tof4(__ldg(&xh[(size_t)s * 32 + lane]));
        acc.x += v.x * w; acc.y += v.y * w; acc.z += v.z * w; acc.w += v.w * w;
    }
    acc.x = rnd32(acc.x * nd); acc.y = rnd32(acc.y * nd);
    acc.z = rnd32(acc.z * nd); acc.w = rnd32(acc.w * nd);
    ((float4*)out)[node * 32 + lane] = acc;
}

// ---------------- TF32 tensor-core GEMM --------------------------------------
// All X/W inputs pre-rounded to tf32 -> mainloop passes raw bits (no cvt).
// EPI: 0 none, 1 relu, 2 l2norm-row, 3 relu+dot(Wn2)+bn2, 4 relu+fp16 store
#define ASTRIDE 36

__device__ __forceinline__ void cpasync16(uint32_t dst, const void* src, bool pred) {
    int sz = pred ? 16 : 0;
    asm volatile("cp.async.cg.shared.global [%0], [%1], 16, %2;"
                 :: "r"(dst), "l"(src), "r"(sz));
}
__device__ __forceinline__ void mma_tf32(float* c, const uint32_t* a, const uint32_t* b) {
    asm volatile(
        "mma.sync.aligned.m16n8k8.row.col.f32.tf32.tf32.f32 "
        "{%0,%1,%2,%3}, {%4,%5,%6,%7}, {%8,%9}, {%0,%1,%2,%3};"
        : "+f"(c[0]), "+f"(c[1]), "+f"(c[2]), "+f"(c[3])
        : "r"(a[0]), "r"(a[1]), "r"(a[2]), "r"(a[3]), "r"(b[0]), "r"(b[1]));
}

template <int BN, int MT, int EPI>
__global__ void gemm_tc(const float* __restrict__ X1, int K1,
                        const float* __restrict__ X2, int K2,
                        const float* __restrict__ W,
                        const float* __restrict__ bias,
                        float* __restrict__ Y, int n,
                        const float* __restrict__ Wn2,
                        const float* __restrict__ bn2) {
    constexpr int SB = BN + 8;
    extern __shared__ float sm[];
    float* Ab = sm;                       // 2 * 128 * ASTRIDE
    float* Bb = sm + 2 * 128 * ASTRIDE;   // 2 * 32 * SB

    const int t = threadIdx.x;
    const int wid = t >> 5;
    const int lane = t & 31;
    const int lr = lane >> 2;
    const int lc = lane & 3;
    const int K = K1 + K2;
    const int T = K / 32;
    const int row0 = blockIdx.x * 128;

    constexpr int WROWS = (BN == 128) ? 4 : 8;
    const int warpRow = (wid % WROWS) * (MT * 16);
    const int warpCol = (wid / WROWS) * 64;

    float acc[MT][8][4];
#pragma unroll
    for (int m = 0; m < MT; m++)
#pragma unroll
        for (int nt = 0; nt < 8; nt++)
#pragma unroll
            for (int j = 0; j < 4; j++) acc[m][nt][j] = 0.0f;

    uint32_t aBase = (uint32_t)__cvta_generic_to_shared(Ab);
    uint32_t bBase = (uint32_t)__cvta_generic_to_shared(Bb);

    auto loadA = [&](int buf, int k0) {
#pragma unroll
        for (int i = 0; i < 4; i++) {
            int idx4 = t + i * 256;
            int row = idx4 >> 3;
            int kq = idx4 & 7;
            int kg = k0 + 4 * kq;
            int rg = row0 + row;
            const float* src = (kg < K1) ? (X1 + (size_t)rg * K1 + kg)
                                         : (X2 + (size_t)rg * K2 + (kg - K1));
            uint32_t dst = aBase + (uint32_t)((buf * 128 * ASTRIDE + row * ASTRIDE + 4 * kq) * 4);
            cpasync16(dst, src, rg < n);
        }
    };
    auto loadB = [&](int buf, int k0) {
        constexpr int ITER = (32 * BN) / (256 * 4);
#pragma unroll
        for (int i = 0; i < ITER; i++) {
            int idx4 = t + i * 256;
            int k = idx4 / (BN / 4);
            int cq = idx4 % (BN / 4);
            const float* src = W + (size_t)(k0 + k) * BN + 4 * cq;
            uint32_t dst = bBase + (uint32_t)((buf * 32 * SB + k * SB + 4 * cq) * 4);
            cpasync16(dst, src, true);
        }
    };

    loadA(0, 0);
    loadB(0, 0);
    asm volatile("cp.async.commit_group;");

    for (int tt = 0; tt < T; tt++) {
        int buf = tt & 1;
        if (tt + 1 < T) {
            loadA(buf ^ 1, (tt + 1) * 32);
            loadB(buf ^ 1, (tt + 1) * 32);
            asm volatile("cp.async.commit_group;");
            asm volatile("cp.async.wait_group 1;");
        } else {
            asm volatile("cp.async.wait_group 0;");
        }
        __syncthreads();

        const float* As = Ab + buf * 128 * ASTRIDE;
        const float* Bs = Bb + buf * 32 * SB;
#pragma unroll
        for (int kk8 = 0; kk8 < 4; kk8++) {
            int kb = kk8 * 8;
            uint32_t af[MT][4];
#pragma unroll
            for (int m = 0; m < MT; m++) {
                int r1 = warpRow + m * 16 + lr;
                af[m][0] = __float_as_uint(As[r1 * ASTRIDE + kb + lc]);
                af[m][1] = __float_as_uint(As[(r1 + 8) * ASTRIDE + kb + lc]);
                af[m][2] = __float_as_uint(As[r1 * ASTRIDE + kb + lc + 4]);
                af[m][3] = __float_as_uint(As[(r1 + 8) * ASTRIDE + kb + lc + 4]);
            }
            uint32_t bf[8][2];
#pragma unroll
            for (int nt = 0; nt < 8; nt++) {
                int cc = warpCol + nt * 8 + lr;
                bf[nt][0] = __float_as_uint(Bs[(kb + lc) * SB + cc]);
                bf[nt][1] = __float_as_uint(Bs[(kb + lc + 4) * SB + cc]);
            }
#pragma unroll
            for (int m = 0; m < MT; m++)
#pragma unroll
                for (int nt = 0; nt < 8; nt++)
                    mma_tf32(acc[m][nt], af[m], bf[nt]);
        }
        __syncthreads();
    }

    // ----------------- epilogue -----------------
#pragma unroll
    for (int m = 0; m < MT; m++) {
        int r1 = row0 + warpRow + m * 16 + lr;
        int r2 = r1 + 8;

        float v[8][4];
#pragma unroll
        for (int nt = 0; nt < 8; nt++) {
            int col = warpCol + nt * 8 + 2 * lc;
            float b0 = __ldg(&bias[col]);
            float b1 = __ldg(&bias[col + 1]);
            v[nt][0] = acc[m][nt][0] + b0;
            v[nt][1] = acc[m][nt][1] + b1;
            v[nt][2] = acc[m][nt][2] + b0;
            v[nt][3] = acc[m][nt][3] + b1;
            if (EPI == 1 || EPI == 3 || EPI == 4) {
#pragma unroll
                for (int j = 0; j < 4; j++) v[nt][j] = fmaxf(v[nt][j], 0.0f);
            }
        }

        if (EPI == 0 || EPI == 1) {
#pragma unroll
            for (int nt = 0; nt < 8; nt++) {
                int col = warpCol + nt * 8 + 2 * lc;
                if (r1 < n) { float2 s = {rnd32(v[nt][0]), rnd32(v[nt][1])}; *(float2*)&Y[(size_t)r1 * BN + col] = s; }
                if (r2 < n) { float2 s = {rnd32(v[nt][2]), rnd32(v[nt][3])}; *(float2*)&Y[(size_t)r2 * BN + col] = s; }
            }
        } else if (EPI == 4) {
            __half* Yh = (__half*)Y;
#pragma unroll
            for (int nt = 0; nt < 8; nt++) {
                int col = warpCol + nt * 8 + 2 * lc;
                if (r1 < n) *(__half2*)&Yh[(size_t)r1 * BN + col] = __floats2half2_rn(v[nt][0], v[nt][1]);
                if (r2 < n) *(__half2*)&Yh[(size_t)r2 * BN + col] = __floats2half2_rn(v[nt][2], v[nt][3]);
            }
        } else if (EPI == 2) {
            float s1 = 0.0f, s2 = 0.0f;
#pragma unroll
            for (int nt = 0; nt < 8; nt++) {
                s1 += v[nt][0] * v[nt][0] + v[nt][1] * v[nt][1];
                s2 += v[nt][2] * v[nt][2] + v[nt][3] * v[nt][3];
            }
            s1 += __shfl_xor_sync(0xffffffffu, s1, 1);
            s1 += __shfl_xor_sync(0xffffffffu, s1, 2);
            s2 += __shfl_xor_sync(0xffffffffu, s2, 1);
            s2 += __shfl_xor_sync(0xffffffffu, s2, 2);
            float i1 = 1.0f / fmaxf(sqrtf(s1), 1e-12f);
            float i2 = 1.0f / fmaxf(sqrtf(s2), 1e-12f);
#pragma unroll
            for (int nt = 0; nt < 8; nt++) {
                int col = warpCol + nt * 8 + 2 * lc;
                if (r1 < n) { float2 s = {rnd32(v[nt][0] * i1), rnd32(v[nt][1] * i1)}; *(float2*)&Y[(size_t)r1 * BN + col] = s; }
                if (r2 < n) { float2 s = {rnd32(v[nt][2] * i2), rnd32(v[nt][3] * i2)}; *(float2*)&Y[(size_t)r2 * BN + col] = s; }
            }
        } else { // EPI == 3
            float d1 = 0.0f, d2 = 0.0f;
#pragma unroll
            for (int nt = 0; nt < 8; nt++) {
                int col = warpCol + nt * 8 + 2 * lc;
                float w0 = __ldg(&Wn2[col]);
                float w1 = __ldg(&Wn2[col + 1]);
                d1 += v[nt][0] * w0 + v[nt][1] * w1;
                d2 += v[nt][2] * w0 + v[nt][3] * w1;
            }
            d1 += __shfl_xor_sync(0xffffffffu, d1, 1);
            d1 += __shfl_xor_sync(0xffffffffu, d1, 2);
            d2 += __shfl_xor_sync(0xffffffffu, d2, 1);
            d2 += __shfl_xor_sync(0xffffffffu, d2, 2);
            if (lc == 0) {
                float bb = __ldg(&bn2[0]);
                if (r1 < n) Y[r1] = d1 + bb;
                if (r2 < n) Y[r2] = d2 + bb;
            }
        }
    }
}

// ---------------- launch ------------------------------------------------------

extern "C" void kernel_launch(void* const* d_in, const int* in_sizes, int n_in,
                              void* d_out, int out_size) {
    const float* xA  = (const float*)d_in[0];
    const float* xB  = (const float*)d_in[1];
    const int*   eA  = (const int*)d_in[2];
    const int*   eB  = (const int*)d_in[3];
    const float* W1  = (const float*)d_in[4];
    const float* b1  = (const float*)d_in[5];
    const float* W2  = (const float*)d_in[6];
    const float* b2  = (const float*)d_in[7];
    const float* Wp1 = (const float*)d_in[8];
    const float* bp1 = (const float*)d_in[9];
    const float* Wp2 = (const float*)d_in[10];
    const float* bp2 = (const float*)d_in[11];
    const float* Wn1 = (const float*)d_in[12];
    const float* bn1 = (const float*)d_in[13];
    const float* Wn2 = (const float*)d_in[14];
    const float* bn2 = (const float*)d_in[15];

    float* out  = (float*)d_out;
    float* h    = out;                               // [2N,128] (hA | hB)
    float* z    = out + (size_t)NTOT * 128;          // [2N,64]
    float* nul  = z + (size_t)NTOT * 64;             // [2N]

    void* p;
    int* degcur;  cudaGetSymbolAddress(&p, g_degcur); degcur = (int*)p;
    float* agg;   cudaGetSymbolAddress(&p, g_agg);    agg    = (float*)p;
    uint2* xh;    cudaGetSymbolAddress(&p, g_xh);     xh     = (uint2*)p;
    uint2* hidh;  cudaGetSymbolAddress(&p, g_hidh);   hidh   = (uint2*)p;
    float* tmp;   cudaGetSymbolAddress(&p, g_tmp);    tmp    = (float*)p;
    float* w;     cudaGetSymbolAddress(&p, g_w);      w      = (float*)p;

    cudaMemsetAsync(degcur, 0, NTOT * sizeof(int));
    roundw_kernel<<<(57344 + 255) / 256, 256>>>(W1, W2, Wp1, Wp2, Wn1);
    conv_kernel<<<(NTOT * 32 + 255) / 256, 256>>>(xA, xB);
    degree_kernel<<<(2 * NEDGES + 255) / 256, 256>>>(eA, eB);
    scan_kernel<<<2, 1024>>>();
    fill_kernel<<<(2 * NEDGES + 255) / 256, 256>>>(eA, eB);

    const int gemmGrid = (NTOT + 127) / 128;
    const int aggGrid  = (NTOT * 32 + 255) / 256;

    size_t sh128 = (2 * 128 * ASTRIDE + 2 * 32 * (128 + 8)) * sizeof(float);
    size_t sh64  = (2 * 128 * ASTRIDE + 2 * 32 * (64 + 8)) * sizeof(float);
    cudaFuncSetAttribute(gemm_tc<128, 2, 4>, cudaFuncAttributeMaxDynamicSharedMemorySize, (int)sh128);
    cudaFuncSetAttribute(gemm_tc<128, 2, 0>, cudaFuncAttributeMaxDynamicSharedMemorySize, (int)sh128);
    cudaFuncSetAttribute(gemm_tc<64, 1, 1>,  cudaFuncAttributeMaxDynamicSharedMemorySize, (int)sh64);
    cudaFuncSetAttribute(gemm_tc<64, 1, 2>,  cudaFuncAttributeMaxDynamicSharedMemorySize, (int)sh64);
    cudaFuncSetAttribute(gemm_tc<64, 1, 3>,  cudaFuncAttributeMaxDynamicSharedMemorySize, (int)sh64);

    // layer 1: agg(x_fp16) -> relu(. @ W1 + b1) -> fp16 hid
    aggh_kernel<<<aggGrid, 256>>>(xh, agg);
    gemm_tc<128, 2, 4><<<gemmGrid, 256, sh128>>>(agg, 128, nullptr, 0, w + OW1, b1, (float*)hidh, NTOT, nullptr, nullptr);
    // layer 2: agg(hid_fp16) -> . @ W2 + b2   (encoder output h)
    aggh_kernel<<<aggGrid, 256>>>(hidh, agg);
    gemm_tc<128, 2, 0><<<gemmGrid, 256, sh128>>>(agg, 128, nullptr, 0, w + OW2, b2, h, NTOT, nullptr, nullptr);
    // proj: relu(h@Wp1+bp1) -> @Wp2+bp2 -> row-l2norm (fused)
    gemm_tc<64, 1, 1><<<gemmGrid, 256, sh64>>>(h, 128, nullptr, 0, w + OWP1, bp1, tmp, NTOT, nullptr, nullptr);
    gemm_tc<64, 1, 2><<<gemmGrid, 256, sh64>>>(tmp, 64, nullptr, 0, w + OWP2, bp2, z, NTOT, nullptr, nullptr);
    // null head: relu([h|z]@Wn1+bn1) . Wn2 + bn2 (fused dot)
    gemm_tc<64, 1, 3><<<gemmGrid, 256, sh64>>>(h, 128, z, 64, w + OWN1, bn1, nul, NTOT, Wn2, bn2);
}

// round 13
// speedup vs baseline: 1.7021x; 1.3067x over previous
#include <cuda_runtime.h>
#include <cuda_fp16.h>
#include <math.h>
#include <stdint.h>

#define NNODES 50000
#define NEDGES 800000
#define NTOT   (2 * NNODES)
#define NBLK   49                     // ceil(NNODES / 1024)

// ---------------- scratch (device globals; no allocations allowed) ----------
__device__ int   g_degcur[NTOT];
__device__ int   g_rowptr[2 * (NNODES + 1)];
__device__ int   g_csr_src[2 * NEDGES];        // unified src ids (graph B +NNODES)
__device__ float g_norm[NTOT];
__device__ float g_agg[NTOT * 128];
__device__ uint2 g_xh[NTOT * 32];              // fp16 features, unified [2N,128]
__device__ uint2 g_hidh[NTOT * 32];            // fp16 hidden layer
__device__ float g_tmp[NTOT * 64];
__device__ float g_w[57344];                   // tf32-rounded weights
__device__ int   g_bsum[2 * NBLK];             // per-block degree sums
__device__ int   g_boff[2 * NBLK];             // per-block exclusive offsets

#define OW1  0
#define OW2  16384
#define OWP1 32768
#define OWP2 40960
#define OWN1 45056

__device__ __forceinline__ uint32_t f2tf32(float f) {
    uint32_t u;
    asm volatile("cvt.rna.tf32.f32 %0, %1;" : "=r"(u) : "f"(f));
    return u;
}
__device__ __forceinline__ float rnd32(float f) {
    return __uint_as_float(f2tf32(f));
}
__device__ __forceinline__ float4 h4tof4(uint2 u) {
    __half2 h0 = *reinterpret_cast<__half2*>(&u.x);
    __half2 h1 = *reinterpret_cast<__half2*>(&u.y);
    float2 f0 = __half22float2(h0);
    float2 f1 = __half22float2(h1);
    float4 r; r.x = f0.x; r.y = f0.y; r.z = f1.x; r.w = f1.y;
    return r;
}

// ---------------- graph preprocessing ---------------------------------------

__global__ void degree_kernel(const int* __restrict__ eA, const int* __restrict__ eB) {
    int i = blockIdx.x * blockDim.x + threadIdx.x;
    if (i >= 2 * NEDGES) return;
    int g = i / NEDGES, e = i - g * NEDGES;
    const int* ei = g ? eB : eA;
    int dst = ei[NEDGES + e];
    atomicAdd(&g_degcur[g * NNODES + dst], 1);
}

// convert x (both graphs) to unified fp16 [2N,128]
__global__ void conv_kernel(const float* __restrict__ xA, const float* __restrict__ xB) {
    int i = blockIdx.x * blockDim.x + threadIdx.x;   // per 4 floats
    if (i >= NTOT * 32) return;
    const float4* src = (i < NNODES * 32) ? ((const float4*)xA + i)
                                          : ((const float4*)xB + (i - NNODES * 32));
    float4 v = __ldg(src);
    __half2 a = __floats2half2_rn(v.x, v.y);
    __half2 b = __floats2half2_rn(v.z, v.w);
    uint2 u;
    u.x = *reinterpret_cast<uint32_t*>(&a);
    u.y = *reinterpret_cast<uint32_t*>(&b);
    g_xh[i] = u;
}

// pre-round all GEMM weights to tf32 (RNA) once
__global__ void roundw_kernel(const float* __restrict__ W1, const float* __restrict__ W2,
                              const float* __restrict__ Wp1, const float* __restrict__ Wp2,
                              const float* __restrict__ Wn1) {
    int i = blockIdx.x * blockDim.x + threadIdx.x;
    if (i >= 57344) return;
    float v;
    if (i < 16384)      v = W1[i];
    else if (i < 32768) v = W2[i - 16384];
    else if (i < 40960) v = Wp1[i - 32768];
    else if (i < 45056) v = Wp2[i - 40960];
    else                v = Wn1[i - 45056];
    g_w[i] = rnd32(v);
}

// ---- parallel 3-level scan of degrees -> rowptr + cursor + norm -------------

// level 1: 2*NBLK blocks x 1024. Block-local inclusive scan; writes in-block
// exclusive prefix to rowptr, block total to g_bsum, and norm.
__global__ void scan1_kernel() {
    __shared__ int sm[1024];
    int g   = blockIdx.x / NBLK;
    int blk = blockIdx.x % NBLK;
    int t   = threadIdx.x;
    int idx = blk * 1024 + t;                 // node index within graph
    int d = 0;
    if (idx < NNODES) {
        d = g_degcur[g * NNODES + idx];
        g_norm[g * NNODES + idx] = rsqrtf((float)d + 1.0f);
    }
    sm[t] = d;
    __syncthreads();
    for (int s = 1; s < 1024; s <<= 1) {
        int v = sm[t];
        int a = (t >= s) ? sm[t - s] : 0;
        __syncthreads();
        sm[t] = v + a;
        __syncthreads();
    }
    if (idx < NNODES) g_rowptr[g * (NNODES + 1) + idx] = sm[t] - d;   // in-block exclusive
    if (t == 1023) g_bsum[blockIdx.x] = sm[1023];
}

// level 2: one block, segmented scan of 2*NBLK block sums (NBLK per graph)
__global__ void scan2_kernel() {
    __shared__ int sm[128];
    int t = threadIdx.x;
    int v = (t < 2 * NBLK) ? g_bsum[t] : 0;
    sm[t] = v;
    __syncthreads();
    int segStart = (t < NBLK) ? 0 : NBLK;
    for (int s = 1; s < 128; s <<= 1) {
        int cur = sm[t];
        int a = (t >= s && (t - s) >= segStart) ? sm[t - s] : 0;
        __syncthreads();
        sm[t] = cur + a;
        __syncthreads();
    }
    if (t < 2 * NBLK) {
        g_boff[t] = sm[t] - v;                            // exclusive within segment
        if (t == NBLK - 1)     g_rowptr[NNODES] = sm[t];                  // graph 0 total
        if (t == 2 * NBLK - 1) g_rowptr[(NNODES + 1) + NNODES] = sm[t];   // graph 1 total
    }
}

// level 3: add block offsets; finalize rowptr and fill cursor
__global__ void scan3_kernel() {
    int g   = blockIdx.x / NBLK;
    int blk = blockIdx.x % NBLK;
    int idx = blk * 1024 + threadIdx.x;
    if (idx >= NNODES) return;
    int v = g_rowptr[g * (NNODES + 1) + idx] + g_boff[blockIdx.x];
    g_rowptr[g * (NNODES + 1) + idx] = v;
    g_degcur[g * NNODES + idx] = v;
}

__global__ void fill_kernel(const int* __restrict__ eA, const int* __restrict__ eB) {
    int i = blockIdx.x * blockDim.x + threadIdx.x;
    if (i >= 2 * NEDGES) return;
    int g = i / NEDGES, e = i - g * NEDGES;
    const int* ei = g ? eB : eA;
    int src = ei[e];
    int dst = ei[NEDGES + e];
    int pos = atomicAdd(&g_degcur[g * NNODES + dst], 1);
    g_csr_src[g * NEDGES + pos] = src + g * NNODES;
}

// ---------------- GCN aggregation: warp per node, fp16 gathers ---------------
// out[d] = tf32rnd( norm[d] * ( sum_e norm[s]*x[s] + norm[d]*x[d] ) )
__global__ void aggh_kernel(const uint2* __restrict__ xh, float* __restrict__ out) {
    int node = (blockIdx.x * blockDim.x + threadIdx.x) >> 5;
    int lane = threadIdx.x & 31;
    if (node >= NTOT) return;
    int g = (node >= NNODES);
    int local = node - (g ? NNODES : 0);

    float nd = g_norm[node];
    float4 a = h4tof4(__ldg(&xh[node * 32 + lane]));
    float4 acc;
    acc.x = a.x * nd; acc.y = a.y * nd; acc.z = a.z * nd; acc.w = a.w * nd;

    int b  = g_rowptr[g * (NNODES + 1) + local]     + g * NEDGES;
    int en = g_rowptr[g * (NNODES + 1) + local + 1] + g * NEDGES;
    int e = b;
    for (; e + 4 <= en; e += 4) {
        int s0 = __ldg(&g_csr_src[e + 0]);
        int s1 = __ldg(&g_csr_src[e + 1]);
        int s2 = __ldg(&g_csr_src[e + 2]);
        int s3 = __ldg(&g_csr_src[e + 3]);
        float w0 = __ldg(&g_norm[s0]);
        float w1 = __ldg(&g_norm[s1]);
        float w2 = __ldg(&g_norm[s2]);
        float w3 = __ldg(&g_norm[s3]);
        float4 v0 = h4tof4(__ldg(&xh[(size_t)s0 * 32 + lane]));
        float4 v1 = h4tof4(__ldg(&xh[(size_t)s1 * 32 + lane]));
        float4 v2 = h4tof4(__ldg(&xh[(size_t)s2 * 32 + lane]));
        float4 v3 = h4tof4(__ldg(&xh[(size_t)s3 * 32 + lane]));
        acc.x += v0.x * w0 + v1.x * w1 + v2.x * w2 + v3.x * w3;
        acc.y += v0.y * w0 + v1.y * w1 + v2.y * w2 + v3.y * w3;
        acc.z += v0.z * w0 + v1.z * w1 + v2.z * w2 + v3.z * w3;
        acc.w += v0.w * w0 + v1.w * w1 + v2.w * w2 + v3.w * w3;
    }
    for (; e < en; e++) {
        int s = __ldg(&g_csr_src[e]);
        float w = __ldg(&g_norm[s]);
        float4 v = h4tof4(__ldg(&xh[(size_t)s * 32 + lane]));
        acc.x += v.x * w; acc.y += v.y * w; acc.z += v.z * w; acc.w += v.w * w;
    }
    acc.x = rnd32(acc.x * nd); acc.y = rnd32(acc.y * nd);
    acc.z = rnd32(acc.z * nd); acc.w = rnd32(acc.w * nd);
    ((float4*)out)[node * 32 + lane] = acc;
}

// ---------------- TF32 tensor-core GEMM --------------------------------------
// All X/W inputs pre-rounded to tf32 -> mainloop passes raw bits (no cvt).
// EPI: 0 none, 1 relu, 2 l2norm-row, 3 relu+dot(Wn2)+bn2, 4 relu+fp16 store
#define ASTRIDE 36

__device__ __forceinline__ void cpasync16(uint32_t dst, const void* src, bool pred) {
    int sz = pred ? 16 : 0;
    asm volatile("cp.async.cg.shared.global [%0], [%1], 16, %2;"
                 :: "r"(dst), "l"(src), "r"(sz));
}
__device__ __forceinline__ void mma_tf32(float* c, const uint32_t* a, const uint32_t* b) {
    asm volatile(
        "mma.sync.aligned.m16n8k8.row.col.f32.tf32.tf32.f32 "
        "{%0,%1,%2,%3}, {%4,%5,%6,%7}, {%8,%9}, {%0,%1,%2,%3};"
        : "+f"(c[0]), "+f"(c[1]), "+f"(c[2]), "+f"(c[3])
        : "r"(a[0]), "r"(a[1]), "r"(a[2]), "r"(a[3]), "r"(b[0]), "r"(b[1]));
}

template <int BN, int MT, int EPI>
__global__ void gemm_tc(const float* __restrict__ X1, int K1,
                        const float* __restrict__ X2, int K2,
                        const float* __restrict__ W,
                        const float* __restrict__ bias,
                        float* __restrict__ Y, int n,
                        const float* __restrict__ Wn2,
                        const float* __restrict__ bn2) {
    constexpr int SB = BN + 8;
    extern __shared__ float sm[];
    float* Ab = sm;                       // 2 * 128 * ASTRIDE
    float* Bb = sm + 2 * 128 * ASTRIDE;   // 2 * 32 * SB

    const int t = threadIdx.x;
    const int wid = t >> 5;
    const int lane = t & 31;
    const int lr = lane >> 2;
    const int lc = lane & 3;
    const int K = K1 + K2;
    const int T = K / 32;
    const int row0 = blockIdx.x * 128;

    constexpr int WROWS = (BN == 128) ? 4 : 8;
    const int warpRow = (wid % WROWS) * (MT * 16);
    const int warpCol = (wid / WROWS) * 64;

    float acc[MT][8][4];
#pragma unroll
    for (int m = 0; m < MT; m++)
#pragma unroll
        for (int nt = 0; nt < 8; nt++)
#pragma unroll
            for (int j = 0; j < 4; j++) acc[m][nt][j] = 0.0f;

    uint32_t aBase = (uint32_t)__cvta_generic_to_shared(Ab);
    uint32_t bBase = (uint32_t)__cvta_generic_to_shared(Bb);

    auto loadA = [&](int buf, int k0) {
#pragma unroll
        for (int i = 0; i < 4; i++) {
            int idx4 = t + i * 256;
            int row = idx4 >> 3;
            int kq = idx4 & 7;
            int kg = k0 + 4 * kq;
            int rg = row0 + row;
            const float* src = (kg < K1) ? (X1 + (size_t)rg * K1 + kg)
                                         : (X2 + (size_t)rg * K2 + (kg - K1));
            uint32_t dst = aBase + (uint32_t)((buf * 128 * ASTRIDE + row * ASTRIDE + 4 * kq) * 4);
            cpasync16(dst, src, rg < n);
        }
    };
    auto loadB = [&](int buf, int k0) {
        constexpr int ITER = (32 * BN) / (256 * 4);
#pragma unroll
        for (int i = 0; i < ITER; i++) {
            int idx4 = t + i * 256;
            int k = idx4 / (BN / 4);
            int cq = idx4 % (BN / 4);
            const float* src = W + (size_t)(k0 + k) * BN + 4 * cq;
            uint32_t dst = bBase + (uint32_t)((buf * 32 * SB + k * SB + 4 * cq) * 4);
            cpasync16(dst, src, true);
        }
    };

    loadA(0, 0);
    loadB(0, 0);
    asm volatile("cp.async.commit_group;");

    for (int tt = 0; tt < T; tt++) {
        int buf = tt & 1;
        if (tt + 1 < T) {
            loadA(buf ^ 1, (tt + 1) * 32);
            loadB(buf ^ 1, (tt + 1) * 32);
            asm volatile("cp.async.commit_group;");
            asm volatile("cp.async.wait_group 1;");
        } else {
            asm volatile("cp.async.wait_group 0;");
        }
        __syncthreads();

        const float* As = Ab + buf * 128 * ASTRIDE;
        const float* Bs = Bb + buf * 32 * SB;
#pragma unroll
        for (int kk8 = 0; kk8 < 4; kk8++) {
            int kb = kk8 * 8;
            uint32_t af[MT][4];
#pragma unroll
            for (int m = 0; m < MT; m++) {
                int r1 = warpRow + m * 16 + lr;
                af[m][0] = __float_as_uint(As[r1 * ASTRIDE + kb + lc]);
                af[m][1] = __float_as_uint(As[(r1 + 8) * ASTRIDE + kb + lc]);
                af[m][2] = __float_as_uint(As[r1 * ASTRIDE + kb + lc + 4]);
                af[m][3] = __float_as_uint(As[(r1 + 8) * ASTRIDE + kb + lc + 4]);
            }
            uint32_t bf[8][2];
#pragma unroll
            for (int nt = 0; nt < 8; nt++) {
                int cc = warpCol + nt * 8 + lr;
                bf[nt][0] = __float_as_uint(Bs[(kb + lc) * SB + cc]);
                bf[nt][1] = __float_as_uint(Bs[(kb + lc + 4) * SB + cc]);
            }
#pragma unroll
            for (int m = 0; m < MT; m++)
#pragma unroll
                for (int nt = 0; nt < 8; nt++)
                    mma_tf32(acc[m][nt], af[m], bf[nt]);
        }
        __syncthreads();
    }

    // ----------------- epilogue -----------------
#pragma unroll
    for (int m = 0; m < MT; m++) {
        int r1 = row0 + warpRow + m * 16 + lr;
        int r2 = r1 + 8;

        float v[8][4];
#pragma unroll
        for (int nt = 0; nt < 8; nt++) {
            int col = warpCol + nt * 8 + 2 * lc;
            float b0 = __ldg(&bias[col]);
            float b1 = __ldg(&bias[col + 1]);
            v[nt][0] = acc[m][nt][0] + b0;
            v[nt][1] = acc[m][nt][1] + b1;
            v[nt][2] = acc[m][nt][2] + b0;
            v[nt][3] = acc[m][nt][3] + b1;
            if (EPI == 1 || EPI == 3 || EPI == 4) {
#pragma unroll
                for (int j = 0; j < 4; j++) v[nt][j] = fmaxf(v[nt][j], 0.0f);
            }
        }

        if (EPI == 0 || EPI == 1) {
#pragma unroll
            for (int nt = 0; nt < 8; nt++) {
                int col = warpCol + nt * 8 + 2 * lc;
                if (r1 < n) { float2 s = {rnd32(v[nt][0]), rnd32(v[nt][1])}; *(float2*)&Y[(size_t)r1 * BN + col] = s; }
                if (r2 < n) { float2 s = {rnd32(v[nt][2]), rnd32(v[nt][3])}; *(float2*)&Y[(size_t)r2 * BN + col] = s; }
            }
        } else if (EPI == 4) {
            __half* Yh = (__half*)Y;
#pragma unroll
            for (int nt = 0; nt < 8; nt++) {
                int col = warpCol + nt * 8 + 2 * lc;
                if (r1 < n) *(__half2*)&Yh[(size_t)r1 * BN + col] = __floats2half2_rn(v[nt][0], v[nt][1]);
                if (r2 < n) *(__half2*)&Yh[(size_t)r2 * BN + col] = __floats2half2_rn(v[nt][2], v[nt][3]);
            }
        } else if (EPI == 2) {
            float s1 = 0.0f, s2 = 0.0f;
#pragma unroll
            for (int nt = 0; nt < 8; nt++) {
                s1 += v[nt][0] * v[nt][0] + v[nt][1] * v[nt][1];
                s2 += v[nt][2] * v[nt][2] + v[nt][3] * v[nt][3];
            }
            s1 += __shfl_xor_sync(0xffffffffu, s1, 1);
            s1 += __shfl_xor_sync(0xffffffffu, s1, 2);
            s2 += __shfl_xor_sync(0xffffffffu, s2, 1);
            s2 += __shfl_xor_sync(0xffffffffu, s2, 2);
            float i1 = 1.0f / fmaxf(sqrtf(s1), 1e-12f);
            float i2 = 1.0f / fmaxf(sqrtf(s2), 1e-12f);
#pragma unroll
            for (int nt = 0; nt < 8; nt++) {
                int col = warpCol + nt * 8 + 2 * lc;
                if (r1 < n) { float2 s = {rnd32(v[nt][0] * i1), rnd32(v[nt][1] * i1)}; *(float2*)&Y[(size_t)r1 * BN + col] = s; }
                if (r2 < n) { float2 s = {rnd32(v[nt][2] * i2), rnd32(v[nt][3] * i2)}; *(float2*)&Y[(size_t)r2 * BN + col] = s; }
            }
        } else { // EPI == 3
            float d1 = 0.0f, d2 = 0.0f;
#pragma unroll
            for (int nt = 0; nt < 8; nt++) {
                int col = warpCol + nt * 8 + 2 * lc;
                float w0 = __ldg(&Wn2[col]);
                float w1 = __ldg(&Wn2[col + 1]);
                d1 += v[nt][0] * w0 + v[nt][1] * w1;
                d2 += v[nt][2] * w0 + v[nt][3] * w1;
            }
            d1 += __shfl_xor_sync(0xffffffffu, d1, 1);
            d1 += __shfl_xor_sync(0xffffffffu, d1, 2);
            d2 += __shfl_xor_sync(0xffffffffu, d2, 1);
            d2 += __shfl_xor_sync(0xffffffffu, d2, 2);
            if (lc == 0) {
                float bb = __ldg(&bn2[0]);
                if (r1 < n) Y[r1] = d1 + bb;
                if (r2 < n) Y[r2] = d2 + bb;
            }
        }
    }
}

// ---------------- launch ------------------------------------------------------

extern "C" void kernel_launch(void* const* d_in, const int* in_sizes, int n_in,
                              void* d_out, int out_size) {
    const float* xA  = (const float*)d_in[0];
    const float* xB  = (const float*)d_in[1];
    const int*   eA  = (const int*)d_in[2];
    const int*   eB  = (const int*)d_in[3];
    const float* W1  = (const float*)d_in[4];
    const float* b1  = (const float*)d_in[5];
    const float* W2  = (const float*)d_in[6];
    const float* b2  = (const float*)d_in[7];
    const float* Wp1 = (const float*)d_in[8];
    const float* bp1 = (const float*)d_in[9];
    const float* Wp2 = (const float*)d_in[10];
    const float* bp2 = (const float*)d_in[11];
    const float* Wn1 = (const float*)d_in[12];
    const float* bn1 = (const float*)d_in[13];
    const float* Wn2 = (const float*)d_in[14];
    const float* bn2 = (const float*)d_in[15];

    float* out  = (float*)d_out;
    float* h    = out;                               // [2N,128] (hA | hB)
    float* z    = out + (size_t)NTOT * 128;          // [2N,64]
    float* nul  = z + (size_t)NTOT * 64;             // [2N]

    void* p;
    int* degcur;  cudaGetSymbolAddress(&p, g_degcur); degcur = (int*)p;
    float* agg;   cudaGetSymbolAddress(&p, g_agg);    agg    = (float*)p;
    uint2* xh;    cudaGetSymbolAddress(&p, g_xh);     xh     = (uint2*)p;
    uint2* hidh;  cudaGetSymbolAddress(&p, g_hidh);   hidh   = (uint2*)p;
    float* tmp;   cudaGetSymbolAddress(&p, g_tmp);    tmp    = (float*)p;
    float* w;     cudaGetSymbolAddress(&p, g_w);      w      = (float*)p;

    cudaMemsetAsync(degcur, 0, NTOT * sizeof(int));
    roundw_kernel<<<(57344 + 255) / 256, 256>>>(W1, W2, Wp1, Wp2, Wn1);
    conv_kernel<<<(NTOT * 32 + 255) / 256, 256>>>(xA, xB);
    degree_kernel<<<(2 * NEDGES + 255) / 256, 256>>>(eA, eB);
    scan1_kernel<<<2 * NBLK, 1024>>>();
    scan2_kernel<<<1, 128>>>();
    scan3_kernel<<<2 * NBLK, 1024>>>();
    fill_kernel<<<(2 * NEDGES + 255) / 256, 256>>>(eA, eB);

    const int gemmGrid = (NTOT + 127) / 128;
    const int aggGrid  = (NTOT * 32 + 255) / 256;

    size_t sh128 = (2 * 128 * ASTRIDE + 2 * 32 * (128 + 8)) * sizeof(float);
    size_t sh64  = (2 * 128 * ASTRIDE + 2 * 32 * (64 + 8)) * sizeof(float);
    cudaFuncSetAttribute(gemm_tc<128, 2, 4>, cudaFuncAttributeMaxDynamicSharedMemorySize, (int)sh128);
    cudaFuncSetAttribute(gemm_tc<128, 2, 0>, cudaFuncAttributeMaxDynamicSharedMemorySize, (int)sh128);
    cudaFuncSetAttribute(gemm_tc<64, 1, 1>,  cudaFuncAttributeMaxDynamicSharedMemorySize, (int)sh64);
    cudaFuncSetAttribute(gemm_tc<64, 1, 2>,  cudaFuncAttributeMaxDynamicSharedMemorySize, (int)sh64);
    cudaFuncSetAttribute(gemm_tc<64, 1, 3>,  cudaFuncAttributeMaxDynamicSharedMemorySize, (int)sh64);

    // layer 1: agg(x_fp16) -> relu(. @ W1 + b1) -> fp16 hid
    aggh_kernel<<<aggGrid, 256>>>(xh, agg);
    gemm_tc<128, 2, 4><<<gemmGrid, 256, sh128>>>(agg, 128, nullptr, 0, w + OW1, b1, (float*)hidh, NTOT, nullptr, nullptr);
    // layer 2: agg(hid_fp16) -> . @ W2 + b2   (encoder output h)
    aggh_kernel<<<aggGrid, 256>>>(hidh, agg);
    gemm_tc<128, 2, 0><<<gemmGrid, 256, sh128>>>(agg, 128, nullptr, 0, w + OW2, b2, h, NTOT, nullptr, nullptr);
    // proj: relu(h@Wp1+bp1) -> @Wp2+bp2 -> row-l2norm (fused)
    gemm_tc<64, 1, 1><<<gemmGrid, 256, sh64>>>(h, 128, nullptr, 0, w + OWP1, bp1, tmp, NTOT, nullptr, nullptr);
    gemm_tc<64, 1, 2><<<gemmGrid, 256, sh64>>>(tmp, 64, nullptr, 0, w + OWP2, bp2, z, NTOT, nullptr, nullptr);
    // null head: relu([h|z]@Wn1+bn1) . Wn2 + bn2 (fused dot)
    gemm_tc<64, 1, 3><<<gemmGrid, 256, sh64>>>(h, 128, z, 64, w + OWN1, bn1, nul, NTOT, Wn2, bn2);
}

// round 15
// speedup vs baseline: 1.7251x; 1.0135x over previous
#include <cuda_runtime.h>
#include <cuda_fp16.h>
#include <math.h>
#include <stdint.h>

#define NNODES 50000
#define NEDGES 800000
#define NTOT   (2 * NNODES)
#define NBLK   49                     // ceil(NNODES / 1024)

// ---------------- scratch (device globals; no allocations allowed) ----------
__device__ int   g_degcur[NTOT];
__device__ int   g_rowptr[2 * (NNODES + 1)];
__device__ int   g_csr_src[2 * NEDGES];        // unified src ids (graph B +NNODES)
__device__ float g_norm[NTOT];
__device__ float g_agg[NTOT * 128];
__device__ uint2 g_xh[NTOT * 32];              // fp16 features, unified [2N,128]
__device__ uint2 g_hidh[NTOT * 32];            // fp16 hidden layer
__device__ float g_w[57344];                   // tf32-rounded weights
__device__ int   g_bsum[2 * NBLK];             // per-block degree sums
__device__ int   g_boff[2 * NBLK];             // per-block exclusive offsets

#define OW1  0
#define OW2  16384
#define OWP1 32768
#define OWP2 40960
#define OWN1 45056

__device__ __forceinline__ uint32_t f2tf32(float f) {
    uint32_t u;
    asm volatile("cvt.rna.tf32.f32 %0, %1;" : "=r"(u) : "f"(f));
    return u;
}
__device__ __forceinline__ float rnd32(float f) {
    return __uint_as_float(f2tf32(f));
}
__device__ __forceinline__ float4 h4tof4(uint2 u) {
    __half2 h0 = *reinterpret_cast<__half2*>(&u.x);
    __half2 h1 = *reinterpret_cast<__half2*>(&u.y);
    float2 f0 = __half22float2(h0);
    float2 f1 = __half22float2(h1);
    float4 r; r.x = f0.x; r.y = f0.y; r.z = f1.x; r.w = f1.y;
    return r;
}

// ---------------- graph preprocessing ---------------------------------------

__global__ void degree_kernel(const int* __restrict__ eA, const int* __restrict__ eB) {
    int i = blockIdx.x * blockDim.x + threadIdx.x;
    if (i >= 2 * NEDGES) return;
    int g = i / NEDGES, e = i - g * NEDGES;
    const int* ei = g ? eB : eA;
    int dst = ei[NEDGES + e];
    atomicAdd(&g_degcur[g * NNODES + dst], 1);
}

// convert x (both graphs) to unified fp16 [2N,128]
__global__ void conv_kernel(const float* __restrict__ xA, const float* __restrict__ xB) {
    int i = blockIdx.x * blockDim.x + threadIdx.x;   // per 4 floats
    if (i >= NTOT * 32) return;
    const float4* src = (i < NNODES * 32) ? ((const float4*)xA + i)
                                          : ((const float4*)xB + (i - NNODES * 32));
    float4 v = __ldg(src);
    __half2 a = __floats2half2_rn(v.x, v.y);
    __half2 b = __floats2half2_rn(v.z, v.w);
    uint2 u;
    u.x = *reinterpret_cast<uint32_t*>(&a);
    u.y = *reinterpret_cast<uint32_t*>(&b);
    g_xh[i] = u;
}

// pre-round all GEMM weights to tf32 (RNA) once
__global__ void roundw_kernel(const float* __restrict__ W1, const float* __restrict__ W2,
                              const float* __restrict__ Wp1, const float* __restrict__ Wp2,
                              const float* __restrict__ Wn1) {
    int i = blockIdx.x * blockDim.x + threadIdx.x;
    if (i >= 57344) return;
    float v;
    if (i < 16384)      v = W1[i];
    else if (i < 32768) v = W2[i - 16384];
    else if (i < 40960) v = Wp1[i - 32768];
    else if (i < 45056) v = Wp2[i - 40960];
    else                v = Wn1[i - 45056];
    g_w[i] = rnd32(v);
}

// ---- parallel 3-level scan of degrees -> rowptr + cursor + norm -------------

__global__ void scan1_kernel() {
    __shared__ int sm[1024];
    int g   = blockIdx.x / NBLK;
    int blk = blockIdx.x % NBLK;
    int t   = threadIdx.x;
    int idx = blk * 1024 + t;
    int d = 0;
    if (idx < NNODES) {
        d = g_degcur[g * NNODES + idx];
        g_norm[g * NNODES + idx] = rsqrtf((float)d + 1.0f);
    }
    sm[t] = d;
    __syncthreads();
    for (int s = 1; s < 1024; s <<= 1) {
        int v = sm[t];
        int a = (t >= s) ? sm[t - s] : 0;
        __syncthreads();
        sm[t] = v + a;
        __syncthreads();
    }
    if (idx < NNODES) g_rowptr[g * (NNODES + 1) + idx] = sm[t] - d;
    if (t == 1023) g_bsum[blockIdx.x] = sm[1023];
}

__global__ void scan2_kernel() {
    __shared__ int sm[128];
    int t = threadIdx.x;
    int v = (t < 2 * NBLK) ? g_bsum[t] : 0;
    sm[t] = v;
    __syncthreads();
    int segStart = (t < NBLK) ? 0 : NBLK;
    for (int s = 1; s < 128; s <<= 1) {
        int cur = sm[t];
        int a = (t >= s && (t - s) >= segStart) ? sm[t - s] : 0;
        __syncthreads();
        sm[t] = cur + a;
        __syncthreads();
    }
    if (t < 2 * NBLK) {
        g_boff[t] = sm[t] - v;
        if (t == NBLK - 1)     g_rowptr[NNODES] = sm[t];
        if (t == 2 * NBLK - 1) g_rowptr[(NNODES + 1) + NNODES] = sm[t];
    }
}

__global__ void scan3_kernel() {
    int g   = blockIdx.x / NBLK;
    int blk = blockIdx.x % NBLK;
    int idx = blk * 1024 + threadIdx.x;
    if (idx >= NNODES) return;
    int v = g_rowptr[g * (NNODES + 1) + idx] + g_boff[blockIdx.x];
    g_rowptr[g * (NNODES + 1) + idx] = v;
    g_degcur[g * NNODES + idx] = v;
}

__global__ void fill_kernel(const int* __restrict__ eA, const int* __restrict__ eB) {
    int i = blockIdx.x * blockDim.x + threadIdx.x;
    if (i >= 2 * NEDGES) return;
    int g = i / NEDGES, e = i - g * NEDGES;
    const int* ei = g ? eB : eA;
    int src = ei[e];
    int dst = ei[NEDGES + e];
    int pos = atomicAdd(&g_degcur[g * NNODES + dst], 1);
    g_csr_src[g * NEDGES + pos] = src + g * NNODES;
}

// ---------------- GCN aggregation: warp per node, fp16 gathers ---------------
__global__ void aggh_kernel(const uint2* __restrict__ xh, float* __restrict__ out) {
    int node = (blockIdx.x * blockDim.x + threadIdx.x) >> 5;
    int lane = threadIdx.x & 31;
    if (node >= NTOT) return;
    int g = (node >= NNODES);
    int local = node - (g ? NNODES : 0);

    float nd = g_norm[node];
    float4 a = h4tof4(__ldg(&xh[node * 32 + lane]));
    float4 acc;
    acc.x = a.x * nd; acc.y = a.y * nd; acc.z = a.z * nd; acc.w = a.w * nd;

    int b  = g_rowptr[g * (NNODES + 1) + local]     + g * NEDGES;
    int en = g_rowptr[g * (NNODES + 1) + local + 1] + g * NEDGES;
    int e = b;
    for (; e + 4 <= en; e += 4) {
        int s0 = __ldg(&g_csr_src[e + 0]);
        int s1 = __ldg(&g_csr_src[e + 1]);
        int s2 = __ldg(&g_csr_src[e + 2]);
        int s3 = __ldg(&g_csr_src[e + 3]);
        float w0 = __ldg(&g_norm[s0]);
        float w1 = __ldg(&g_norm[s1]);
        float w2 = __ldg(&g_norm[s2]);
        float w3 = __ldg(&g_norm[s3]);
        float4 v0 = h4tof4(__ldg(&xh[(size_t)s0 * 32 + lane]));
        float4 v1 = h4tof4(__ldg(&xh[(size_t)s1 * 32 + lane]));
        float4 v2 = h4tof4(__ldg(&xh[(size_t)s2 * 32 + lane]));
        float4 v3 = h4tof4(__ldg(&xh[(size_t)s3 * 32 + lane]));
        acc.x += v0.x * w0 + v1.x * w1 + v2.x * w2 + v3.x * w3;
        acc.y += v0.y * w0 + v1.y * w1 + v2.y * w2 + v3.y * w3;
        acc.z += v0.z * w0 + v1.z * w1 + v2.z * w2 + v3.z * w3;
        acc.w += v0.w * w0 + v1.w * w1 + v2.w * w2 + v3.w * w3;
    }
    for (; e < en; e++) {
        int s = __ldg(&g_csr_src[e]);
        float w = __ldg(&g_norm[s]);
        float4 v = h4tof4(__ldg(&xh[(size_t)s * 32 + lane]));
        acc.x += v.x * w; acc.y += v.y * w; acc.z += v.z * w; acc.w += v.w * w;
    }
    acc.x = rnd32(acc.x * nd); acc.y = rnd32(acc.y * nd);
    acc.z = rnd32(acc.z * nd); acc.w = rnd32(acc.w * nd);
    ((float4*)out)[node * 32 + lane] = acc;
}

// ---------------- TF32 tensor-core GEMM --------------------------------------
// All X/W inputs pre-rounded to tf32 -> mainloop passes raw bits (no cvt).
// EPI: 0 none, 3 relu+dot(Wn2)+bn2, 4 relu+fp16 store
#define ASTRIDE 36

__device__ __forceinline__ void cpasync16(uint32_t dst, const void* src, bool pred) {
    int sz = pred ? 16 : 0;
    asm volatile("cp.async.cg.shared.global [%0], [%1], 16, %2;"
                 :: "r"(dst), "l"(src), "r"(sz));
}
__device__ __forceinline__ void mma_tf32(float* c, const uint32_t* a, const uint32_t* b) {
    asm volatile(
        "mma.sync.aligned.m16n8k8.row.col.f32.tf32.tf32.f32 "
        "{%0,%1,%2,%3}, {%4,%5,%6,%7}, {%8,%9}, {%0,%1,%2,%3};"
        : "+f"(c[0]), "+f"(c[1]), "+f"(c[2]), "+f"(c[3])
        : "r"(a[0]), "r"(a[1]), "r"(a[2]), "r"(a[3]), "r"(b[0]), "r"(b[1]));
}

template <int BN, int MT, int EPI>
__global__ void gemm_tc(const float* __restrict__ X1, int K1,
                        const float* __restrict__ X2, int K2,
                        const float* __restrict__ W,
                        const float* __restrict__ bias,
                        float* __restrict__ Y, int n,
                        const float* __restrict__ Wn2,
                        const float* __restrict__ bn2) {
    constexpr int SB = BN + 8;
    extern __shared__ float sm[];
    float* Ab = sm;                       // 2 * 128 * ASTRIDE
    float* Bb = sm + 2 * 128 * ASTRIDE;   // 2 * 32 * SB

    const int t = threadIdx.x;
    const int wid = t >> 5;
    const int lane = t & 31;
    const int lr = lane >> 2;
    const int lc = lane & 3;
    const int K = K1 + K2;
    const int T = K / 32;
    const int row0 = blockIdx.x * 128;

    constexpr int WROWS = (BN == 128) ? 4 : 8;
    const int warpRow = (wid % WROWS) * (MT * 16);
    const int warpCol = (wid / WROWS) * 64;

    float acc[MT][8][4];
#pragma unroll
    for (int m = 0; m < MT; m++)
#pragma unroll
        for (int nt = 0; nt < 8; nt++)
#pragma unroll
            for (int j = 0; j < 4; j++) acc[m][nt][j] = 0.0f;

    uint32_t aBase = (uint32_t)__cvta_generic_to_shared(Ab);
    uint32_t bBase = (uint32_t)__cvta_generic_to_shared(Bb);

    auto loadA = [&](int buf, int k0) {
#pragma unroll
        for (int i = 0; i < 4; i++) {
            int idx4 = t + i * 256;
            int row = idx4 >> 3;
            int kq = idx4 & 7;
            int kg = k0 + 4 * kq;
            int rg = row0 + row;
            const float* src = (kg < K1) ? (X1 + (size_t)rg * K1 + kg)
                                         : (X2 + (size_t)rg * K2 + (kg - K1));
            uint32_t dst = aBase + (uint32_t)((buf * 128 * ASTRIDE + row * ASTRIDE + 4 * kq) * 4);
            cpasync16(dst, src, rg < n);
        }
    };
    auto loadB = [&](int buf, int k0) {
        constexpr int ITER = (32 * BN) / (256 * 4);
#pragma unroll
        for (int i = 0; i < ITER; i++) {
            int idx4 = t + i * 256;
            int k = idx4 / (BN / 4);
            int cq = idx4 % (BN / 4);
            const float* src = W + (size_t)(k0 + k) * BN + 4 * cq;
            uint32_t dst = bBase + (uint32_t)((buf * 32 * SB + k * SB + 4 * cq) * 4);
            cpasync16(dst, src, true);
        }
    };

    loadA(0, 0);
    loadB(0, 0);
    asm volatile("cp.async.commit_group;");

    for (int tt = 0; tt < T; tt++) {
        int buf = tt & 1;
        if (tt + 1 < T) {
            loadA(buf ^ 1, (tt + 1) * 32);
            loadB(buf ^ 1, (tt + 1) * 32);
            asm volatile("cp.async.commit_group;");
            asm volatile("cp.async.wait_group 1;");
        } else {
            asm volatile("cp.async.wait_group 0;");
        }
        __syncthreads();

        const float* As = Ab + buf * 128 * ASTRIDE;
        const float* Bs = Bb + buf * 32 * SB;
#pragma unroll
        for (int kk8 = 0; kk8 < 4; kk8++) {
            int kb = kk8 * 8;
            uint32_t af[MT][4];
#pragma unroll
            for (int m = 0; m < MT; m++) {
                int r1 = warpRow + m * 16 + lr;
                af[m][0] = __float_as_uint(As[r1 * ASTRIDE + kb + lc]);
                af[m][1] = __float_as_uint(As[(r1 + 8) * ASTRIDE + kb + lc]);
                af[m][2] = __float_as_uint(As[r1 * ASTRIDE + kb + lc + 4]);
                af[m][3] = __float_as_uint(As[(r1 + 8) * ASTRIDE + kb + lc + 4]);
            }
            uint32_t bf[8][2];
#pragma unroll
            for (int nt = 0; nt < 8; nt++) {
                int cc = warpCol + nt * 8 + lr;
                bf[nt][0] = __float_as_uint(Bs[(kb + lc) * SB + cc]);
                bf[nt][1] = __float_as_uint(Bs[(kb + lc + 4) * SB + cc]);
            }
#pragma unroll
            for (int m = 0; m < MT; m++)
#pragma unroll
                for (int nt = 0; nt < 8; nt++)
                    mma_tf32(acc[m][nt], af[m], bf[nt]);
        }
        __syncthreads();
    }

    // ----------------- epilogue -----------------
#pragma unroll
    for (int m = 0; m < MT; m++) {
        int r1 = row0 + warpRow + m * 16 + lr;
        int r2 = r1 + 8;

        float v[8][4];
#pragma unroll
        for (int nt = 0; nt < 8; nt++) {
            int col = warpCol + nt * 8 + 2 * lc;
            float b0 = __ldg(&bias[col]);
            float b1 = __ldg(&bias[col + 1]);
            v[nt][0] = acc[m][nt][0] + b0;
            v[nt][1] = acc[m][nt][1] + b1;
            v[nt][2] = acc[m][nt][2] + b0;
            v[nt][3] = acc[m][nt][3] + b1;
            if (EPI == 3 || EPI == 4) {
#pragma unroll
                for (int j = 0; j < 4; j++) v[nt][j] = fmaxf(v[nt][j], 0.0f);
            }
        }

        if (EPI == 0) {
#pragma unroll
            for (int nt = 0; nt < 8; nt++) {
                int col = warpCol + nt * 8 + 2 * lc;
                if (r1 < n) { float2 s = {rnd32(v[nt][0]), rnd32(v[nt][1])}; *(float2*)&Y[(size_t)r1 * BN + col] = s; }
                if (r2 < n) { float2 s = {rnd32(v[nt][2]), rnd32(v[nt][3])}; *(float2*)&Y[(size_t)r2 * BN + col] = s; }
            }
        } else if (EPI == 4) {
            __half* Yh = (__half*)Y;
#pragma unroll
            for (int nt = 0; nt < 8; nt++) {
                int col = warpCol + nt * 8 + 2 * lc;
                if (r1 < n) *(__half2*)&Yh[(size_t)r1 * BN + col] = __floats2half2_rn(v[nt][0], v[nt][1]);
                if (r2 < n) *(__half2*)&Yh[(size_t)r2 * BN + col] = __floats2half2_rn(v[nt][2], v[nt][3]);
            }
        } else { // EPI == 3
            float d1 = 0.0f, d2 = 0.0f;
#pragma unroll
            for (int nt = 0; nt < 8; nt++) {
                int col = warpCol + nt * 8 + 2 * lc;
                float w0 = __ldg(&Wn2[col]);
                float w1 = __ldg(&Wn2[col + 1]);
                d1 += v[nt][0] * w0 + v[nt][1] * w1;
                d2 += v[nt][2] * w0 + v[nt][3] * w1;
            }
            d1 += __shfl_xor_sync(0xffffffffu, d1, 1);
            d1 += __shfl_xor_sync(0xffffffffu, d1, 2);
            d2 += __shfl_xor_sync(0xffffffffu, d2, 1);
            d2 += __shfl_xor_sync(0xffffffffu, d2, 2);
            if (lc == 0) {
                float bb = __ldg(&bn2[0]);
                if (r1 < n) Y[r1] = d1 + bb;
                if (r2 < n) Y[r2] = d2 + bb;
            }
        }
    }
}

// ============================================================================
// Fused projection: z = l2norm( relu(h@Wp1+bp1) @ Wp2 + bp2 )
// Stage-1 result stored tf32-rounded in smem (bit-identical to 2-kernel path).
// smem: Ab 2*128*36, Wb 2*32*72, Ts 128*68  (90,112 B)
// ============================================================================
#define PW_STRIDE 72
#define TS_STRIDE 68

__global__ void proj_fused(const float* __restrict__ h,
                           const float* __restrict__ Wp1, const float* __restrict__ bp1,
                           const float* __restrict__ Wp2, const float* __restrict__ bp2,
                           float* __restrict__ z) {
    extern __shared__ float sm[];
    float* Ab = sm;                                   // 2*128*36
    float* Wb = sm + 2 * 128 * ASTRIDE;               // 2*32*72
    float* Ts = Wb + 2 * 32 * PW_STRIDE;              // 128*68

    const int t = threadIdx.x;
    const int wid = t >> 5;
    const int lane = t & 31;
    const int lr = lane >> 2;
    const int lc = lane & 3;
    const int row0 = blockIdx.x * 128;
    const int warpRow = wid * 16;

    uint32_t aBase = (uint32_t)__cvta_generic_to_shared(Ab);
    uint32_t bBase = (uint32_t)__cvta_generic_to_shared(Wb);

    auto loadA = [&](int buf, int k0) {
#pragma unroll
        for (int i = 0; i < 4; i++) {
            int idx4 = t + i * 256;
            int row = idx4 >> 3;
            int kq = idx4 & 7;
            int rg = row0 + row;
            uint32_t dst = aBase + (uint32_t)((buf * 128 * ASTRIDE + row * ASTRIDE + 4 * kq) * 4);
            cpasync16(dst, h + (size_t)rg * 128 + k0 + 4 * kq, rg < NTOT);
        }
    };
    auto loadW = [&](const float* W, int buf, int k0) {
#pragma unroll
        for (int i = 0; i < 2; i++) {
            int idx4 = t + i * 256;
            int k = idx4 >> 4;
            int cq = idx4 & 15;
            uint32_t dst = bBase + (uint32_t)((buf * 32 * PW_STRIDE + k * PW_STRIDE + 4 * cq) * 4);
            cpasync16(dst, W + (size_t)(k0 + k) * 64 + 4 * cq, true);
        }
    };

    float acc[8][4];
#pragma unroll
    for (int nt = 0; nt < 8; nt++)
#pragma unroll
        for (int j = 0; j < 4; j++) acc[nt][j] = 0.0f;

    // ---------------- stage 1: Ts = rnd32(relu(h @ Wp1 + bp1)) ----------------
    loadA(0, 0);
    loadW(Wp1, 0, 0);
    asm volatile("cp.async.commit_group;");

    for (int tt = 0; tt < 4; tt++) {
        int buf = tt & 1;
        if (tt < 3) {
            loadA(buf ^ 1, (tt + 1) * 32);
            loadW(Wp1, buf ^ 1, (tt + 1) * 32);
            asm volatile("cp.async.commit_group;");
            asm volatile("cp.async.wait_group 1;");
        } else {
            asm volatile("cp.async.wait_group 0;");
        }
        __syncthreads();
        const float* As = Ab + buf * 128 * ASTRIDE;
        const float* Bs = Wb + buf * 32 * PW_STRIDE;
#pragma unroll
        for (int kk8 = 0; kk8 < 4; kk8++) {
            int kb = kk8 * 8;
            uint32_t af[4];
            int r1 = warpRow + lr;
            af[0] = __float_as_uint(As[r1 * ASTRIDE + kb + lc]);
            af[1] = __float_as_uint(As[(r1 + 8) * ASTRIDE + kb + lc]);
            af[2] = __float_as_uint(As[r1 * ASTRIDE + kb + lc + 4]);
            af[3] = __float_as_uint(As[(r1 + 8) * ASTRIDE + kb + lc + 4]);
            uint32_t bf[8][2];
#pragma unroll
            for (int nt = 0; nt < 8; nt++) {
                int cc = nt * 8 + lr;
                bf[nt][0] = __float_as_uint(Bs[(kb + lc) * PW_STRIDE + cc]);
                bf[nt][1] = __float_as_uint(Bs[(kb + lc + 4) * PW_STRIDE + cc]);
            }
#pragma unroll
            for (int nt = 0; nt < 8; nt++)
                mma_tf32(acc[nt], af, bf[nt]);
        }
        __syncthreads();
    }

    {
        int r1l = warpRow + lr;
        int r2l = r1l + 8;
#pragma unroll
        for (int nt = 0; nt < 8; nt++) {
            int col = nt * 8 + 2 * lc;
            float b0 = __ldg(&bp1[col]);
            float b1 = __ldg(&bp1[col + 1]);
            Ts[r1l * TS_STRIDE + col]     = rnd32(fmaxf(acc[nt][0] + b0, 0.f));
            Ts[r1l * TS_STRIDE + col + 1] = rnd32(fmaxf(acc[nt][1] + b1, 0.f));
            Ts[r2l * TS_STRIDE + col]     = rnd32(fmaxf(acc[nt][2] + b0, 0.f));
            Ts[r2l * TS_STRIDE + col + 1] = rnd32(fmaxf(acc[nt][3] + b1, 0.f));
        }
    }
    __syncthreads();

    // ---------------- stage 2: z = l2norm(Ts @ Wp2 + bp2) ----------------
#pragma unroll
    for (int nt = 0; nt < 8; nt++)
#pragma unroll
        for (int j = 0; j < 4; j++) acc[nt][j] = 0.0f;

    loadW(Wp2, 0, 0);
    asm volatile("cp.async.commit_group;");

    for (int tt = 0; tt < 2; tt++) {
        int buf = tt & 1;
        if (tt < 1) {
            loadW(Wp2, buf ^ 1, 32);
            asm volatile("cp.async.commit_group;");
            asm volatile("cp.async.wait_group 1;");
        } else {
            asm volatile("cp.async.wait_group 0;");
        }
        __syncthreads();
        const float* Bs = Wb + buf * 32 * PW_STRIDE;
#pragma unroll
        for (int kk8 = 0; kk8 < 4; kk8++) {
            int kb = kk8 * 8;
            int col = tt * 32 + kb + lc;
            uint32_t af[4];
            int r1 = warpRow + lr;
            af[0] = __float_as_uint(Ts[r1 * TS_STRIDE + col]);
            af[1] = __float_as_uint(Ts[(r1 + 8) * TS_STRIDE + col]);
            af[2] = __float_as_uint(Ts[r1 * TS_STRIDE + col + 4]);
            af[3] = __float_as_uint(Ts[(r1 + 8) * TS_STRIDE + col + 4]);
            uint32_t bf[8][2];
#pragma unroll
            for (int nt = 0; nt < 8; nt++) {
                int cc = nt * 8 + lr;
                bf[nt][0] = __float_as_uint(Bs[(kb + lc) * PW_STRIDE + cc]);
                bf[nt][1] = __float_as_uint(Bs[(kb + lc + 4) * PW_STRIDE + cc]);
            }
#pragma unroll
            for (int nt = 0; nt < 8; nt++)
                mma_tf32(acc[nt], af, bf[nt]);
        }
        __syncthreads();
    }

    {
        int r1 = row0 + warpRow + lr;
        int r2 = r1 + 8;
        float v[8][4];
#pragma unroll
        for (int nt = 0; nt < 8; nt++) {
            int col = nt * 8 + 2 * lc;
            float b0 = __ldg(&bp2[col]);
            float b1 = __ldg(&bp2[col + 1]);
            v[nt][0] = acc[nt][0] + b0;
            v[nt][1] = acc[nt][1] + b1;
            v[nt][2] = acc[nt][2] + b0;
            v[nt][3] = acc[nt][3] + b1;
        }
        float s1 = 0.f, s2 = 0.f;
#pragma unroll
        for (int nt = 0; nt < 8; nt++) {
            s1 += v[nt][0] * v[nt][0] + v[nt][1] * v[nt][1];
            s2 += v[nt][2] * v[nt][2] + v[nt][3] * v[nt][3];
        }
        s1 += __shfl_xor_sync(0xffffffffu, s1, 1);
        s1 += __shfl_xor_sync(0xffffffffu, s1, 2);
        s2 += __shfl_xor_sync(0xffffffffu, s2, 1);
        s2 += __shfl_xor_sync(0xffffffffu, s2, 2);
        float i1 = 1.0f / fmaxf(sqrtf(s1), 1e-12f);
        float i2 = 1.0f / fmaxf(sqrtf(s2), 1e-12f);
#pragma unroll
        for (int nt = 0; nt < 8; nt++) {
            int col = nt * 8 + 2 * lc;
            if (r1 < NTOT) { float2 s = {rnd32(v[nt][0] * i1), rnd32(v[nt][1] * i1)}; *(float2*)&z[(size_t)r1 * 64 + col] = s; }
            if (r2 < NTOT) { float2 s = {rnd32(v[nt][2] * i2), rnd32(v[nt][3] * i2)}; *(float2*)&z[(size_t)r2 * 64 + col] = s; }
        }
    }
}

// ---------------- launch ------------------------------------------------------

extern "C" void kernel_launch(void* const* d_in, const int* in_sizes, int n_in,
                              void* d_out, int out_size) {
    const float* xA  = (const float*)d_in[0];
    const float* xB  = (const float*)d_in[1];
    const int*   eA  = (const int*)d_in[2];
    const int*   eB  = (const int*)d_in[3];
    const float* W1  = (const float*)d_in[4];
    const float* b1  = (const float*)d_in[5];
    const float* W2  = (const float*)d_in[6];
    const float* b2  = (const float*)d_in[7];
    const float* Wp1 = (const float*)d_in[8];
    const float* bp1 = (const float*)d_in[9];
    const float* Wp2 = (const float*)d_in[10];
    const float* bp2 = (const float*)d_in[11];
    const float* Wn1 = (const float*)d_in[12];
    const float* bn1 = (const float*)d_in[13];
    const float* Wn2 = (const float*)d_in[14];
    const float* bn2 = (const float*)d_in[15];

    float* out  = (float*)d_out;
    float* h    = out;                               // [2N,128] (hA | hB)
    float* z    = out + (size_t)NTOT * 128;          // [2N,64]
    float* nul  = z + (size_t)NTOT * 64;             // [2N]

    void* p;
    int* degcur;  cudaGetSymbolAddress(&p, g_degcur); degcur = (int*)p;
    float* agg;   cudaGetSymbolAddress(&p, g_agg);    agg    = (float*)p;
    uint2* xh;    cudaGetSymbolAddress(&p, g_xh);     xh     = (uint2*)p;
    uint2* hidh;  cudaGetSymbolAddress(&p, g_hidh);   hidh   = (uint2*)p;
    float* w;     cudaGetSymbolAddress(&p, g_w);      w      = (float*)p;

    cudaMemsetAsync(degcur, 0, NTOT * sizeof(int));
    roundw_kernel<<<(57344 + 255) / 256, 256>>>(W1, W2, Wp1, Wp2, Wn1);
    conv_kernel<<<(NTOT * 32 + 255) / 256, 256>>>(xA, xB);
    degree_kernel<<<(2 * NEDGES + 255) / 256, 256>>>(eA, eB);
    scan1_kernel<<<2 * NBLK, 1024>>>();
    scan2_kernel<<<1, 128>>>();
    scan3_kernel<<<2 * NBLK, 1024>>>();
    fill_kernel<<<(2 * NEDGES + 255) / 256, 256>>>(eA, eB);

    const int gemmGrid = (NTOT + 127) / 128;
    const int aggGrid  = (NTOT * 32 + 255) / 256;

    size_t sh128  = (2 * 128 * ASTRIDE + 2 * 32 * (128 + 8)) * sizeof(float);
    size_t sh64   = (2 * 128 * ASTRIDE + 2 * 32 * (64 + 8)) * sizeof(float);
    size_t shProj = (2 * 128 * ASTRIDE + 2 * 32 * PW_STRIDE + 128 * TS_STRIDE) * sizeof(float);
    cudaFuncSetAttribute(gemm_tc<128, 2, 4>, cudaFuncAttributeMaxDynamicSharedMemorySize, (int)sh128);
    cudaFuncSetAttribute(gemm_tc<128, 2, 0>, cudaFuncAttributeMaxDynamicSharedMemorySize, (int)sh128);
    cudaFuncSetAttribute(gemm_tc<64, 1, 3>,  cudaFuncAttributeMaxDynamicSharedMemorySize, (int)sh64);
    cudaFuncSetAttribute(proj_fused,         cudaFuncAttributeMaxDynamicSharedMemorySize, (int)shProj);

    // layer 1: agg(x_fp16) -> relu(. @ W1 + b1) -> fp16 hid
    aggh_kernel<<<aggGrid, 256>>>(xh, agg);
    gemm_tc<128, 2, 4><<<gemmGrid, 256, sh128>>>(agg, 128, nullptr, 0, w + OW1, b1, (float*)hidh, NTOT, nullptr, nullptr);
    // layer 2: agg(hid_fp16) -> . @ W2 + b2   (encoder output h)
    aggh_kernel<<<aggGrid, 256>>>(hidh, agg);
    gemm_tc<128, 2, 0><<<gemmGrid, 256, sh128>>>(agg, 128, nullptr, 0, w + OW2, b2, h, NTOT, nullptr, nullptr);
    // proj (fused): z = l2norm(relu(h@Wp1+bp1) @ Wp2 + bp2)
    proj_fused<<<gemmGrid, 256, shProj>>>(h, w + OWP1, bp1, w + OWP2, bp2, z);
    // null head: relu([h|z]@Wn1+bn1) . Wn2 + bn2 (fused dot)
    gemm_tc<64, 1, 3><<<gemmGrid, 256, sh64>>>(h, 128, z, 64, w + OWN1, bn1, nul, NTOT, Wn2, bn2);
}

// round 16
// speedup vs baseline: 1.7609x; 1.0208x over previous
#include <cuda_runtime.h>
#include <cuda_fp16.h>
#include <math.h>
#include <stdint.h>

#define NNODES 50000
#define NEDGES 800000
#define NTOT   (2 * NNODES)
#define NBLK   49                     // ceil(NNODES / 1024)

// ---------------- scratch (device globals; no allocations allowed) ----------
__device__ int   g_degcur[NTOT];
__device__ int   g_rowptr[2 * (NNODES + 1)];
__device__ int   g_csr_src[2 * NEDGES];        // unified src ids (graph B +NNODES)
__device__ float g_norm[NTOT];
__device__ float g_agg[NTOT * 128];
__device__ uint2 g_xh[NTOT * 32];              // fp16 features, unified [2N,128]
__device__ uint2 g_hidh[NTOT * 32];            // fp16 hidden layer
__device__ float g_w[57344];                   // tf32-rounded weights
__device__ int   g_bsum[2 * NBLK];
__device__ int   g_boff[2 * NBLK];

#define OW1  0
#define OW2  16384
#define OWP1 32768
#define OWP2 40960
#define OWN1 45056

__device__ __forceinline__ uint32_t f2tf32(float f) {
    uint32_t u;
    asm volatile("cvt.rna.tf32.f32 %0, %1;" : "=r"(u) : "f"(f));
    return u;
}
__device__ __forceinline__ float rnd32(float f) {
    return __uint_as_float(f2tf32(f));
}
__device__ __forceinline__ float4 h4tof4(uint2 u) {
    __half2 h0 = *reinterpret_cast<__half2*>(&u.x);
    __half2 h1 = *reinterpret_cast<__half2*>(&u.y);
    float2 f0 = __half22float2(h0);
    float2 f1 = __half22float2(h1);
    float4 r; r.x = f0.x; r.y = f0.y; r.z = f1.x; r.w = f1.y;
    return r;
}

// ---------------- graph preprocessing ---------------------------------------

__global__ void degree_kernel(const int* __restrict__ eA, const int* __restrict__ eB) {
    int i = blockIdx.x * blockDim.x + threadIdx.x;
    if (i >= 2 * NEDGES) return;
    int g = i / NEDGES, e = i - g * NEDGES;
    const int* ei = g ? eB : eA;
    int dst = ei[NEDGES + e];
    atomicAdd(&g_degcur[g * NNODES + dst], 1);
}

__global__ void conv_kernel(const float* __restrict__ xA, const float* __restrict__ xB) {
    int i = blockIdx.x * blockDim.x + threadIdx.x;
    if (i >= NTOT * 32) return;
    const float4* src = (i < NNODES * 32) ? ((const float4*)xA + i)
                                          : ((const float4*)xB + (i - NNODES * 32));
    float4 v = __ldg(src);
    __half2 a = __floats2half2_rn(v.x, v.y);
    __half2 b = __floats2half2_rn(v.z, v.w);
    uint2 u;
    u.x = *reinterpret_cast<uint32_t*>(&a);
    u.y = *reinterpret_cast<uint32_t*>(&b);
    g_xh[i] = u;
}

__global__ void roundw_kernel(const float* __restrict__ W1, const float* __restrict__ W2,
                              const float* __restrict__ Wp1, const float* __restrict__ Wp2,
                              const float* __restrict__ Wn1) {
    int i = blockIdx.x * blockDim.x + threadIdx.x;
    if (i >= 57344) return;
    float v;
    if (i < 16384)      v = W1[i];
    else if (i < 32768) v = W2[i - 16384];
    else if (i < 40960) v = Wp1[i - 32768];
    else if (i < 45056) v = Wp2[i - 40960];
    else                v = Wn1[i - 45056];
    g_w[i] = rnd32(v);
}

// ---- parallel 3-level scan of degrees -> rowptr + cursor + norm -------------

__global__ void scan1_kernel() {
    __shared__ int sm[1024];
    int g   = blockIdx.x / NBLK;
    int blk = blockIdx.x % NBLK;
    int t   = threadIdx.x;
    int idx = blk * 1024 + t;
    int d = 0;
    if (idx < NNODES) {
        d = g_degcur[g * NNODES + idx];
        g_norm[g * NNODES + idx] = rsqrtf((float)d + 1.0f);
    }
    sm[t] = d;
    __syncthreads();
    for (int s = 1; s < 1024; s <<= 1) {
        int v = sm[t];
        int a = (t >= s) ? sm[t - s] : 0;
        __syncthreads();
        sm[t] = v + a;
        __syncthreads();
    }
    if (idx < NNODES) g_rowptr[g * (NNODES + 1) + idx] = sm[t] - d;
    if (t == 1023) g_bsum[blockIdx.x] = sm[1023];
}

__global__ void scan2_kernel() {
    __shared__ int sm[128];
    int t = threadIdx.x;
    int v = (t < 2 * NBLK) ? g_bsum[t] : 0;
    sm[t] = v;
    __syncthreads();
    int segStart = (t < NBLK) ? 0 : NBLK;
    for (int s = 1; s < 128; s <<= 1) {
        int cur = sm[t];
        int a = (t >= s && (t - s) >= segStart) ? sm[t - s] : 0;
        __syncthreads();
        sm[t] = cur + a;
        __syncthreads();
    }
    if (t < 2 * NBLK) {
        g_boff[t] = sm[t] - v;
        if (t == NBLK - 1)     g_rowptr[NNODES] = sm[t];
        if (t == 2 * NBLK - 1) g_rowptr[(NNODES + 1) + NNODES] = sm[t];
    }
}

__global__ void scan3_kernel() {
    int g   = blockIdx.x / NBLK;
    int blk = blockIdx.x % NBLK;
    int idx = blk * 1024 + threadIdx.x;
    if (idx >= NNODES) return;
    int v = g_rowptr[g * (NNODES + 1) + idx] + g_boff[blockIdx.x];
    g_rowptr[g * (NNODES + 1) + idx] = v;
    g_degcur[g * NNODES + idx] = v;
}

__global__ void fill_kernel(const int* __restrict__ eA, const int* __restrict__ eB) {
    int i = blockIdx.x * blockDim.x + threadIdx.x;
    if (i >= 2 * NEDGES) return;
    int g = i / NEDGES, e = i - g * NEDGES;
    const int* ei = g ? eB : eA;
    int src = ei[e];
    int dst = ei[NEDGES + e];
    int pos = atomicAdd(&g_degcur[g * NNODES + dst], 1);
    g_csr_src[g * NEDGES + pos] = src + g * NNODES;
}

// ---------------- GCN aggregation: warp per node, fp16 gathers ---------------
__global__ void aggh_kernel(const uint2* __restrict__ xh, float* __restrict__ out) {
    int node = (blockIdx.x * blockDim.x + threadIdx.x) >> 5;
    int lane = threadIdx.x & 31;
    if (node >= NTOT) return;
    int g = (node >= NNODES);
    int local = node - (g ? NNODES : 0);

    float nd = g_norm[node];
    float4 a = h4tof4(__ldg(&xh[node * 32 + lane]));
    float4 acc;
    acc.x = a.x * nd; acc.y = a.y * nd; acc.z = a.z * nd; acc.w = a.w * nd;

    int b  = g_rowptr[g * (NNODES + 1) + local]     + g * NEDGES;
    int en = g_rowptr[g * (NNODES + 1) + local + 1] + g * NEDGES;
    int e = b;
    for (; e + 4 <= en; e += 4) {
        int s0 = __ldg(&g_csr_src[e + 0]);
        int s1 = __ldg(&g_csr_src[e + 1]);
        int s2 = __ldg(&g_csr_src[e + 2]);
        int s3 = __ldg(&g_csr_src[e + 3]);
        float w0 = __ldg(&g_norm[s0]);
        float w1 = __ldg(&g_norm[s1]);
        float w2 = __ldg(&g_norm[s2]);
        float w3 = __ldg(&g_norm[s3]);
        float4 v0 = h4tof4(__ldg(&xh[(size_t)s0 * 32 + lane]));
        float4 v1 = h4tof4(__ldg(&xh[(size_t)s1 * 32 + lane]));
        float4 v2 = h4tof4(__ldg(&xh[(size_t)s2 * 32 + lane]));
        float4 v3 = h4tof4(__ldg(&xh[(size_t)s3 * 32 + lane]));
        acc.x += v0.x * w0 + v1.x * w1 + v2.x * w2 + v3.x * w3;
        acc.y += v0.y * w0 + v1.y * w1 + v2.y * w2 + v3.y * w3;
        acc.z += v0.z * w0 + v1.z * w1 + v2.z * w2 + v3.z * w3;
        acc.w += v0.w * w0 + v1.w * w1 + v2.w * w2 + v3.w * w3;
    }
    for (; e < en; e++) {
        int s = __ldg(&g_csr_src[e]);
        float w = __ldg(&g_norm[s]);
        float4 v = h4tof4(__ldg(&xh[(size_t)s * 32 + lane]));
        acc.x += v.x * w; acc.y += v.y * w; acc.z += v.z * w; acc.w += v.w * w;
    }
    acc.x = rnd32(acc.x * nd); acc.y = rnd32(acc.y * nd);
    acc.z = rnd32(acc.z * nd); acc.w = rnd32(acc.w * nd);
    ((float4*)out)[node * 32 + lane] = acc;
}

// ---------------- TF32 tensor-core GEMM --------------------------------------
// EPI: 0 none (tf32-rounded store), 4 relu+fp16 store
#define ASTRIDE 36

__device__ __forceinline__ void cpasync16(uint32_t dst, const void* src, bool pred) {
    int sz = pred ? 16 : 0;
    asm volatile("cp.async.cg.shared.global [%0], [%1], 16, %2;"
                 :: "r"(dst), "l"(src), "r"(sz));
}
__device__ __forceinline__ void mma_tf32(float* c, const uint32_t* a, const uint32_t* b) {
    asm volatile(
        "mma.sync.aligned.m16n8k8.row.col.f32.tf32.tf32.f32 "
        "{%0,%1,%2,%3}, {%4,%5,%6,%7}, {%8,%9}, {%0,%1,%2,%3};"
        : "+f"(c[0]), "+f"(c[1]), "+f"(c[2]), "+f"(c[3])
        : "r"(a[0]), "r"(a[1]), "r"(a[2]), "r"(a[3]), "r"(b[0]), "r"(b[1]));
}

template <int BN, int MT, int EPI>
__global__ void gemm_tc(const float* __restrict__ X1, int K1,
                        const float* __restrict__ W,
                        const float* __restrict__ bias,
                        float* __restrict__ Y, int n) {
    constexpr int SB = BN + 8;
    extern __shared__ float sm[];
    float* Ab = sm;
    float* Bb = sm + 2 * 128 * ASTRIDE;

    const int t = threadIdx.x;
    const int wid = t >> 5;
    const int lane = t & 31;
    const int lr = lane >> 2;
    const int lc = lane & 3;
    const int K = K1;
    const int T = K / 32;
    const int row0 = blockIdx.x * 128;

    constexpr int WROWS = (BN == 128) ? 4 : 8;
    const int warpRow = (wid % WROWS) * (MT * 16);
    const int warpCol = (wid / WROWS) * 64;

    float acc[MT][8][4];
#pragma unroll
    for (int m = 0; m < MT; m++)
#pragma unroll
        for (int nt = 0; nt < 8; nt++)
#pragma unroll
            for (int j = 0; j < 4; j++) acc[m][nt][j] = 0.0f;

    uint32_t aBase = (uint32_t)__cvta_generic_to_shared(Ab);
    uint32_t bBase = (uint32_t)__cvta_generic_to_shared(Bb);

    auto loadA = [&](int buf, int k0) {
#pragma unroll
        for (int i = 0; i < 4; i++) {
            int idx4 = t + i * 256;
            int row = idx4 >> 3;
            int kq = idx4 & 7;
            int rg = row0 + row;
            uint32_t dst = aBase + (uint32_t)((buf * 128 * ASTRIDE + row * ASTRIDE + 4 * kq) * 4);
            cpasync16(dst, X1 + (size_t)rg * K1 + k0 + 4 * kq, rg < n);
        }
    };
    auto loadB = [&](int buf, int k0) {
        constexpr int ITER = (32 * BN) / (256 * 4);
#pragma unroll
        for (int i = 0; i < ITER; i++) {
            int idx4 = t + i * 256;
            int k = idx4 / (BN / 4);
            int cq = idx4 % (BN / 4);
            uint32_t dst = bBase + (uint32_t)((buf * 32 * SB + k * SB + 4 * cq) * 4);
            cpasync16(dst, W + (size_t)(k0 + k) * BN + 4 * cq, true);
        }
    };

    loadA(0, 0);
    loadB(0, 0);
    asm volatile("cp.async.commit_group;");

    for (int tt = 0; tt < T; tt++) {
        int buf = tt & 1;
        if (tt + 1 < T) {
            loadA(buf ^ 1, (tt + 1) * 32);
            loadB(buf ^ 1, (tt + 1) * 32);
            asm volatile("cp.async.commit_group;");
            asm volatile("cp.async.wait_group 1;");
        } else {
            asm volatile("cp.async.wait_group 0;");
        }
        __syncthreads();

        const float* As = Ab + buf * 128 * ASTRIDE;
        const float* Bs = Bb + buf * 32 * SB;
#pragma unroll
        for (int kk8 = 0; kk8 < 4; kk8++) {
            int kb = kk8 * 8;
            uint32_t af[MT][4];
#pragma unroll
            for (int m = 0; m < MT; m++) {
                int r1 = warpRow + m * 16 + lr;
                af[m][0] = __float_as_uint(As[r1 * ASTRIDE + kb + lc]);
                af[m][1] = __float_as_uint(As[(r1 + 8) * ASTRIDE + kb + lc]);
                af[m][2] = __float_as_uint(As[r1 * ASTRIDE + kb + lc + 4]);
                af[m][3] = __float_as_uint(As[(r1 + 8) * ASTRIDE + kb + lc + 4]);
            }
            uint32_t bf[8][2];
#pragma unroll
            for (int nt = 0; nt < 8; nt++) {
                int cc = warpCol + nt * 8 + lr;
                bf[nt][0] = __float_as_uint(Bs[(kb + lc) * SB + cc]);
                bf[nt][1] = __float_as_uint(Bs[(kb + lc + 4) * SB + cc]);
            }
#pragma unroll
            for (int m = 0; m < MT; m++)
#pragma unroll
                for (int nt = 0; nt < 8; nt++)
                    mma_tf32(acc[m][nt], af[m], bf[nt]);
        }
        __syncthreads();
    }

#pragma unroll
    for (int m = 0; m < MT; m++) {
        int r1 = row0 + warpRow + m * 16 + lr;
        int r2 = r1 + 8;
        float v[8][4];
#pragma unroll
        for (int nt = 0; nt < 8; nt++) {
            int col = warpCol + nt * 8 + 2 * lc;
            float b0 = __ldg(&bias[col]);
            float b1 = __ldg(&bias[col + 1]);
            v[nt][0] = acc[m][nt][0] + b0;
            v[nt][1] = acc[m][nt][1] + b1;
            v[nt][2] = acc[m][nt][2] + b0;
            v[nt][3] = acc[m][nt][3] + b1;
            if (EPI == 4) {
#pragma unroll
                for (int j = 0; j < 4; j++) v[nt][j] = fmaxf(v[nt][j], 0.0f);
            }
        }
        if (EPI == 0) {
#pragma unroll
            for (int nt = 0; nt < 8; nt++) {
                int col = warpCol + nt * 8 + 2 * lc;
                if (r1 < n) { float2 s = {rnd32(v[nt][0]), rnd32(v[nt][1])}; *(float2*)&Y[(size_t)r1 * BN + col] = s; }
                if (r2 < n) { float2 s = {rnd32(v[nt][2]), rnd32(v[nt][3])}; *(float2*)&Y[(size_t)r2 * BN + col] = s; }
            }
        } else { // EPI == 4
            __half* Yh = (__half*)Y;
#pragma unroll
            for (int nt = 0; nt < 8; nt++) {
                int col = warpCol + nt * 8 + 2 * lc;
                if (r1 < n) *(__half2*)&Yh[(size_t)r1 * BN + col] = __floats2half2_rn(v[nt][0], v[nt][1]);
                if (r2 < n) *(__half2*)&Yh[(size_t)r2 * BN + col] = __floats2half2_rn(v[nt][2], v[nt][3]);
            }
        }
    }
}

// ============================================================================
// Fused projection + null head:
//   z   = l2norm( relu(h@Wp1+bp1) @ Wp2 + bp2 )
//   nul = relu( h@Wn1[0:128] + z@Wn1[128:192] + bn1 ) . Wn2 + bn2
// Stage-1/z values tf32-rounded at each handoff -> bit-identical to split path.
// smem: Ab 2*128*36, Wb 2*32*72 (Wp), Wn 2*32*72 (Wn1), Ts 128*68  (108,544 B)
// ============================================================================
#define PW_STRIDE 72
#define TS_STRIDE 68

__global__ void proj_null_fused(const float* __restrict__ h,
                                const float* __restrict__ Wp1, const float* __restrict__ bp1,
                                const float* __restrict__ Wp2, const float* __restrict__ bp2,
                                const float* __restrict__ Wn1, const float* __restrict__ bn1,
                                const float* __restrict__ Wn2, const float* __restrict__ bn2,
                                float* __restrict__ z, float* __restrict__ nul) {
    extern __shared__ float sm[];
    float* Ab = sm;                                   // 2*128*36
    float* Wb = sm + 2 * 128 * ASTRIDE;               // 2*32*72
    float* Wn = Wb + 2 * 32 * PW_STRIDE;              // 2*32*72
    float* Ts = Wn + 2 * 32 * PW_STRIDE;              // 128*68

    const int t = threadIdx.x;
    const int wid = t >> 5;
    const int lane = t & 31;
    const int lr = lane >> 2;
    const int lc = lane & 3;
    const int row0 = blockIdx.x * 128;
    const int warpRow = wid * 16;

    uint32_t aBase  = (uint32_t)__cvta_generic_to_shared(Ab);
    uint32_t bBase  = (uint32_t)__cvta_generic_to_shared(Wb);
    uint32_t nBase  = (uint32_t)__cvta_generic_to_shared(Wn);

    auto loadA = [&](int buf, int k0) {
#pragma unroll
        for (int i = 0; i < 4; i++) {
            int idx4 = t + i * 256;
            int row = idx4 >> 3;
            int kq = idx4 & 7;
            int rg = row0 + row;
            uint32_t dst = aBase + (uint32_t)((buf * 128 * ASTRIDE + row * ASTRIDE + 4 * kq) * 4);
            cpasync16(dst, h + (size_t)rg * 128 + k0 + 4 * kq, rg < NTOT);
        }
    };
    auto loadW = [&](const float* W, uint32_t base, int buf, int k0) {
#pragma unroll
        for (int i = 0; i < 2; i++) {
            int idx4 = t + i * 256;
            int k = idx4 >> 4;
            int cq = idx4 & 15;
            uint32_t dst = base + (uint32_t)((buf * 32 * PW_STRIDE + k * PW_STRIDE + 4 * cq) * 4);
            cpasync16(dst, W + (size_t)(k0 + k) * 64 + 4 * cq, true);
        }
    };

    float p_acc[8][4];   // proj stage-1 / stage-2 accumulator (reused)
    float n_acc[8][4];   // null-head accumulator (lives across all stages)
#pragma unroll
    for (int nt = 0; nt < 8; nt++)
#pragma unroll
        for (int j = 0; j < 4; j++) { p_acc[nt][j] = 0.0f; n_acc[nt][j] = 0.0f; }

    // ---------------- stage 1: h tiles -> p_acc (Wp1), n_acc (Wn1 rows 0..127) ----
    loadA(0, 0);
    loadW(Wp1, bBase, 0, 0);
    loadW(Wn1, nBase, 0, 0);
    asm volatile("cp.async.commit_group;");

    for (int tt = 0; tt < 4; tt++) {
        int buf = tt & 1;
        if (tt < 3) {
            loadA(buf ^ 1, (tt + 1) * 32);
            loadW(Wp1, bBase, buf ^ 1, (tt + 1) * 32);
            loadW(Wn1, nBase, buf ^ 1, (tt + 1) * 32);
            asm volatile("cp.async.commit_group;");
            asm volatile("cp.async.wait_group 1;");
        } else {
            asm volatile("cp.async.wait_group 0;");
        }
        __syncthreads();
        const float* As = Ab + buf * 128 * ASTRIDE;
        const float* Bs = Wb + buf * 32 * PW_STRIDE;
        const float* Ns = Wn + buf * 32 * PW_STRIDE;
#pragma unroll
        for (int kk8 = 0; kk8 < 4; kk8++) {
            int kb = kk8 * 8;
            uint32_t af[4];
            int r1 = warpRow + lr;
            af[0] = __float_as_uint(As[r1 * ASTRIDE + kb + lc]);
            af[1] = __float_as_uint(As[(r1 + 8) * ASTRIDE + kb + lc]);
            af[2] = __float_as_uint(As[r1 * ASTRIDE + kb + lc + 4]);
            af[3] = __float_as_uint(As[(r1 + 8) * ASTRIDE + kb + lc + 4]);
            uint32_t bf[8][2], nf[8][2];
#pragma unroll
            for (int nt = 0; nt < 8; nt++) {
                int cc = nt * 8 + lr;
                bf[nt][0] = __float_as_uint(Bs[(kb + lc) * PW_STRIDE + cc]);
                bf[nt][1] = __float_as_uint(Bs[(kb + lc + 4) * PW_STRIDE + cc]);
                nf[nt][0] = __float_as_uint(Ns[(kb + lc) * PW_STRIDE + cc]);
                nf[nt][1] = __float_as_uint(Ns[(kb + lc + 4) * PW_STRIDE + cc]);
            }
#pragma unroll
            for (int nt = 0; nt < 8; nt++) {
                mma_tf32(p_acc[nt], af, bf[nt]);
                mma_tf32(n_acc[nt], af, nf[nt]);
            }
        }
        __syncthreads();
    }

    // Ts = rnd32(relu(p_acc + bp1))
    {
        int r1l = warpRow + lr;
        int r2l = r1l + 8;
#pragma unroll
        for (int nt = 0; nt < 8; nt++) {
            int col = nt * 8 + 2 * lc;
            float b0 = __ldg(&bp1[col]);
            float b1 = __ldg(&bp1[col + 1]);
            Ts[r1l * TS_STRIDE + col]     = rnd32(fmaxf(p_acc[nt][0] + b0, 0.f));
            Ts[r1l * TS_STRIDE + col + 1] = rnd32(fmaxf(p_acc[nt][1] + b1, 0.f));
            Ts[r2l * TS_STRIDE + col]     = rnd32(fmaxf(p_acc[nt][2] + b0, 0.f));
            Ts[r2l * TS_STRIDE + col + 1] = rnd32(fmaxf(p_acc[nt][3] + b1, 0.f));
        }
    }
    __syncthreads();

    // ---------------- stage 2: z = l2norm(Ts @ Wp2 + bp2) ----------------
#pragma unroll
    for (int nt = 0; nt < 8; nt++)
#pragma unroll
        for (int j = 0; j < 4; j++) p_acc[nt][j] = 0.0f;

    loadW(Wp2, bBase, 0, 0);
    asm volatile("cp.async.commit_group;");

    for (int tt = 0; tt < 2; tt++) {
        int buf = tt & 1;
        if (tt < 1) {
            loadW(Wp2, bBase, buf ^ 1, 32);
            asm volatile("cp.async.commit_group;");
            asm volatile("cp.async.wait_group 1;");
        } else {
            asm volatile("cp.async.wait_group 0;");
        }
        __syncthreads();
        const float* Bs = Wb + buf * 32 * PW_STRIDE;
#pragma unroll
        for (int kk8 = 0; kk8 < 4; kk8++) {
            int kb = kk8 * 8;
            int col = tt * 32 + kb + lc;
            uint32_t af[4];
            int r1 = warpRow + lr;
            af[0] = __float_as_uint(Ts[r1 * TS_STRIDE + col]);
            af[1] = __float_as_uint(Ts[(r1 + 8) * TS_STRIDE + col]);
            af[2] = __float_as_uint(Ts[r1 * TS_STRIDE + col + 4]);
            af[3] = __float_as_uint(Ts[(r1 + 8) * TS_STRIDE + col + 4]);
            uint32_t bf[8][2];
#pragma unroll
            for (int nt = 0; nt < 8; nt++) {
                int cc = nt * 8 + lr;
                bf[nt][0] = __float_as_uint(Bs[(kb + lc) * PW_STRIDE + cc]);
                bf[nt][1] = __float_as_uint(Bs[(kb + lc + 4) * PW_STRIDE + cc]);
            }
#pragma unroll
            for (int nt = 0; nt < 8; nt++)
                mma_tf32(p_acc[nt], af, bf[nt]);
        }
        __syncthreads();
    }

    // z epilogue: l2norm; write gmem z AND Ts(z) for stage 3
    {
        int r1g = row0 + warpRow + lr;
        int r2g = r1g + 8;
        int r1l = warpRow + lr;
        int r2l = r1l + 8;
        float v[8][4];
#pragma unroll
        for (int nt = 0; nt < 8; nt++) {
            int col = nt * 8 + 2 * lc;
            float b0 = __ldg(&bp2[col]);
            float b1 = __ldg(&bp2[col + 1]);
            v[nt][0] = p_acc[nt][0] + b0;
            v[nt][1] = p_acc[nt][1] + b1;
            v[nt][2] = p_acc[nt][2] + b0;
            v[nt][3] = p_acc[nt][3] + b1;
        }
        float s1 = 0.f, s2 = 0.f;
#pragma unroll
        for (int nt = 0; nt < 8; nt++) {
            s1 += v[nt][0] * v[nt][0] + v[nt][1] * v[nt][1];
            s2 += v[nt][2] * v[nt][2] + v[nt][3] * v[nt][3];
        }
        s1 += __shfl_xor_sync(0xffffffffu, s1, 1);
        s1 += __shfl_xor_sync(0xffffffffu, s1, 2);
        s2 += __shfl_xor_sync(0xffffffffu, s2, 1);
        s2 += __shfl_xor_sync(0xffffffffu, s2, 2);
        float i1 = 1.0f / fmaxf(sqrtf(s1), 1e-12f);
        float i2 = 1.0f / fmaxf(sqrtf(s2), 1e-12f);
#pragma unroll
        for (int nt = 0; nt < 8; nt++) {
            int col = nt * 8 + 2 * lc;
            float z0 = rnd32(v[nt][0] * i1), z1 = rnd32(v[nt][1] * i1);
            float z2 = rnd32(v[nt][2] * i2), z3 = rnd32(v[nt][3] * i2);
            if (r1g < NTOT) { float2 s = {z0, z1}; *(float2*)&z[(size_t)r1g * 64 + col] = s; }
            if (r2g < NTOT) { float2 s = {z2, z3}; *(float2*)&z[(size_t)r2g * 64 + col] = s; }
            Ts[r1l * TS_STRIDE + col]     = z0;
            Ts[r1l * TS_STRIDE + col + 1] = z1;
            Ts[r2l * TS_STRIDE + col]     = z2;
            Ts[r2l * TS_STRIDE + col + 1] = z3;
        }
    }
    __syncthreads();

    // ---------------- stage 3: n_acc += Ts(z) @ Wn1[128:192] ----------------
    loadW(Wn1 + (size_t)128 * 64, nBase, 0, 0);
    asm volatile("cp.async.commit_group;");

    for (int tt = 0; tt < 2; tt++) {
        int buf = tt & 1;
        if (tt < 1) {
            loadW(Wn1 + (size_t)128 * 64, nBase, buf ^ 1, 32);
            asm volatile("cp.async.commit_group;");
            asm volatile("cp.async.wait_group 1;");
        } else {
            asm volatile("cp.async.wait_group 0;");
        }
        __syncthreads();
        const float* Ns = Wn + buf * 32 * PW_STRIDE;
#pragma unroll
        for (int kk8 = 0; kk8 < 4; kk8++) {
            int kb = kk8 * 8;
            int col = tt * 32 + kb + lc;
            uint32_t af[4];
            int r1 = warpRow + lr;
            af[0] = __float_as_uint(Ts[r1 * TS_STRIDE + col]);
            af[1] = __float_as_uint(Ts[(r1 + 8) * TS_STRIDE + col]);
            af[2] = __float_as_uint(Ts[r1 * TS_STRIDE + col + 4]);
            af[3] = __float_as_uint(Ts[(r1 + 8) * TS_STRIDE + col + 4]);
            uint32_t nf[8][2];
#pragma unroll
            for (int nt = 0; nt < 8; nt++) {
                int cc = nt * 8 + lr;
                nf[nt][0] = __float_as_uint(Ns[(kb + lc) * PW_STRIDE + cc]);
                nf[nt][1] = __float_as_uint(Ns[(kb + lc + 4) * PW_STRIDE + cc]);
            }
#pragma unroll
            for (int nt = 0; nt < 8; nt++)
                mma_tf32(n_acc[nt], af, nf[nt]);
        }
        __syncthreads();
    }

    // null epilogue: relu(n_acc + bn1) . Wn2 + bn2
    {
        int r1 = row0 + warpRow + lr;
        int r2 = r1 + 8;
        float d1 = 0.0f, d2 = 0.0f;
#pragma unroll
        for (int nt = 0; nt < 8; nt++) {
            int col = nt * 8 + 2 * lc;
            float b0 = __ldg(&bn1[col]);
            float b1 = __ldg(&bn1[col + 1]);
            float w0 = __ldg(&Wn2[col]);
            float w1 = __ldg(&Wn2[col + 1]);
            d1 += fmaxf(n_acc[nt][0] + b0, 0.f) * w0 + fmaxf(n_acc[nt][1] + b1, 0.f) * w1;
            d2 += fmaxf(n_acc[nt][2] + b0, 0.f) * w0 + fmaxf(n_acc[nt][3] + b1, 0.f) * w1;
        }
        d1 += __shfl_xor_sync(0xffffffffu, d1, 1);
        d1 += __shfl_xor_sync(0xffffffffu, d1, 2);
        d2 += __shfl_xor_sync(0xffffffffu, d2, 1);
        d2 += __shfl_xor_sync(0xffffffffu, d2, 2);
        if (lc == 0) {
            float bb = __ldg(&bn2[0]);
            if (r1 < NTOT) nul[r1] = d1 + bb;
            if (r2 < NTOT) nul[r2] = d2 + bb;
        }
    }
}

// ---------------- launch ------------------------------------------------------

extern "C" void kernel_launch(void* const* d_in, const int* in_sizes, int n_in,
                              void* d_out, int out_size) {
    const float* xA  = (const float*)d_in[0];
    const float* xB  = (const float*)d_in[1];
    const int*   eA  = (const int*)d_in[2];
    const int*   eB  = (const int*)d_in[3];
    const float* W1  = (const float*)d_in[4];
    const float* b1  = (const float*)d_in[5];
    const float* W2  = (const float*)d_in[6];
    const float* b2  = (const float*)d_in[7];
    const float* Wp1 = (const float*)d_in[8];
    const float* bp1 = (const float*)d_in[9];
    const float* Wp2 = (const float*)d_in[10];
    const float* bp2 = (const float*)d_in[11];
    const float* Wn1 = (const float*)d_in[12];
    const float* bn1 = (const float*)d_in[13];
    const float* Wn2 = (const float*)d_in[14];
    const float* bn2 = (const float*)d_in[15];

    float* out  = (float*)d_out;
    float* h    = out;                               // [2N,128] (hA | hB)
    float* z    = out + (size_t)NTOT * 128;          // [2N,64]
    float* nul  = z + (size_t)NTOT * 64;             // [2N]

    void* p;
    int* degcur;  cudaGetSymbolAddress(&p, g_degcur); degcur = (int*)p;
    float* agg;   cudaGetSymbolAddress(&p, g_agg);    agg    = (float*)p;
    uint2* xh;    cudaGetSymbolAddress(&p, g_xh);     xh     = (uint2*)p;
    uint2* hidh;  cudaGetSymbolAddress(&p, g_hidh);   hidh   = (uint2*)p;
    float* w;     cudaGetSymbolAddress(&p, g_w);      w      = (float*)p;

    cudaMemsetAsync(degcur, 0, NTOT * sizeof(int));
    roundw_kernel<<<(57344 + 255) / 256, 256>>>(W1, W2, Wp1, Wp2, Wn1);
    conv_kernel<<<(NTOT * 32 + 255) / 256, 256>>>(xA, xB);
    degree_kernel<<<(2 * NEDGES + 255) / 256, 256>>>(eA, eB);
    scan1_kernel<<<2 * NBLK, 1024>>>();
    scan2_kernel<<<1, 128>>>();
    scan3_kernel<<<2 * NBLK, 1024>>>();
    fill_kernel<<<(2 * NEDGES + 255) / 256, 256>>>(eA, eB);

    const int gemmGrid = (NTOT + 127) / 128;
    const int aggGrid  = (NTOT * 32 + 255) / 256;

    size_t sh128  = (2 * 128 * ASTRIDE + 2 * 32 * (128 + 8)) * sizeof(float);
    size_t shPN   = (2 * 128 * ASTRIDE + 4 * 32 * PW_STRIDE + 128 * TS_STRIDE) * sizeof(float);
    cudaFuncSetAttribute(gemm_tc<128, 2, 4>, cudaFuncAttributeMaxDynamicSharedMemorySize, (int)sh128);
    cudaFuncSetAttribute(gemm_tc<128, 2, 0>, cudaFuncAttributeMaxDynamicSharedMemorySize, (int)sh128);
    cudaFuncSetAttribute(proj_null_fused,    cudaFuncAttributeMaxDynamicSharedMemorySize, (int)shPN);

    // layer 1: agg(x_fp16) -> relu(. @ W1 + b1) -> fp16 hid
    aggh_kernel<<<aggGrid, 256>>>(xh, agg);
    gemm_tc<128, 2, 4><<<gemmGrid, 256, sh128>>>(agg, 128, w + OW1, b1, (float*)hidh, NTOT);
    // layer 2: agg(hid_fp16) -> . @ W2 + b2   (encoder output h)
    aggh_kernel<<<aggGrid, 256>>>(hidh, agg);
    gemm_tc<128, 2, 0><<<gemmGrid, 256, sh128>>>(agg, 128, w + OW2, b2, h, NTOT);
    // proj + null head, fully fused
    proj_null_fused<<<gemmGrid, 256, shPN>>>(h, w + OWP1, bp1, w + OWP2, bp2,
                                             w + OWN1, bn1, Wn2, bn2, z, nul);
}

// round 17
// speedup vs baseline: 1.8604x; 1.0565x over previous
#include <cuda_runtime.h>
#include <cuda_fp16.h>
#include <math.h>
#include <stdint.h>

#define NNODES 50000
#define NEDGES 800000
#define NTOT   (2 * NNODES)
#define NBLK   49                     // ceil(NNODES / 1024)

// ---------------- scratch (device globals; no allocations allowed) ----------
__device__ int   g_degcur[NTOT];
__device__ int   g_rowptr[2 * (NNODES + 1)];
__device__ int   g_csr_src[2 * NEDGES];        // unified src ids (graph B +NNODES)
__device__ float g_norm[NTOT];
__device__ float g_agg[NTOT * 128];
__device__ uint2 g_xh[NTOT * 32];              // fp16 features*norm, unified [2N,128]
__device__ uint2 g_hidh[NTOT * 32];            // fp16 hidden*norm
__device__ float g_w[57344];                   // tf32-rounded weights
__device__ int   g_bsum[2 * NBLK];
__device__ int   g_boff[2 * NBLK];

#define OW1  0
#define OW2  16384
#define OWP1 32768
#define OWP2 40960
#define OWN1 45056

__device__ __forceinline__ uint32_t f2tf32(float f) {
    uint32_t u;
    asm volatile("cvt.rna.tf32.f32 %0, %1;" : "=r"(u) : "f"(f));
    return u;
}
__device__ __forceinline__ float rnd32(float f) {
    return __uint_as_float(f2tf32(f));
}
__device__ __forceinline__ float4 h4tof4(uint2 u) {
    __half2 h0 = *reinterpret_cast<__half2*>(&u.x);
    __half2 h1 = *reinterpret_cast<__half2*>(&u.y);
    float2 f0 = __half22float2(h0);
    float2 f1 = __half22float2(h1);
    float4 r; r.x = f0.x; r.y = f0.y; r.z = f1.x; r.w = f1.y;
    return r;
}

// ---------------- graph preprocessing ---------------------------------------

// 4 edges per thread (int4 loads of dst halves)
__global__ void degree_kernel(const int* __restrict__ eA, const int* __restrict__ eB) {
    int i = blockIdx.x * blockDim.x + threadIdx.x;        // quad index
    if (i >= (2 * NEDGES) / 4) return;
    int g = (i >= NEDGES / 4);
    int q = i - g * (NEDGES / 4);
    const int* ei = g ? eB : eA;
    int4 d4 = __ldg((const int4*)(ei + NEDGES) + q);
    int base = g * NNODES;
    atomicAdd(&g_degcur[base + d4.x], 1);
    atomicAdd(&g_degcur[base + d4.y], 1);
    atomicAdd(&g_degcur[base + d4.z], 1);
    atomicAdd(&g_degcur[base + d4.w], 1);
}

// convert x (both graphs) to unified fp16 [2N,128], PRE-SCALED by norm
__global__ void conv_kernel(const float* __restrict__ xA, const float* __restrict__ xB) {
    int i = blockIdx.x * blockDim.x + threadIdx.x;   // per 4 floats
    if (i >= NTOT * 32) return;
    int node = i >> 5;
    float nn = g_norm[node];
    const float4* src = (i < NNODES * 32) ? ((const float4*)xA + i)
                                          : ((const float4*)xB + (i - NNODES * 32));
    float4 v = __ldg(src);
    __half2 a = __floats2half2_rn(v.x * nn, v.y * nn);
    __half2 b = __floats2half2_rn(v.z * nn, v.w * nn);
    uint2 u;
    u.x = *reinterpret_cast<uint32_t*>(&a);
    u.y = *reinterpret_cast<uint32_t*>(&b);
    g_xh[i] = u;
}

__global__ void roundw_kernel(const float* __restrict__ W1, const float* __restrict__ W2,
                              const float* __restrict__ Wp1, const float* __restrict__ Wp2,
                              const float* __restrict__ Wn1) {
    int i = blockIdx.x * blockDim.x + threadIdx.x;
    if (i >= 57344) return;
    float v;
    if (i < 16384)      v = W1[i];
    else if (i < 32768) v = W2[i - 16384];
    else if (i < 40960) v = Wp1[i - 32768];
    else if (i < 45056) v = Wp2[i - 40960];
    else                v = Wn1[i - 45056];
    g_w[i] = rnd32(v);
}

// ---- parallel 3-level scan of degrees -> rowptr + cursor + norm -------------

__global__ void scan1_kernel() {
    __shared__ int sm[1024];
    int g   = blockIdx.x / NBLK;
    int blk = blockIdx.x % NBLK;
    int t   = threadIdx.x;
    int idx = blk * 1024 + t;
    int d = 0;
    if (idx < NNODES) {
        d = g_degcur[g * NNODES + idx];
        g_norm[g * NNODES + idx] = rsqrtf((float)d + 1.0f);
    }
    sm[t] = d;
    __syncthreads();
    for (int s = 1; s < 1024; s <<= 1) {
        int v = sm[t];
        int a = (t >= s) ? sm[t - s] : 0;
        __syncthreads();
        sm[t] = v + a;
        __syncthreads();
    }
    if (idx < NNODES) g_rowptr[g * (NNODES + 1) + idx] = sm[t] - d;
    if (t == 1023) g_bsum[blockIdx.x] = sm[1023];
}

__global__ void scan2_kernel() {
    __shared__ int sm[128];
    int t = threadIdx.x;
    int v = (t < 2 * NBLK) ? g_bsum[t] : 0;
    sm[t] = v;
    __syncthreads();
    int segStart = (t < NBLK) ? 0 : NBLK;
    for (int s = 1; s < 128; s <<= 1) {
        int cur = sm[t];
        int a = (t >= s && (t - s) >= segStart) ? sm[t - s] : 0;
        __syncthreads();
        sm[t] = cur + a;
        __syncthreads();
    }
    if (t < 2 * NBLK) {
        g_boff[t] = sm[t] - v;
        if (t == NBLK - 1)     g_rowptr[NNODES] = sm[t];
        if (t == 2 * NBLK - 1) g_rowptr[(NNODES + 1) + NNODES] = sm[t];
    }
}

__global__ void scan3_kernel() {
    int g   = blockIdx.x / NBLK;
    int blk = blockIdx.x % NBLK;
    int idx = blk * 1024 + threadIdx.x;
    if (idx >= NNODES) return;
    int v = g_rowptr[g * (NNODES + 1) + idx] + g_boff[blockIdx.x];
    g_rowptr[g * (NNODES + 1) + idx] = v;
    g_degcur[g * NNODES + idx] = v;
}

// 4 edges per thread (int4 loads of src and dst halves)
__global__ void fill_kernel(const int* __restrict__ eA, const int* __restrict__ eB) {
    int i = blockIdx.x * blockDim.x + threadIdx.x;
    if (i >= (2 * NEDGES) / 4) return;
    int g = (i >= NEDGES / 4);
    int q = i - g * (NEDGES / 4);
    const int* ei = g ? eB : eA;
    int4 s4 = __ldg((const int4*)ei + q);
    int4 d4 = __ldg((const int4*)(ei + NEDGES) + q);
    int nbase = g * NNODES;
    int ebase = g * NEDGES;
    int p0 = atomicAdd(&g_degcur[nbase + d4.x], 1);
    g_csr_src[ebase + p0] = s4.x + nbase;
    int p1 = atomicAdd(&g_degcur[nbase + d4.y], 1);
    g_csr_src[ebase + p1] = s4.y + nbase;
    int p2 = atomicAdd(&g_degcur[nbase + d4.z], 1);
    g_csr_src[ebase + p2] = s4.z + nbase;
    int p3 = atomicAdd(&g_degcur[nbase + d4.w], 1);
    g_csr_src[ebase + p3] = s4.w + nbase;
}

// ---------------- GCN aggregation: warp per node, norm-prescaled fp16 --------
// xh rows already include norm[s]; out[d] = tf32rnd( norm[d] * Σ (incl self) )
__global__ void aggh_kernel(const uint2* __restrict__ xh, float* __restrict__ out) {
    int node = (blockIdx.x * blockDim.x + threadIdx.x) >> 5;
    int lane = threadIdx.x & 31;
    if (node >= NTOT) return;
    int g = (node >= NNODES);
    int local = node - (g ? NNODES : 0);

    float nd = g_norm[node];
    float4 acc = h4tof4(__ldg(&xh[node * 32 + lane]));   // self term (pre-scaled)

    int b  = g_rowptr[g * (NNODES + 1) + local]     + g * NEDGES;
    int en = g_rowptr[g * (NNODES + 1) + local + 1] + g * NEDGES;
    int e = b;
    for (; e + 4 <= en; e += 4) {
        int s0 = __ldg(&g_csr_src[e + 0]);
        int s1 = __ldg(&g_csr_src[e + 1]);
        int s2 = __ldg(&g_csr_src[e + 2]);
        int s3 = __ldg(&g_csr_src[e + 3]);
        float4 v0 = h4tof4(__ldg(&xh[(size_t)s0 * 32 + lane]));
        float4 v1 = h4tof4(__ldg(&xh[(size_t)s1 * 32 + lane]));
        float4 v2 = h4tof4(__ldg(&xh[(size_t)s2 * 32 + lane]));
        float4 v3 = h4tof4(__ldg(&xh[(size_t)s3 * 32 + lane]));
        acc.x += v0.x + v1.x + v2.x + v3.x;
        acc.y += v0.y + v1.y + v2.y + v3.y;
        acc.z += v0.z + v1.z + v2.z + v3.z;
        acc.w += v0.w + v1.w + v2.w + v3.w;
    }
    for (; e < en; e++) {
        int s = __ldg(&g_csr_src[e]);
        float4 v = h4tof4(__ldg(&xh[(size_t)s * 32 + lane]));
        acc.x += v.x; acc.y += v.y; acc.z += v.z; acc.w += v.w;
    }
    acc.x = rnd32(acc.x * nd); acc.y = rnd32(acc.y * nd);
    acc.z = rnd32(acc.z * nd); acc.w = rnd32(acc.w * nd);
    ((float4*)out)[node * 32 + lane] = acc;
}

// ---------------- TF32 tensor-core GEMM --------------------------------------
// EPI: 0 none (tf32-rounded store), 4 relu -> fp16 store PRE-SCALED by norm
#define ASTRIDE 36

__device__ __forceinline__ void cpasync16(uint32_t dst, const void* src, bool pred) {
    int sz = pred ? 16 : 0;
    asm volatile("cp.async.cg.shared.global [%0], [%1], 16, %2;"
                 :: "r"(dst), "l"(src), "r"(sz));
}
__device__ __forceinline__ void mma_tf32(float* c, const uint32_t* a, const uint32_t* b) {
    asm volatile(
        "mma.sync.aligned.m16n8k8.row.col.f32.tf32.tf32.f32 "
        "{%0,%1,%2,%3}, {%4,%5,%6,%7}, {%8,%9}, {%0,%1,%2,%3};"
        : "+f"(c[0]), "+f"(c[1]), "+f"(c[2]), "+f"(c[3])
        : "r"(a[0]), "r"(a[1]), "r"(a[2]), "r"(a[3]), "r"(b[0]), "r"(b[1]));
}

template <int BN, int MT, int EPI>
__global__ void gemm_tc(const float* __restrict__ X1, int K1,
                        const float* __restrict__ W,
                        const float* __restrict__ bias,
                        float* __restrict__ Y, int n) {
    constexpr int SB = BN + 8;
    extern __shared__ float sm[];
    float* Ab = sm;
    float* Bb = sm + 2 * 128 * ASTRIDE;

    const int t = threadIdx.x;
    const int wid = t >> 5;
    const int lane = t & 31;
    const int lr = lane >> 2;
    const int lc = lane & 3;
    const int K = K1;
    const int T = K / 32;
    const int row0 = blockIdx.x * 128;

    constexpr int WROWS = (BN == 128) ? 4 : 8;
    const int warpRow = (wid % WROWS) * (MT * 16);
    const int warpCol = (wid / WROWS) * 64;

    float acc[MT][8][4];
#pragma unroll
    for (int m = 0; m < MT; m++)
#pragma unroll
        for (int nt = 0; nt < 8; nt++)
#pragma unroll
            for (int j = 0; j < 4; j++) acc[m][nt][j] = 0.0f;

    uint32_t aBase = (uint32_t)__cvta_generic_to_shared(Ab);
    uint32_t bBase = (uint32_t)__cvta_generic_to_shared(Bb);

    auto loadA = [&](int buf, int k0) {
#pragma unroll
        for (int i = 0; i < 4; i++) {
            int idx4 = t + i * 256;
            int row = idx4 >> 3;
            int kq = idx4 & 7;
            int rg = row0 + row;
            uint32_t dst = aBase + (uint32_t)((buf * 128 * ASTRIDE + row * ASTRIDE + 4 * kq) * 4);
            cpasync16(dst, X1 + (size_t)rg * K1 + k0 + 4 * kq, rg < n);
        }
    };
    auto loadB = [&](int buf, int k0) {
        constexpr int ITER = (32 * BN) / (256 * 4);
#pragma unroll
        for (int i = 0; i < ITER; i++) {
            int idx4 = t + i * 256;
            int k = idx4 / (BN / 4);
            int cq = idx4 % (BN / 4);
            uint32_t dst = bBase + (uint32_t)((buf * 32 * SB + k * SB + 4 * cq) * 4);
            cpasync16(dst, W + (size_t)(k0 + k) * BN + 4 * cq, true);
        }
    };

    loadA(0, 0);
    loadB(0, 0);
    asm volatile("cp.async.commit_group;");

    for (int tt = 0; tt < T; tt++) {
        int buf = tt & 1;
        if (tt + 1 < T) {
            loadA(buf ^ 1, (tt + 1) * 32);
            loadB(buf ^ 1, (tt + 1) * 32);
            asm volatile("cp.async.commit_group;");
            asm volatile("cp.async.wait_group 1;");
        } else {
            asm volatile("cp.async.wait_group 0;");
        }
        __syncthreads();

        const float* As = Ab + buf * 128 * ASTRIDE;
        const float* Bs = Bb + buf * 32 * SB;
#pragma unroll
        for (int kk8 = 0; kk8 < 4; kk8++) {
            int kb = kk8 * 8;
            uint32_t af[MT][4];
#pragma unroll
            for (int m = 0; m < MT; m++) {
                int r1 = warpRow + m * 16 + lr;
                af[m][0] = __float_as_uint(As[r1 * ASTRIDE + kb + lc]);
                af[m][1] = __float_as_uint(As[(r1 + 8) * ASTRIDE + kb + lc]);
                af[m][2] = __float_as_uint(As[r1 * ASTRIDE + kb + lc + 4]);
                af[m][3] = __float_as_uint(As[(r1 + 8) * ASTRIDE + kb + lc + 4]);
            }
            uint32_t bf[8][2];
#pragma unroll
            for (int nt = 0; nt < 8; nt++) {
                int cc = warpCol + nt * 8 + lr;
                bf[nt][0] = __float_as_uint(Bs[(kb + lc) * SB + cc]);
                bf[nt][1] = __float_as_uint(Bs[(kb + lc + 4) * SB + cc]);
            }
#pragma unroll
            for (int m = 0; m < MT; m++)
#pragma unroll
                for (int nt = 0; nt < 8; nt++)
                    mma_tf32(acc[m][nt], af[m], bf[nt]);
        }
        __syncthreads();
    }

#pragma unroll
    for (int m = 0; m < MT; m++) {
        int r1 = row0 + warpRow + m * 16 + lr;
        int r2 = r1 + 8;
        float v[8][4];
#pragma unroll
        for (int nt = 0; nt < 8; nt++) {
            int col = warpCol + nt * 8 + 2 * lc;
            float b0 = __ldg(&bias[col]);
            float b1 = __ldg(&bias[col + 1]);
            v[nt][0] = acc[m][nt][0] + b0;
            v[nt][1] = acc[m][nt][1] + b1;
            v[nt][2] = acc[m][nt][2] + b0;
            v[nt][3] = acc[m][nt][3] + b1;
            if (EPI == 4) {
#pragma unroll
                for (int j = 0; j < 4; j++) v[nt][j] = fmaxf(v[nt][j], 0.0f);
            }
        }
        if (EPI == 0) {
#pragma unroll
            for (int nt = 0; nt < 8; nt++) {
                int col = warpCol + nt * 8 + 2 * lc;
                if (r1 < n) { float2 s = {rnd32(v[nt][0]), rnd32(v[nt][1])}; *(float2*)&Y[(size_t)r1 * BN + col] = s; }
                if (r2 < n) { float2 s = {rnd32(v[nt][2]), rnd32(v[nt][3])}; *(float2*)&Y[(size_t)r2 * BN + col] = s; }
            }
        } else { // EPI == 4: relu -> *norm -> fp16
            __half* Yh = (__half*)Y;
            float n1 = (r1 < n) ? g_norm[r1] : 0.f;
            float n2 = (r2 < n) ? g_norm[r2] : 0.f;
#pragma unroll
            for (int nt = 0; nt < 8; nt++) {
                int col = warpCol + nt * 8 + 2 * lc;
                if (r1 < n) *(__half2*)&Yh[(size_t)r1 * BN + col] = __floats2half2_rn(v[nt][0] * n1, v[nt][1] * n1);
                if (r2 < n) *(__half2*)&Yh[(size_t)r2 * BN + col] = __floats2half2_rn(v[nt][2] * n2, v[nt][3] * n2);
            }
        }
    }
}

// ============================================================================
// Fused projection + null head (unchanged from R16):
//   z   = l2norm( relu(h@Wp1+bp1) @ Wp2 + bp2 )
//   nul = relu( h@Wn1[0:128] + z@Wn1[128:192] + bn1 ) . Wn2 + bn2
// ============================================================================
#define PW_STRIDE 72
#define TS_STRIDE 68

__global__ void proj_null_fused(const float* __restrict__ h,
                                const float* __restrict__ Wp1, const float* __restrict__ bp1,
                                const float* __restrict__ Wp2, const float* __restrict__ bp2,
                                const float* __restrict__ Wn1, const float* __restrict__ bn1,
                                const float* __restrict__ Wn2, const float* __restrict__ bn2,
                                float* __restrict__ z, float* __restrict__ nul) {
    extern __shared__ float sm[];
    float* Ab = sm;
    float* Wb = sm + 2 * 128 * ASTRIDE;
    float* Wn = Wb + 2 * 32 * PW_STRIDE;
    float* Ts = Wn + 2 * 32 * PW_STRIDE;

    const int t = threadIdx.x;
    const int wid = t >> 5;
    const int lane = t & 31;
    const int lr = lane >> 2;
    const int lc = lane & 3;
    const int row0 = blockIdx.x * 128;
    const int warpRow = wid * 16;

    uint32_t aBase  = (uint32_t)__cvta_generic_to_shared(Ab);
    uint32_t bBase  = (uint32_t)__cvta_generic_to_shared(Wb);
    uint32_t nBase  = (uint32_t)__cvta_generic_to_shared(Wn);

    auto loadA = [&](int buf, int k0) {
#pragma unroll
        for (int i = 0; i < 4; i++) {
            int idx4 = t + i * 256;
            int row = idx4 >> 3;
            int kq = idx4 & 7;
            int rg = row0 + row;
            uint32_t dst = aBase + (uint32_t)((buf * 128 * ASTRIDE + row * ASTRIDE + 4 * kq) * 4);
            cpasync16(dst, h + (size_t)rg * 128 + k0 + 4 * kq, rg < NTOT);
        }
    };
    auto loadW = [&](const float* W, uint32_t base, int buf, int k0) {
#pragma unroll
        for (int i = 0; i < 2; i++) {
            int idx4 = t + i * 256;
            int k = idx4 >> 4;
            int cq = idx4 & 15;
            uint32_t dst = base + (uint32_t)((buf * 32 * PW_STRIDE + k * PW_STRIDE + 4 * cq) * 4);
            cpasync16(dst, W + (size_t)(k0 + k) * 64 + 4 * cq, true);
        }
    };

    float p_acc[8][4];
    float n_acc[8][4];
#pragma unroll
    for (int nt = 0; nt < 8; nt++)
#pragma unroll
        for (int j = 0; j < 4; j++) { p_acc[nt][j] = 0.0f; n_acc[nt][j] = 0.0f; }

    loadA(0, 0);
    loadW(Wp1, bBase, 0, 0);
    loadW(Wn1, nBase, 0, 0);
    asm volatile("cp.async.commit_group;");

    for (int tt = 0; tt < 4; tt++) {
        int buf = tt & 1;
        if (tt < 3) {
            loadA(buf ^ 1, (tt + 1) * 32);
            loadW(Wp1, bBase, buf ^ 1, (tt + 1) * 32);
            loadW(Wn1, nBase, buf ^ 1, (tt + 1) * 32);
            asm volatile("cp.async.commit_group;");
            asm volatile("cp.async.wait_group 1;");
        } else {
            asm volatile("cp.async.wait_group 0;");
        }
        __syncthreads();
        const float* As = Ab + buf * 128 * ASTRIDE;
        const float* Bs = Wb + buf * 32 * PW_STRIDE;
        const float* Ns = Wn + buf * 32 * PW_STRIDE;
#pragma unroll
        for (int kk8 = 0; kk8 < 4; kk8++) {
            int kb = kk8 * 8;
            uint32_t af[4];
            int r1 = warpRow + lr;
            af[0] = __float_as_uint(As[r1 * ASTRIDE + kb + lc]);
            af[1] = __float_as_uint(As[(r1 + 8) * ASTRIDE + kb + lc]);
            af[2] = __float_as_uint(As[r1 * ASTRIDE + kb + lc + 4]);
            af[3] = __float_as_uint(As[(r1 + 8) * ASTRIDE + kb + lc + 4]);
            uint32_t bf[8][2], nf[8][2];
#pragma unroll
            for (int nt = 0; nt < 8; nt++) {
                int cc = nt * 8 + lr;
                bf[nt][0] = __float_as_uint(Bs[(kb + lc) * PW_STRIDE + cc]);
                bf[nt][1] = __float_as_uint(Bs[(kb + lc + 4) * PW_STRIDE + cc]);
                nf[nt][0] = __float_as_uint(Ns[(kb + lc) * PW_STRIDE + cc]);
                nf[nt][1] = __float_as_uint(Ns[(kb + lc + 4) * PW_STRIDE + cc]);
            }
#pragma unroll
            for (int nt = 0; nt < 8; nt++) {
                mma_tf32(p_acc[nt], af, bf[nt]);
                mma_tf32(n_acc[nt], af, nf[nt]);
            }
        }
        __syncthreads();
    }

    {
        int r1l = warpRow + lr;
        int r2l = r1l + 8;
#pragma unroll
        for (int nt = 0; nt < 8; nt++) {
            int col = nt * 8 + 2 * lc;
            float b0 = __ldg(&bp1[col]);
            float b1 = __ldg(&bp1[col + 1]);
            Ts[r1l * TS_STRIDE + col]     = rnd32(fmaxf(p_acc[nt][0] + b0, 0.f));
            Ts[r1l * TS_STRIDE + col + 1] = rnd32(fmaxf(p_acc[nt][1] + b1, 0.f));
            Ts[r2l * TS_STRIDE + col]     = rnd32(fmaxf(p_acc[nt][2] + b0, 0.f));
            Ts[r2l * TS_STRIDE + col + 1] = rnd32(fmaxf(p_acc[nt][3] + b1, 0.f));
        }
    }
    __syncthreads();

#pragma unroll
    for (int nt = 0; nt < 8; nt++)
#pragma unroll
        for (int j = 0; j < 4; j++) p_acc[nt][j] = 0.0f;

    loadW(Wp2, bBase, 0, 0);
    asm volatile("cp.async.commit_group;");

    for (int tt = 0; tt < 2; tt++) {
        int buf = tt & 1;
        if (tt < 1) {
            loadW(Wp2, bBase, buf ^ 1, 32);
            asm volatile("cp.async.commit_group;");
            asm volatile("cp.async.wait_group 1;");
        } else {
            asm volatile("cp.async.wait_group 0;");
        }
        __syncthreads();
        const float* Bs = Wb + buf * 32 * PW_STRIDE;
#pragma unroll
        for (int kk8 = 0; kk8 < 4; kk8++) {
            int kb = kk8 * 8;
            int col = tt * 32 + kb + lc;
            uint32_t af[4];
            int r1 = warpRow + lr;
            af[0] = __float_as_uint(Ts[r1 * TS_STRIDE + col]);
            af[1] = __float_as_uint(Ts[(r1 + 8) * TS_STRIDE + col]);
            af[2] = __float_as_uint(Ts[r1 * TS_STRIDE + col + 4]);
            af[3] = __float_as_uint(Ts[(r1 + 8) * TS_STRIDE + col + 4]);
            uint32_t bf[8][2];
#pragma unroll
            for (int nt = 0; nt < 8; nt++) {
                int cc = nt * 8 + lr;
                bf[nt][0] = __float_as_uint(Bs[(kb + lc) * PW_STRIDE + cc]);
                bf[nt][1] = __float_as_uint(Bs[(kb + lc + 4) * PW_STRIDE + cc]);
            }
#pragma unroll
            for (int nt = 0; nt < 8; nt++)
                mma_tf32(p_acc[nt], af, bf[nt]);
        }
        __syncthreads();
    }

    {
        int r1g = row0 + warpRow + lr;
        int r2g = r1g + 8;
        int r1l = warpRow + lr;
        int r2l = r1l + 8;
        float v[8][4];
#pragma unroll
        for (int nt = 0; nt < 8; nt++) {
            int col = nt * 8 + 2 * lc;
            float b0 = __ldg(&bp2[col]);
            float b1 = __ldg(&bp2[col + 1]);
            v[nt][0] = p_acc[nt][0] + b0;
            v[nt][1] = p_acc[nt][1] + b1;
            v[nt][2] = p_acc[nt][2] + b0;
            v[nt][3] = p_acc[nt][3] + b1;
        }
        float s1 = 0.f, s2 = 0.f;
#pragma unroll
        for (int nt = 0; nt < 8; nt++) {
            s1 += v[nt][0] * v[nt][0] + v[nt][1] * v[nt][1];
            s2 += v[nt][2] * v[nt][2] + v[nt][3] * v[nt][3];
        }
        s1 += __shfl_xor_sync(0xffffffffu, s1, 1);
        s1 += __shfl_xor_sync(0xffffffffu, s1, 2);
        s2 += __shfl_xor_sync(0xffffffffu, s2, 1);
        s2 += __shfl_xor_sync(0xffffffffu, s2, 2);
        float i1 = 1.0f / fmaxf(sqrtf(s1), 1e-12f);
        float i2 = 1.0f / fmaxf(sqrtf(s2), 1e-12f);
#pragma unroll
        for (int nt = 0; nt < 8; nt++) {
            int col = nt * 8 + 2 * lc;
            float z0 = rnd32(v[nt][0] * i1), z1 = rnd32(v[nt][1] * i1);
            float z2 = rnd32(v[nt][2] * i2), z3 = rnd32(v[nt][3] * i2);
            if (r1g < NTOT) { float2 s = {z0, z1}; *(float2*)&z[(size_t)r1g * 64 + col] = s; }
            if (r2g < NTOT) { float2 s = {z2, z3}; *(float2*)&z[(size_t)r2g * 64 + col] = s; }
            Ts[r1l * TS_STRIDE + col]     = z0;
            Ts[r1l * TS_STRIDE + col + 1] = z1;
            Ts[r2l * TS_STRIDE + col]     = z2;
            Ts[r2l * TS_STRIDE + col + 1] = z3;
        }
    }
    __syncthreads();

    loadW(Wn1 + (size_t)128 * 64, nBase, 0, 0);
    asm volatile("cp.async.commit_group;");

    for (int tt = 0; tt < 2; tt++) {
        int buf = tt & 1;
        if (tt < 1) {
            loadW(Wn1 + (size_t)128 * 64, nBase, buf ^ 1, 32);
            asm volatile("cp.async.commit_group;");
            asm volatile("cp.async.wait_group 1;");
        } else {
            asm volatile("cp.async.wait_group 0;");
        }
        __syncthreads();
        const float* Ns = Wn + buf * 32 * PW_STRIDE;
#pragma unroll
        for (int kk8 = 0; kk8 < 4; kk8++) {
            int kb = kk8 * 8;
            int col = tt * 32 + kb + lc;
            uint32_t af[4];
            int r1 = warpRow + lr;
            af[0] = __float_as_uint(Ts[r1 * TS_STRIDE + col]);
            af[1] = __float_as_uint(Ts[(r1 + 8) * TS_STRIDE + col]);
            af[2] = __float_as_uint(Ts[r1 * TS_STRIDE + col + 4]);
            af[3] = __float_as_uint(Ts[(r1 + 8) * TS_STRIDE + col + 4]);
            uint32_t nf[8][2];
#pragma unroll
            for (int nt = 0; nt < 8; nt++) {
                int cc = nt * 8 + lr;
                nf[nt][0] = __float_as_uint(Ns[(kb + lc) * PW_STRIDE + cc]);
                nf[nt][1] = __float_as_uint(Ns[(kb + lc + 4) * PW_STRIDE + cc]);
            }
#pragma unroll
            for (int nt = 0; nt < 8; nt++)
                mma_tf32(n_acc[nt], af, nf[nt]);
        }
        __syncthreads();
    }

    {
        int r1 = row0 + warpRow + lr;
        int r2 = r1 + 8;
        float d1 = 0.0f, d2 = 0.0f;
#pragma unroll
        for (int nt = 0; nt < 8; nt++) {
            int col = nt * 8 + 2 * lc;
            float b0 = __ldg(&bn1[col]);
            float b1 = __ldg(&bn1[col + 1]);
            float w0 = __ldg(&Wn2[col]);
            float w1 = __ldg(&Wn2[col + 1]);
            d1 += fmaxf(n_acc[nt][0] + b0, 0.f) * w0 + fmaxf(n_acc[nt][1] + b1, 0.f) * w1;
            d2 += fmaxf(n_acc[nt][2] + b0, 0.f) * w0 + fmaxf(n_acc[nt][3] + b1, 0.f) * w1;
        }
        d1 += __shfl_xor_sync(0xffffffffu, d1, 1);
        d1 += __shfl_xor_sync(0xffffffffu, d1, 2);
        d2 += __shfl_xor_sync(0xffffffffu, d2, 1);
        d2 += __shfl_xor_sync(0xffffffffu, d2, 2);
        if (lc == 0) {
            float bb = __ldg(&bn2[0]);
            if (r1 < NTOT) nul[r1] = d1 + bb;
            if (r2 < NTOT) nul[r2] = d2 + bb;
        }
    }
}

// ---------------- launch ------------------------------------------------------

extern "C" void kernel_launch(void* const* d_in, const int* in_sizes, int n_in,
                              void* d_out, int out_size) {
    const float* xA  = (const float*)d_in[0];
    const float* xB  = (const float*)d_in[1];
    const int*   eA  = (const int*)d_in[2];
    const int*   eB  = (const int*)d_in[3];
    const float* W1  = (const float*)d_in[4];
    const float* b1  = (const float*)d_in[5];
    const float* W2  = (const float*)d_in[6];
    const float* b2  = (const float*)d_in[7];
    const float* Wp1 = (const float*)d_in[8];
    const float* bp1 = (const float*)d_in[9];
    const float* Wp2 = (const float*)d_in[10];
    const float* bp2 = (const float*)d_in[11];
    const float* Wn1 = (const float*)d_in[12];
    const float* bn1 = (const float*)d_in[13];
    const float* Wn2 = (const float*)d_in[14];
    const float* bn2 = (const float*)d_in[15];

    float* out  = (float*)d_out;
    float* h    = out;                               // [2N,128] (hA | hB)
    float* z    = out + (size_t)NTOT * 128;          // [2N,64]
    float* nul  = z + (size_t)NTOT * 64;             // [2N]

    void* p;
    int* degcur;  cudaGetSymbolAddress(&p, g_degcur); degcur = (int*)p;
    float* agg;   cudaGetSymbolAddress(&p, g_agg);    agg    = (float*)p;
    uint2* xh;    cudaGetSymbolAddress(&p, g_xh);     xh     = (uint2*)p;
    uint2* hidh;  cudaGetSymbolAddress(&p, g_hidh);   hidh   = (uint2*)p;
    float* w;     cudaGetSymbolAddress(&p, g_w);      w      = (float*)p;

    cudaMemsetAsync(degcur, 0, NTOT * sizeof(int));
    roundw_kernel<<<(57344 + 255) / 256, 256>>>(W1, W2, Wp1, Wp2, Wn1);
    degree_kernel<<<((2 * NEDGES / 4) + 255) / 256, 256>>>(eA, eB);
    scan1_kernel<<<2 * NBLK, 1024>>>();
    scan2_kernel<<<1, 128>>>();
    scan3_kernel<<<2 * NBLK, 1024>>>();
    conv_kernel<<<(NTOT * 32 + 255) / 256, 256>>>(xA, xB);   // needs norm (scan1)
    fill_kernel<<<((2 * NEDGES / 4) + 255) / 256, 256>>>(eA, eB);

    const int gemmGrid = (NTOT + 127) / 128;
    const int aggGrid  = (NTOT * 32 + 255) / 256;

    size_t sh128  = (2 * 128 * ASTRIDE + 2 * 32 * (128 + 8)) * sizeof(float);
    size_t shPN   = (2 * 128 * ASTRIDE + 4 * 32 * PW_STRIDE + 128 * TS_STRIDE) * sizeof(float);
    cudaFuncSetAttribute(gemm_tc<128, 2, 4>, cudaFuncAttributeMaxDynamicSharedMemorySize, (int)sh128);
    cudaFuncSetAttribute(gemm_tc<128, 2, 0>, cudaFuncAttributeMaxDynamicSharedMemorySize, (int)sh128);
    cudaFuncSetAttribute(proj_null_fused,    cudaFuncAttributeMaxDynamicSharedMemorySize, (int)shPN);

    // layer 1: agg(x_fp16*norm) -> relu(. @ W1 + b1)*norm -> fp16 hid
    aggh_kernel<<<aggGrid, 256>>>(xh, agg);
    gemm_tc<128, 2, 4><<<gemmGrid, 256, sh128>>>(agg, 128, w + OW1, b1, (float*)hidh, NTOT);
    // layer 2: agg(hid_fp16*norm) -> . @ W2 + b2   (encoder output h)
    aggh_kernel<<<aggGrid, 256>>>(hidh, agg);
    gemm_tc<128, 2, 0><<<gemmGrid, 256, sh128>>>(agg, 128, w + OW2, b2, h, NTOT);
    // proj + null head, fully fused
    proj_null_fused<<<gemmGrid, 256, shPN>>>(h, w + OWP1, bp1, w + OWP2, bp2,
                                             w + OWN1, bn1, Wn2, bn2, z, nul);
}